// round 1
// baseline (speedup 1.0000x reference)
#include <cuda_runtime.h>

// Problem constants
#define BB   2
#define TT   2048
#define DDIM 1024
#define HH   16
#define HDD  64
#define MM   (BB*TT)   // 4096 rows

// Scratch (allocation-free rule: __device__ globals)
__device__ float g_q[MM*DDIM];
__device__ float g_k[MM*DDIM];
__device__ float g_v[MM*DDIM];
__device__ float g_att[MM*DDIM];

// ---------------------------------------------------------------------------
// Generic NT GEMM: C[m][n] = sum_k A[m][k] * W[n][k]
// A: [Mdim,Kdim] row-major, W: [Ndim,Kdim] row-major (torch Linear convention)
// 64x64 block tile, K-tile 16, 256 threads, 4x4 per thread.
// Shared tiles stored kk-major so compute does 2x LDS.128 + 16 FFMA per kk.
// ---------------------------------------------------------------------------
__global__ __launch_bounds__(256) void gemm_nt(const float* __restrict__ A,
                                               const float* __restrict__ W,
                                               float* __restrict__ C,
                                               int Mdim, int Ndim, int Kdim) {
    __shared__ float As[16][68];
    __shared__ float Bs[16][68];
    const int tid  = threadIdx.x;
    const int m0   = blockIdx.y << 6;
    const int n0   = blockIdx.x << 6;
    const int tr   = tid >> 4;          // 0..15 -> rows tr*4..tr*4+3
    const int tc   = tid & 15;          // 0..15 -> cols tc*4..tc*4+3
    const int lrow = tid >> 2;          // 0..63 load row
    const int lk4  = (tid & 3) << 2;    // 0,4,8,12 load k offset

    const float* Aptr = A + (size_t)(m0 + lrow) * Kdim + lk4;
    const float* Wptr = W + (size_t)(n0 + lrow) * Kdim + lk4;

    float acc[4][4];
#pragma unroll
    for (int i = 0; i < 4; i++)
#pragma unroll
        for (int j = 0; j < 4; j++) acc[i][j] = 0.f;

    for (int k0 = 0; k0 < Kdim; k0 += 16) {
        float4 av = *(const float4*)(Aptr + k0);
        float4 bv = *(const float4*)(Wptr + k0);
        __syncthreads();
        As[lk4+0][lrow] = av.x; As[lk4+1][lrow] = av.y;
        As[lk4+2][lrow] = av.z; As[lk4+3][lrow] = av.w;
        Bs[lk4+0][lrow] = bv.x; Bs[lk4+1][lrow] = bv.y;
        Bs[lk4+2][lrow] = bv.z; Bs[lk4+3][lrow] = bv.w;
        __syncthreads();
#pragma unroll
        for (int kk = 0; kk < 16; kk++) {
            float4 a = *(const float4*)&As[kk][tr << 2];
            float4 b = *(const float4*)&Bs[kk][tc << 2];
            acc[0][0] += a.x*b.x; acc[0][1] += a.x*b.y; acc[0][2] += a.x*b.z; acc[0][3] += a.x*b.w;
            acc[1][0] += a.y*b.x; acc[1][1] += a.y*b.y; acc[1][2] += a.y*b.z; acc[1][3] += a.y*b.w;
            acc[2][0] += a.z*b.x; acc[2][1] += a.z*b.y; acc[2][2] += a.z*b.z; acc[2][3] += a.z*b.w;
            acc[3][0] += a.w*b.x; acc[3][1] += a.w*b.y; acc[3][2] += a.w*b.z; acc[3][3] += a.w*b.w;
        }
    }
#pragma unroll
    for (int i = 0; i < 4; i++) {
        float4 r4 = make_float4(acc[i][0], acc[i][1], acc[i][2], acc[i][3]);
        *(float4*)&C[(size_t)(m0 + (tr << 2) + i) * Ndim + n0 + (tc << 2)] = r4;
    }
}

// ---------------------------------------------------------------------------
// Flash-style causal attention.
// Grid: (T/64, H, B). Block: 256 threads. Each block: 64 query rows.
// Thread (r = tid/4, seg = tid%4) owns query row r, 16-wide column segment.
// Online softmax; O accumulator (16 floats) in registers.
// q/k/v layout: [B*T, D] row-major, head h at column offset h*64.
// Q is pre-scaled by 1/sqrt(HD) at load.
// ---------------------------------------------------------------------------
__global__ __launch_bounds__(256) void attn_fwd(float* __restrict__ o_out) {
    extern __shared__ float sm[];
    float* Qs = sm;                 // [64][68] (row, d)
    float* Kt = sm + 64 * 68;       // [64][68] transposed (d, s)
    float* Vs = sm + 2 * 64 * 68;   // [64][68] (s, d)
    float* Ps = sm + 3 * 64 * 68;   // [64][68] (r, s)

    const int tid = threadIdx.x;
    const int r   = tid >> 2;            // query row within tile, 0..63
    const int c0  = (tid & 3) << 4;      // 16-wide segment offset
    const int b = blockIdx.z, h = blockIdx.y, qt = blockIdx.x;
    const int tq = (qt << 6) + r;
    const size_t rowbase = (size_t)(b * TT + tq) * DDIM + h * HDD;

    // Load + scale Q tile
#pragma unroll
    for (int i = 0; i < 16; i += 4) {
        float4 qv = *(const float4*)&g_q[rowbase + c0 + i];
        qv.x *= 0.125f; qv.y *= 0.125f; qv.z *= 0.125f; qv.w *= 0.125f;
        *(float4*)&Qs[r * 68 + c0 + i] = qv;
    }

    float m_run = -1e30f, l_run = 0.f;
    float o[16];
#pragma unroll
    for (int i = 0; i < 16; i++) o[i] = 0.f;

    const int ntiles = qt + 1;   // causal: skip tiles fully above diagonal
    for (int jt = 0; jt < ntiles; jt++) {
        const size_t kvbase = (size_t)(b * TT + (jt << 6) + r) * DDIM + h * HDD;
        __syncthreads();   // previous iteration fully consumed Kt/Vs/Ps
#pragma unroll
        for (int i = 0; i < 16; i += 4) {
            float4 kv = *(const float4*)&g_k[kvbase + c0 + i];
            Kt[(c0 + i + 0) * 68 + r] = kv.x;
            Kt[(c0 + i + 1) * 68 + r] = kv.y;
            Kt[(c0 + i + 2) * 68 + r] = kv.z;
            Kt[(c0 + i + 3) * 68 + r] = kv.w;
            float4 vv = *(const float4*)&g_v[kvbase + c0 + i];
            *(float4*)&Vs[r * 68 + c0 + i] = vv;
        }
        __syncthreads();

        // S[r][c0..c0+15] = Q[r][:] . K[s][:]
        float sv[16];
#pragma unroll
        for (int i = 0; i < 16; i++) sv[i] = 0.f;
#pragma unroll 8
        for (int d = 0; d < 64; d++) {
            float qd = Qs[r * 68 + d];
            const float* kp = &Kt[d * 68 + c0];
            float4 k0 = *(const float4*)(kp);
            float4 k1 = *(const float4*)(kp + 4);
            float4 k2 = *(const float4*)(kp + 8);
            float4 k3 = *(const float4*)(kp + 12);
            sv[0]  += qd * k0.x; sv[1]  += qd * k0.y; sv[2]  += qd * k0.z; sv[3]  += qd * k0.w;
            sv[4]  += qd * k1.x; sv[5]  += qd * k1.y; sv[6]  += qd * k1.z; sv[7]  += qd * k1.w;
            sv[8]  += qd * k2.x; sv[9]  += qd * k2.y; sv[10] += qd * k2.z; sv[11] += qd * k2.w;
            sv[12] += qd * k3.x; sv[13] += qd * k3.y; sv[14] += qd * k3.z; sv[15] += qd * k3.w;
        }

        if (jt == ntiles - 1) {   // diagonal tile: mask s > t
#pragma unroll
            for (int i = 0; i < 16; i++)
                if (c0 + i > r) sv[i] = -1e30f;
        }

        // online softmax: row = 4 consecutive lanes
        float mloc = sv[0];
#pragma unroll
        for (int i = 1; i < 16; i++) mloc = fmaxf(mloc, sv[i]);
        mloc = fmaxf(mloc, __shfl_xor_sync(0xffffffffu, mloc, 1));
        mloc = fmaxf(mloc, __shfl_xor_sync(0xffffffffu, mloc, 2));
        float m_new = fmaxf(m_run, mloc);
        float lloc = 0.f;
#pragma unroll
        for (int i = 0; i < 16; i++) { sv[i] = __expf(sv[i] - m_new); lloc += sv[i]; }
        lloc += __shfl_xor_sync(0xffffffffu, lloc, 1);
        lloc += __shfl_xor_sync(0xffffffffu, lloc, 2);
        float alpha = __expf(m_run - m_new);
        l_run = l_run * alpha + lloc;
        m_run = m_new;

#pragma unroll
        for (int i = 0; i < 16; i += 4)
            *(float4*)&Ps[r * 68 + c0 + i] = make_float4(sv[i], sv[i+1], sv[i+2], sv[i+3]);
#pragma unroll
        for (int i = 0; i < 16; i++) o[i] *= alpha;
        __syncthreads();

        // O[r][c0..] += P[r][:] . V[:][c0..]
#pragma unroll 4
        for (int s = 0; s < 64; s++) {
            float p = Ps[r * 68 + s];
            const float* vp = &Vs[s * 68 + c0];
            float4 v0 = *(const float4*)(vp);
            float4 v1 = *(const float4*)(vp + 4);
            float4 v2 = *(const float4*)(vp + 8);
            float4 v3 = *(const float4*)(vp + 12);
            o[0]  += p * v0.x; o[1]  += p * v0.y; o[2]  += p * v0.z; o[3]  += p * v0.w;
            o[4]  += p * v1.x; o[5]  += p * v1.y; o[6]  += p * v1.z; o[7]  += p * v1.w;
            o[8]  += p * v2.x; o[9]  += p * v2.y; o[10] += p * v2.z; o[11] += p * v2.w;
            o[12] += p * v3.x; o[13] += p * v3.y; o[14] += p * v3.z; o[15] += p * v3.w;
        }
    }

    float inv = 1.f / l_run;
#pragma unroll
    for (int i = 0; i < 16; i += 4) {
        float4 r4 = make_float4(o[i]*inv, o[i+1]*inv, o[i+2]*inv, o[i+3]*inv);
        *(float4*)&o_out[rowbase + c0 + i] = r4;
    }
}

// ---------------------------------------------------------------------------
extern "C" void kernel_launch(void* const* d_in, const int* in_sizes, int n_in,
                              void* d_out, int out_size) {
    const float* x  = (const float*)d_in[0];
    const float* Wq = (const float*)d_in[1];
    const float* Wk = (const float*)d_in[2];
    const float* Wv = (const float*)d_in[3];
    const float* Wo = (const float*)d_in[4];
    // d_in[5] = mask: causal, handled analytically
    float* out = (float*)d_out;

    float *qb, *kb, *vb, *ab;
    cudaGetSymbolAddress((void**)&qb, g_q);
    cudaGetSymbolAddress((void**)&kb, g_k);
    cudaGetSymbolAddress((void**)&vb, g_v);
    cudaGetSymbolAddress((void**)&ab, g_att);

    const int smem_attn = 4 * 64 * 68 * (int)sizeof(float);   // 69632 B
    cudaFuncSetAttribute(attn_fwd, cudaFuncAttributeMaxDynamicSharedMemorySize, smem_attn);

    dim3 ggrid(DDIM / 64, MM / 64);   // (16, 64)
    gemm_nt<<<ggrid, 256>>>(x, Wq, qb, MM, DDIM, DDIM);
    gemm_nt<<<ggrid, 256>>>(x, Wk, kb, MM, DDIM, DDIM);
    gemm_nt<<<ggrid, 256>>>(x, Wv, vb, MM, DDIM, DDIM);

    dim3 agrid(TT / 64, HH, BB);      // (32, 16, 2)
    attn_fwd<<<agrid, 256, smem_attn>>>(ab);

    gemm_nt<<<ggrid, 256>>>(ab, Wo, out, MM, DDIM, DDIM);
}

// round 3
// speedup vs baseline: 1.2186x; 1.2186x over previous
#include <cuda_runtime.h>
#include <cuda_bf16.h>
#include <cstdint>

// Problem constants
#define BB   2
#define TT   2048
#define DDIM 1024
#define HH   16
#define HDD  64
#define MM   (BB*TT)   // 4096 rows
#define K3   3072      // split-K: [hi | hi/lo | lo/hi]

// Scratch (__device__ globals; no allocations allowed)
__device__ float g_q[MM*DDIM];
__device__ float g_k[MM*DDIM];
__device__ float g_v[MM*DDIM];
__device__ float g_att[MM*DDIM];
__device__ __nv_bfloat16 g_xs[MM*K3];
__device__ __nv_bfloat16 g_atts[MM*K3];
__device__ __nv_bfloat16 g_wqs[DDIM*K3];
__device__ __nv_bfloat16 g_wks[DDIM*K3];
__device__ __nv_bfloat16 g_wvs[DDIM*K3];
__device__ __nv_bfloat16 g_wos[DDIM*K3];

// ---------------------------------------------------------------------------
__device__ __forceinline__ uint32_t s2u(const void* p) {
    uint32_t a;
    asm("{ .reg .u64 t; cvta.to.shared.u64 t, %1; cvt.u32.u64 %0, t; }" : "=r"(a) : "l"(p));
    return a;
}
__device__ __forceinline__ uint32_t swz(uint32_t o) { return o ^ ((o >> 3) & 0x70); }
__device__ __forceinline__ void cp16(uint32_t dst, const void* src) {
    asm volatile("cp.async.cg.shared.global [%0], [%1], 16;" :: "r"(dst), "l"(src));
}
__device__ __forceinline__ void ldsm4(uint32_t* r, uint32_t addr) {
    asm volatile("ldmatrix.sync.aligned.m8n8.x4.shared.b16 {%0,%1,%2,%3}, [%4];"
                 : "=r"(r[0]), "=r"(r[1]), "=r"(r[2]), "=r"(r[3]) : "r"(addr));
}
__device__ __forceinline__ void mma16816(float* c, const uint32_t* a, const uint32_t* b) {
    asm volatile("mma.sync.aligned.m16n8k16.row.col.f32.bf16.bf16.f32 "
                 "{%0,%1,%2,%3}, {%4,%5,%6,%7}, {%8,%9}, {%0,%1,%2,%3};"
                 : "+f"(c[0]), "+f"(c[1]), "+f"(c[2]), "+f"(c[3])
                 : "r"(a[0]), "r"(a[1]), "r"(a[2]), "r"(a[3]), "r"(b[0]), "r"(b[1]));
}

// ---------------------------------------------------------------------------
// split3: fp32 [rows,1024] -> bf16 [rows,3072]
// amode=1 (activation): [hi | hi | lo]   amode=0 (weight): [hi | lo | hi]
// ---------------------------------------------------------------------------
__global__ __launch_bounds__(256) void split3(const float* __restrict__ in,
                                              __nv_bfloat16* __restrict__ out,
                                              int amode) {
    int idx = (blockIdx.x * 256 + threadIdx.x) * 4;
    int r = idx >> 10, c = idx & 1023;
    float4 v = *(const float4*)(in + idx);
    float vv[4] = {v.x, v.y, v.z, v.w};
    __nv_bfloat16 h[4], l[4];
#pragma unroll
    for (int j = 0; j < 4; j++) {
        h[j] = __float2bfloat16(vv[j]);
        l[j] = __float2bfloat16(vv[j] - __bfloat162float(h[j]));
    }
    size_t base = (size_t)r * K3 + c;
    __nv_bfloat162 h01{h[0], h[1]}, h23{h[2], h[3]};
    __nv_bfloat162 l01{l[0], l[1]}, l23{l[2], l[3]};
    *(__nv_bfloat162*)(out + base)     = h01;
    *(__nv_bfloat162*)(out + base + 2) = h23;
    if (amode) {
        *(__nv_bfloat162*)(out + base + 1024)     = h01;
        *(__nv_bfloat162*)(out + base + 1024 + 2) = h23;
        *(__nv_bfloat162*)(out + base + 2048)     = l01;
        *(__nv_bfloat162*)(out + base + 2048 + 2) = l23;
    } else {
        *(__nv_bfloat162*)(out + base + 1024)     = l01;
        *(__nv_bfloat162*)(out + base + 1024 + 2) = l23;
        *(__nv_bfloat162*)(out + base + 2048)     = h01;
        *(__nv_bfloat162*)(out + base + 2048 + 2) = h23;
    }
}

// ---------------------------------------------------------------------------
// mma.sync bf16 NT GEMM: C[4096,1024] = A[4096,3072] @ B[1024,3072]^T, fp32 out.
// CTA tile 128x128, BK=64, 3-stage cp.async pipeline, 8 warps (2x4 grid),
// warp tile 64x32. SW128-style swizzled smem, ldmatrix fragment loads.
// Grid: (1024/128, 4096/128) = (8, 32). 256 threads.
// ---------------------------------------------------------------------------
#define BK      64
#define STAGES  3
#define NCHUNK  (K3 / BK)                 // 48
#define STG_A   (128 * 128)               // bytes
#define STG_B   (128 * 128)
#define STG_SZ  (STG_A + STG_B)           // 32 KB
#define GEMM_DYN (STAGES * STG_SZ + 1024) // ~97 KB

__global__ __launch_bounds__(256) void gemm_mma(const __nv_bfloat16* __restrict__ A,
                                                const __nv_bfloat16* __restrict__ B,
                                                float* __restrict__ C) {
    extern __shared__ char dyn[];
    const int tid  = threadIdx.x;
    const int wid  = tid >> 5, lane = tid & 31;
    const int wm   = wid >> 2;            // 0..1  (64-row slab)
    const int wn   = wid & 3;             // 0..3  (32-col slab)
    const int m0   = blockIdx.y << 7;
    const int n0   = blockIdx.x << 7;

    const uint32_t sbase = (s2u(dyn) + 1023) & ~1023u;

    const int lrow = tid >> 3;            // 0..31 base load row
    const int ls16 = tid & 7;             // 16B segment within 128B row

    float acc[4][4][4];
#pragma unroll
    for (int mi = 0; mi < 4; mi++)
#pragma unroll
        for (int ni = 0; ni < 4; ni++)
#pragma unroll
            for (int j = 0; j < 4; j++) acc[mi][ni][j] = 0.f;

    // ldmatrix lane address components
    const int sub  = lane >> 3;           // 0..3
    const int lr8  = lane & 7;
    const int aRowOff = ((sub & 1) << 3) + lr8;      // A: T0/T2 rows0-7, T1/T3 rows8-15
    const int aKHalf  = (sub >> 1) << 4;             // A: T0/T1 k0, T2/T3 k+16B
    const int bRowOff = ((sub >> 1) << 3) + lr8;     // B: T0/T1 rows0-7, T2/T3 rows8-15
    const int bKHalf  = (sub & 1) << 4;              // B: T0/T2 k0, T1/T3 k+16B

#define LOAD_CHUNK(c)                                                            \
    {                                                                            \
        const int s_ = (c) % STAGES;                                             \
        const uint32_t sA_ = sbase + s_ * STG_SZ;                                \
        const uint32_t sB_ = sA_ + STG_A;                                        \
        _Pragma("unroll")                                                        \
        for (int it = 0; it < 4; it++) {                                         \
            int row = lrow + (it << 5);                                          \
            cp16(sA_ + swz(row * 128 + ls16 * 16),                               \
                 A + (size_t)(m0 + row) * K3 + (c) * BK + ls16 * 8);             \
        }                                                                        \
        _Pragma("unroll")                                                        \
        for (int it = 0; it < 4; it++) {                                         \
            int row = lrow + (it << 5);                                          \
            cp16(sB_ + swz(row * 128 + ls16 * 16),                               \
                 B + (size_t)(n0 + row) * K3 + (c) * BK + ls16 * 8);             \
        }                                                                        \
        asm volatile("cp.async.commit_group;" ::: "memory");                     \
    }

    LOAD_CHUNK(0);
    LOAD_CHUNK(1);

    for (int i = 0; i < NCHUNK; i++) {
        if (i < NCHUNK - 1) asm volatile("cp.async.wait_group 1;" ::: "memory");
        else                asm volatile("cp.async.wait_group 0;" ::: "memory");
        __syncthreads();

        if (i + 2 < NCHUNK) LOAD_CHUNK(i + 2);

        const int s = i % STAGES;
        const uint32_t sA = sbase + s * STG_SZ;
        const uint32_t sB = sA + STG_A;

#pragma unroll
        for (int kk = 0; kk < 4; kk++) {
            uint32_t af[4][4], bf[2][4];
#pragma unroll
            for (int mi = 0; mi < 4; mi++) {
                int row = wm * 64 + mi * 16 + aRowOff;
                ldsm4(af[mi], sA + swz(row * 128 + kk * 32 + aKHalf));
            }
#pragma unroll
            for (int p = 0; p < 2; p++) {
                int row = wn * 32 + p * 16 + bRowOff;
                ldsm4(bf[p], sB + swz(row * 128 + kk * 32 + bKHalf));
            }
#pragma unroll
            for (int mi = 0; mi < 4; mi++) {
                mma16816(acc[mi][0], af[mi], &bf[0][0]);
                mma16816(acc[mi][1], af[mi], &bf[0][2]);
                mma16816(acc[mi][2], af[mi], &bf[1][0]);
                mma16816(acc[mi][3], af[mi], &bf[1][2]);
            }
        }
    }

    // Epilogue: direct stores (float2 pairs, 32B-contiguous per 4-lane group)
    const int lr = lane >> 2, lc = (lane & 3) << 1;
#pragma unroll
    for (int mi = 0; mi < 4; mi++) {
#pragma unroll
        for (int ni = 0; ni < 4; ni++) {
            int grow = m0 + wm * 64 + mi * 16 + lr;
            int gcol = n0 + wn * 32 + ni * 8 + lc;
            *(float2*)&C[(size_t)grow * DDIM + gcol] =
                make_float2(acc[mi][ni][0], acc[mi][ni][1]);
            *(float2*)&C[(size_t)(grow + 8) * DDIM + gcol] =
                make_float2(acc[mi][ni][2], acc[mi][ni][3]);
        }
    }
#undef LOAD_CHUNK
}

// ---------------------------------------------------------------------------
// Flash-style causal attention (unchanged from R1 baseline).
// ---------------------------------------------------------------------------
__global__ __launch_bounds__(256) void attn_fwd(float* __restrict__ o_out) {
    extern __shared__ float sm[];
    float* Qs = sm;
    float* Kt = sm + 64 * 68;
    float* Vs = sm + 2 * 64 * 68;
    float* Ps = sm + 3 * 64 * 68;

    const int tid = threadIdx.x;
    const int r   = tid >> 2;
    const int c0  = (tid & 3) << 4;
    const int b = blockIdx.z, h = blockIdx.y, qt = blockIdx.x;
    const int tq = (qt << 6) + r;
    const size_t rowbase = (size_t)(b * TT + tq) * DDIM + h * HDD;

#pragma unroll
    for (int i = 0; i < 16; i += 4) {
        float4 qv = *(const float4*)&g_q[rowbase + c0 + i];
        qv.x *= 0.125f; qv.y *= 0.125f; qv.z *= 0.125f; qv.w *= 0.125f;
        *(float4*)&Qs[r * 68 + c0 + i] = qv;
    }

    float m_run = -1e30f, l_run = 0.f;
    float o[16];
#pragma unroll
    for (int i = 0; i < 16; i++) o[i] = 0.f;

    const int ntiles = qt + 1;
    for (int jt = 0; jt < ntiles; jt++) {
        const size_t kvbase = (size_t)(b * TT + (jt << 6) + r) * DDIM + h * HDD;
        __syncthreads();
#pragma unroll
        for (int i = 0; i < 16; i += 4) {
            float4 kv = *(const float4*)&g_k[kvbase + c0 + i];
            Kt[(c0 + i + 0) * 68 + r] = kv.x;
            Kt[(c0 + i + 1) * 68 + r] = kv.y;
            Kt[(c0 + i + 2) * 68 + r] = kv.z;
            Kt[(c0 + i + 3) * 68 + r] = kv.w;
            float4 vv = *(const float4*)&g_v[kvbase + c0 + i];
            *(float4*)&Vs[r * 68 + c0 + i] = vv;
        }
        __syncthreads();

        float sv[16];
#pragma unroll
        for (int i = 0; i < 16; i++) sv[i] = 0.f;
#pragma unroll 8
        for (int d = 0; d < 64; d++) {
            float qd = Qs[r * 68 + d];
            const float* kp = &Kt[d * 68 + c0];
            float4 k0 = *(const float4*)(kp);
            float4 k1 = *(const float4*)(kp + 4);
            float4 k2 = *(const float4*)(kp + 8);
            float4 k3 = *(const float4*)(kp + 12);
            sv[0]  += qd * k0.x; sv[1]  += qd * k0.y; sv[2]  += qd * k0.z; sv[3]  += qd * k0.w;
            sv[4]  += qd * k1.x; sv[5]  += qd * k1.y; sv[6]  += qd * k1.z; sv[7]  += qd * k1.w;
            sv[8]  += qd * k2.x; sv[9]  += qd * k2.y; sv[10] += qd * k2.z; sv[11] += qd * k2.w;
            sv[12] += qd * k3.x; sv[13] += qd * k3.y; sv[14] += qd * k3.z; sv[15] += qd * k3.w;
        }

        if (jt == ntiles - 1) {
#pragma unroll
            for (int i = 0; i < 16; i++)
                if (c0 + i > r) sv[i] = -1e30f;
        }

        float mloc = sv[0];
#pragma unroll
        for (int i = 1; i < 16; i++) mloc = fmaxf(mloc, sv[i]);
        mloc = fmaxf(mloc, __shfl_xor_sync(0xffffffffu, mloc, 1));
        mloc = fmaxf(mloc, __shfl_xor_sync(0xffffffffu, mloc, 2));
        float m_new = fmaxf(m_run, mloc);
        float lloc = 0.f;
#pragma unroll
        for (int i = 0; i < 16; i++) { sv[i] = __expf(sv[i] - m_new); lloc += sv[i]; }
        lloc += __shfl_xor_sync(0xffffffffu, lloc, 1);
        lloc += __shfl_xor_sync(0xffffffffu, lloc, 2);
        float alpha = __expf(m_run - m_new);
        l_run = l_run * alpha + lloc;
        m_run = m_new;

#pragma unroll
        for (int i = 0; i < 16; i += 4)
            *(float4*)&Ps[r * 68 + c0 + i] = make_float4(sv[i], sv[i+1], sv[i+2], sv[i+3]);
#pragma unroll
        for (int i = 0; i < 16; i++) o[i] *= alpha;
        __syncthreads();

#pragma unroll 4
        for (int s = 0; s < 64; s++) {
            float p = Ps[r * 68 + s];
            const float* vp = &Vs[s * 68 + c0];
            float4 v0 = *(const float4*)(vp);
            float4 v1 = *(const float4*)(vp + 4);
            float4 v2 = *(const float4*)(vp + 8);
            float4 v3 = *(const float4*)(vp + 12);
            o[0]  += p * v0.x; o[1]  += p * v0.y; o[2]  += p * v0.z; o[3]  += p * v0.w;
            o[4]  += p * v1.x; o[5]  += p * v1.y; o[6]  += p * v1.z; o[7]  += p * v1.w;
            o[8]  += p * v2.x; o[9]  += p * v2.y; o[10] += p * v2.z; o[11] += p * v2.w;
            o[12] += p * v3.x; o[13] += p * v3.y; o[14] += p * v3.z; o[15] += p * v3.w;
        }
    }

    float inv = 1.f / l_run;
#pragma unroll
    for (int i = 0; i < 16; i += 4) {
        float4 r4 = make_float4(o[i]*inv, o[i+1]*inv, o[i+2]*inv, o[i+3]*inv);
        *(float4*)&o_out[rowbase + c0 + i] = r4;
    }
}

// ---------------------------------------------------------------------------
extern "C" void kernel_launch(void* const* d_in, const int* in_sizes, int n_in,
                              void* d_out, int out_size) {
    const float* x  = (const float*)d_in[0];
    const float* Wq = (const float*)d_in[1];
    const float* Wk = (const float*)d_in[2];
    const float* Wv = (const float*)d_in[3];
    const float* Wo = (const float*)d_in[4];
    float* out = (float*)d_out;

    float *qb, *kb, *vb, *ab;
    __nv_bfloat16 *xs, *ats, *wqs, *wks, *wvs, *wos;
    cudaGetSymbolAddress((void**)&qb, g_q);
    cudaGetSymbolAddress((void**)&kb, g_k);
    cudaGetSymbolAddress((void**)&vb, g_v);
    cudaGetSymbolAddress((void**)&ab, g_att);
    cudaGetSymbolAddress((void**)&xs, g_xs);
    cudaGetSymbolAddress((void**)&ats, g_atts);
    cudaGetSymbolAddress((void**)&wqs, g_wqs);
    cudaGetSymbolAddress((void**)&wks, g_wks);
    cudaGetSymbolAddress((void**)&wvs, g_wvs);
    cudaGetSymbolAddress((void**)&wos, g_wos);

    cudaFuncSetAttribute(gemm_mma, cudaFuncAttributeMaxDynamicSharedMemorySize, GEMM_DYN);
    const int smem_attn = 4 * 64 * 68 * (int)sizeof(float);
    cudaFuncSetAttribute(attn_fwd, cudaFuncAttributeMaxDynamicSharedMemorySize, smem_attn);

    // Split fp32 -> bf16 hi/lo packed K=3072
    split3<<<MM,   256>>>(x,  xs,  1);
    split3<<<DDIM, 256>>>(Wq, wqs, 0);
    split3<<<DDIM, 256>>>(Wk, wks, 0);
    split3<<<DDIM, 256>>>(Wv, wvs, 0);
    split3<<<DDIM, 256>>>(Wo, wos, 0);

    dim3 ggrid(DDIM / 128, MM / 128);   // (8, 32)
    gemm_mma<<<ggrid, 256, GEMM_DYN>>>(xs, wqs, qb);
    gemm_mma<<<ggrid, 256, GEMM_DYN>>>(xs, wks, kb);
    gemm_mma<<<ggrid, 256, GEMM_DYN>>>(xs, wvs, vb);

    dim3 agrid(TT / 64, HH, BB);
    attn_fwd<<<agrid, 256, smem_attn>>>(ab);

    split3<<<MM, 256>>>(ab, ats, 1);
    gemm_mma<<<ggrid, 256, GEMM_DYN>>>(ats, wos, out);
}

// round 4
// speedup vs baseline: 6.7887x; 5.5709x over previous
#include <cuda_runtime.h>
#include <cuda_bf16.h>
#include <cstdint>

// Problem constants
#define BB   2
#define TT   2048
#define DDIM 1024
#define HH   16
#define HDD  64
#define MM   (BB*TT)   // 4096 rows
#define K3   3072      // GEMM split-K: [hi | hi/lo | lo/hi]
#define DKP  192       // attention packed head dim (64*3)

// Scratch (__device__ globals; no allocations allowed)
__device__ float g_q[MM*DDIM];
__device__ float g_k[MM*DDIM];
__device__ float g_v[MM*DDIM];
__device__ float g_att[MM*DDIM];
__device__ __nv_bfloat16 g_xs[MM*K3];
__device__ __nv_bfloat16 g_atts[MM*K3];
__device__ __nv_bfloat16 g_wqs[DDIM*K3];
__device__ __nv_bfloat16 g_wks[DDIM*K3];
__device__ __nv_bfloat16 g_wvs[DDIM*K3];
__device__ __nv_bfloat16 g_wos[DDIM*K3];
__device__ __nv_bfloat16 g_qp[BB*HH*TT*DKP];
__device__ __nv_bfloat16 g_kp[BB*HH*TT*DKP];
__device__ __nv_bfloat16 g_vth[BB*HH*HDD*TT];
__device__ __nv_bfloat16 g_vtl[BB*HH*HDD*TT];

// ---------------------------------------------------------------------------
__device__ __forceinline__ uint32_t s2u(const void* p) {
    uint32_t a;
    asm("{ .reg .u64 t; cvta.to.shared.u64 t, %1; cvt.u32.u64 %0, t; }" : "=r"(a) : "l"(p));
    return a;
}
__device__ __forceinline__ uint32_t swz(uint32_t o) { return o ^ ((o >> 3) & 0x70); }
__device__ __forceinline__ void cp16(uint32_t dst, const void* src) {
    asm volatile("cp.async.cg.shared.global [%0], [%1], 16;" :: "r"(dst), "l"(src));
}
__device__ __forceinline__ void ldsm4(uint32_t* r, uint32_t addr) {
    asm volatile("ldmatrix.sync.aligned.m8n8.x4.shared.b16 {%0,%1,%2,%3}, [%4];"
                 : "=r"(r[0]), "=r"(r[1]), "=r"(r[2]), "=r"(r[3]) : "r"(addr));
}
__device__ __forceinline__ void mma16816(float* c, const uint32_t* a, const uint32_t* b) {
    asm volatile("mma.sync.aligned.m16n8k16.row.col.f32.bf16.bf16.f32 "
                 "{%0,%1,%2,%3}, {%4,%5,%6,%7}, {%8,%9}, {%0,%1,%2,%3};"
                 : "+f"(c[0]), "+f"(c[1]), "+f"(c[2]), "+f"(c[3])
                 : "r"(a[0]), "r"(a[1]), "r"(a[2]), "r"(a[3]), "r"(b[0]), "r"(b[1]));
}

// ---------------------------------------------------------------------------
// split3: fp32 [rows,1024] -> bf16 [rows,3072]
// amode=1 (activation): [hi | hi | lo]   amode=0 (weight): [hi | lo | hi]
// ---------------------------------------------------------------------------
__global__ __launch_bounds__(256) void split3(const float* __restrict__ in,
                                              __nv_bfloat16* __restrict__ out,
                                              int amode) {
    int idx = (blockIdx.x * 256 + threadIdx.x) * 4;
    int r = idx >> 10, c = idx & 1023;
    float4 v = *(const float4*)(in + idx);
    float vv[4] = {v.x, v.y, v.z, v.w};
    __nv_bfloat16 h[4], l[4];
#pragma unroll
    for (int j = 0; j < 4; j++) {
        h[j] = __float2bfloat16(vv[j]);
        l[j] = __float2bfloat16(vv[j] - __bfloat162float(h[j]));
    }
    size_t base = (size_t)r * K3 + c;
    __nv_bfloat162 h01{h[0], h[1]}, h23{h[2], h[3]};
    __nv_bfloat162 l01{l[0], l[1]}, l23{l[2], l[3]};
    *(__nv_bfloat162*)(out + base)     = h01;
    *(__nv_bfloat162*)(out + base + 2) = h23;
    if (amode) {
        *(__nv_bfloat162*)(out + base + 1024)     = h01;
        *(__nv_bfloat162*)(out + base + 1024 + 2) = h23;
        *(__nv_bfloat162*)(out + base + 2048)     = l01;
        *(__nv_bfloat162*)(out + base + 2048 + 2) = l23;
    } else {
        *(__nv_bfloat162*)(out + base + 1024)     = l01;
        *(__nv_bfloat162*)(out + base + 1024 + 2) = l23;
        *(__nv_bfloat162*)(out + base + 2048)     = h01;
        *(__nv_bfloat162*)(out + base + 2048 + 2) = h23;
    }
}

// ---------------------------------------------------------------------------
// pack_qk: fp32 q/k [B*T,1024] -> packed bf16 [B,H,T,192]
// isq=1: [hi/8 | hi/8 | lo/8]     isq=0: [hi | lo | hi]
// ---------------------------------------------------------------------------
__global__ __launch_bounds__(256) void pack_qk(const float* __restrict__ src,
                                               __nv_bfloat16* __restrict__ dst,
                                               int isq) {
    int e = (blockIdx.x * 256 + threadIdx.x) * 4;
    int row = e >> 10, c = e & 1023;
    int hh = c >> 6, d = c & 63;
    int bb = row >> 11, t = row & 2047;
    float4 v = *(const float4*)(src + e);
    float vv[4] = {v.x, v.y, v.z, v.w};
    __nv_bfloat16 hi[4], lo[4];
#pragma unroll
    for (int j = 0; j < 4; j++) {
        hi[j] = __float2bfloat16(vv[j]);
        float res = vv[j] - __bfloat162float(hi[j]);
        lo[j] = __float2bfloat16(res);
        if (isq) {  // exact power-of-two scale
            hi[j] = __float2bfloat16(__bfloat162float(hi[j]) * 0.125f);
            lo[j] = __float2bfloat16(__bfloat162float(lo[j]) * 0.125f);
        }
    }
    size_t base = ((size_t)(bb * HH + hh) * TT + t) * DKP + d;
    __nv_bfloat162 h01{hi[0], hi[1]}, h23{hi[2], hi[3]};
    __nv_bfloat162 l01{lo[0], lo[1]}, l23{lo[2], lo[3]};
    *(__nv_bfloat162*)(dst + base)     = h01;
    *(__nv_bfloat162*)(dst + base + 2) = h23;
    if (isq) {
        *(__nv_bfloat162*)(dst + base + 64)      = h01;
        *(__nv_bfloat162*)(dst + base + 64 + 2)  = h23;
        *(__nv_bfloat162*)(dst + base + 128)     = l01;
        *(__nv_bfloat162*)(dst + base + 128 + 2) = l23;
    } else {
        *(__nv_bfloat162*)(dst + base + 64)      = l01;
        *(__nv_bfloat162*)(dst + base + 64 + 2)  = l23;
        *(__nv_bfloat162*)(dst + base + 128)     = h01;
        *(__nv_bfloat162*)(dst + base + 128 + 2) = h23;
    }
}

// ---------------------------------------------------------------------------
// vtrans: fp32 V [B*T,1024] -> Vt hi/lo bf16 [B,H,64,T] (transpose per head)
// Grid (T/64, H, B), 256 threads.
// ---------------------------------------------------------------------------
__global__ __launch_bounds__(256) void vtrans(const float* __restrict__ vsrc,
                                              __nv_bfloat16* __restrict__ vh,
                                              __nv_bfloat16* __restrict__ vl) {
    __shared__ float tile[64][65];
    int t0 = blockIdx.x << 6, h = blockIdx.y, b = blockIdx.z;
    int tid = threadIdx.x;
#pragma unroll
    for (int it = 0; it < 4; it++) {
        int idx = tid + it * 256;
        int r = idx >> 4, c4 = (idx & 15) << 2;
        float4 v = *(const float4*)&vsrc[(size_t)(b * TT + t0 + r) * DDIM + h * HDD + c4];
        tile[r][c4] = v.x; tile[r][c4 + 1] = v.y; tile[r][c4 + 2] = v.z; tile[r][c4 + 3] = v.w;
    }
    __syncthreads();
    size_t obase = (size_t)(b * HH + h) * HDD;
#pragma unroll
    for (int it = 0; it < 2; it++) {
        int idx = tid + it * 256;
        int d = idx >> 3, ts = (idx & 7) << 3;
        uint32_t hw[4], lw[4];
#pragma unroll
        for (int i = 0; i < 4; i++) {
            float x0 = tile[ts + 2 * i][d], x1 = tile[ts + 2 * i + 1][d];
            __nv_bfloat16 h0 = __float2bfloat16(x0), h1 = __float2bfloat16(x1);
            __nv_bfloat16 l0 = __float2bfloat16(x0 - __bfloat162float(h0));
            __nv_bfloat16 l1 = __float2bfloat16(x1 - __bfloat162float(h1));
            __nv_bfloat162 hp{h0, h1}, lp{l0, l1};
            hw[i] = *(uint32_t*)&hp; lw[i] = *(uint32_t*)&lp;
        }
        size_t o = (obase + d) * TT + t0 + ts;
        *(uint4*)(vh + o) = make_uint4(hw[0], hw[1], hw[2], hw[3]);
        *(uint4*)(vl + o) = make_uint4(lw[0], lw[1], lw[2], lw[3]);
    }
}

// ---------------------------------------------------------------------------
// mma.sync bf16 NT GEMM (unchanged from R3): C[4096,1024]=A[4096,3072]@B^T
// ---------------------------------------------------------------------------
#define BK      64
#define STAGES  3
#define NCHUNK  (K3 / BK)                 // 48
#define STG_A   (128 * 128)
#define STG_B   (128 * 128)
#define STG_SZ  (STG_A + STG_B)
#define GEMM_DYN (STAGES * STG_SZ + 1024)

__global__ __launch_bounds__(256) void gemm_mma(const __nv_bfloat16* __restrict__ A,
                                                const __nv_bfloat16* __restrict__ B,
                                                float* __restrict__ C) {
    extern __shared__ char dyn[];
    const int tid  = threadIdx.x;
    const int wid  = tid >> 5, lane = tid & 31;
    const int wm   = wid >> 2;
    const int wn   = wid & 3;
    const int m0   = blockIdx.y << 7;
    const int n0   = blockIdx.x << 7;

    const uint32_t sbase = (s2u(dyn) + 1023) & ~1023u;
    const int lrow = tid >> 3;
    const int ls16 = tid & 7;

    float acc[4][4][4];
#pragma unroll
    for (int mi = 0; mi < 4; mi++)
#pragma unroll
        for (int ni = 0; ni < 4; ni++)
#pragma unroll
            for (int j = 0; j < 4; j++) acc[mi][ni][j] = 0.f;

    const int sub  = lane >> 3;
    const int lr8  = lane & 7;
    const int aRowOff = ((sub & 1) << 3) + lr8;
    const int aKHalf  = (sub >> 1) << 4;
    const int bRowOff = ((sub >> 1) << 3) + lr8;
    const int bKHalf  = (sub & 1) << 4;

#define LOAD_CHUNK(c)                                                            \
    {                                                                            \
        const int s_ = (c) % STAGES;                                             \
        const uint32_t sA_ = sbase + s_ * STG_SZ;                                \
        const uint32_t sB_ = sA_ + STG_A;                                        \
        _Pragma("unroll")                                                        \
        for (int it = 0; it < 4; it++) {                                         \
            int row = lrow + (it << 5);                                          \
            cp16(sA_ + swz(row * 128 + ls16 * 16),                               \
                 A + (size_t)(m0 + row) * K3 + (c) * BK + ls16 * 8);             \
        }                                                                        \
        _Pragma("unroll")                                                        \
        for (int it = 0; it < 4; it++) {                                         \
            int row = lrow + (it << 5);                                          \
            cp16(sB_ + swz(row * 128 + ls16 * 16),                               \
                 B + (size_t)(n0 + row) * K3 + (c) * BK + ls16 * 8);             \
        }                                                                        \
        asm volatile("cp.async.commit_group;" ::: "memory");                     \
    }

    LOAD_CHUNK(0);
    LOAD_CHUNK(1);

    for (int i = 0; i < NCHUNK; i++) {
        if (i < NCHUNK - 1) asm volatile("cp.async.wait_group 1;" ::: "memory");
        else                asm volatile("cp.async.wait_group 0;" ::: "memory");
        __syncthreads();

        if (i + 2 < NCHUNK) LOAD_CHUNK(i + 2);

        const int s = i % STAGES;
        const uint32_t sA = sbase + s * STG_SZ;
        const uint32_t sB = sA + STG_A;

#pragma unroll
        for (int kk = 0; kk < 4; kk++) {
            uint32_t af[4][4], bf[2][4];
#pragma unroll
            for (int mi = 0; mi < 4; mi++) {
                int row = wm * 64 + mi * 16 + aRowOff;
                ldsm4(af[mi], sA + swz(row * 128 + kk * 32 + aKHalf));
            }
#pragma unroll
            for (int p = 0; p < 2; p++) {
                int row = wn * 32 + p * 16 + bRowOff;
                ldsm4(bf[p], sB + swz(row * 128 + kk * 32 + bKHalf));
            }
#pragma unroll
            for (int mi = 0; mi < 4; mi++) {
                mma16816(acc[mi][0], af[mi], &bf[0][0]);
                mma16816(acc[mi][1], af[mi], &bf[0][2]);
                mma16816(acc[mi][2], af[mi], &bf[1][0]);
                mma16816(acc[mi][3], af[mi], &bf[1][2]);
            }
        }
    }

    const int lr = lane >> 2, lc = (lane & 3) << 1;
#pragma unroll
    for (int mi = 0; mi < 4; mi++) {
#pragma unroll
        for (int ni = 0; ni < 4; ni++) {
            int grow = m0 + wm * 64 + mi * 16 + lr;
            int gcol = n0 + wn * 32 + ni * 8 + lc;
            *(float2*)&C[(size_t)grow * DDIM + gcol] =
                make_float2(acc[mi][ni][0], acc[mi][ni][1]);
            *(float2*)&C[(size_t)(grow + 8) * DDIM + gcol] =
                make_float2(acc[mi][ni][2], acc[mi][ni][3]);
        }
    }
#undef LOAD_CHUNK
}

// ---------------------------------------------------------------------------
// Tensor-core flash attention.
// Grid (T/128, H, B), 256 threads, 8 warps x 16 q-rows.
// Q packed [b,h,t,192] in regs; K packed tiles + Vt hi/lo tiles double-buffered.
// ---------------------------------------------------------------------------
#define ATT_QSZ   49152                    // 3 planes x (128 x 128B)
#define ATT_STG   40960                    // K 3x8KB + Vh 8KB + Vl 8KB
#define ATT_DYN   (ATT_QSZ + 2*ATT_STG + 1024)

__global__ __launch_bounds__(256, 1) void attn_mma(const __nv_bfloat16* __restrict__ Qp,
                                                   const __nv_bfloat16* __restrict__ Kp,
                                                   const __nv_bfloat16* __restrict__ Vth,
                                                   const __nv_bfloat16* __restrict__ Vtl,
                                                   float* __restrict__ Oo) {
    extern __shared__ char dyn[];
    const int tid = threadIdx.x, wid = tid >> 5, lane = tid & 31;
    const int qb = blockIdx.x, h = blockIdx.y, b = blockIdx.z;
    const int q0 = qb << 7;
    const int ntiles = 2 * qb + 2;

    const uint32_t sb = (s2u(dyn) + 1023) & ~1023u;
    const uint32_t QS = sb;
    const uint32_t ST0 = sb + ATT_QSZ;
    const uint32_t ST1 = ST0 + ATT_STG;

    const int sub = lane >> 3, lr8 = lane & 7;
    const int aRowOff = ((sub & 1) << 3) + lr8;
    const int aKHalf  = (sub >> 1) << 4;
    const int bRowOff = ((sub >> 1) << 3) + lr8;
    const int bKHalf  = (sub & 1) << 4;

    const size_t bh = (size_t)(b * HH + h);
    const __nv_bfloat16* Qg  = Qp  + (bh * TT + q0) * DKP;
    const __nv_bfloat16* Kg  = Kp  + bh * TT * DKP;
    const __nv_bfloat16* Vhg = Vth + bh * HDD * TT;
    const __nv_bfloat16* Vlg = Vtl + bh * HDD * TT;

    // Q tile: 3072 16B units
#pragma unroll
    for (int it = 0; it < 12; it++) {
        int idx = tid + it * 256;
        int pl = idx >> 10, rem = idx & 1023, row = rem >> 3, seg = rem & 7;
        cp16(QS + pl * 16384 + swz(row * 128 + seg * 16),
             Qg + (size_t)row * DKP + pl * 64 + seg * 8);
    }
    asm volatile("cp.async.commit_group;" ::: "memory");

    auto load_kv = [&](int jt) {
        const uint32_t S = (jt & 1) ? ST1 : ST0;
        const int kv0 = jt << 6;
#pragma unroll
        for (int it = 0; it < 6; it++) {       // K: 1536 units
            int idx = tid + it * 256;
            int pl = idx >> 9, rem = idx & 511, row = rem >> 3, seg = rem & 7;
            cp16(S + pl * 8192 + swz(row * 128 + seg * 16),
                 Kg + (size_t)(kv0 + row) * DKP + pl * 64 + seg * 8);
        }
#pragma unroll
        for (int it = 0; it < 2; it++) {       // Vh: 512 units
            int idx = tid + it * 256;
            int row = idx >> 3, seg = idx & 7;
            cp16(S + 24576 + swz(row * 128 + seg * 16),
                 Vhg + (size_t)row * TT + kv0 + seg * 8);
        }
#pragma unroll
        for (int it = 0; it < 2; it++) {       // Vl
            int idx = tid + it * 256;
            int row = idx >> 3, seg = idx & 7;
            cp16(S + 32768 + swz(row * 128 + seg * 16),
                 Vlg + (size_t)row * TT + kv0 + seg * 8);
        }
        asm volatile("cp.async.commit_group;" ::: "memory");
    };
    load_kv(0);
    load_kv(1);

    asm volatile("cp.async.wait_group 2;" ::: "memory");
    __syncthreads();

    uint32_t qa[12][4];
#pragma unroll
    for (int kk = 0; kk < 12; kk++) {
        int row = wid * 16 + aRowOff;
        ldsm4(qa[kk], QS + (kk >> 2) * 16384 + swz(row * 128 + (kk & 3) * 32 + aKHalf));
    }

    float oc[8][4];
#pragma unroll
    for (int j = 0; j < 8; j++)
#pragma unroll
        for (int e = 0; e < 4; e++) oc[j][e] = 0.f;
    float m0 = -1e30f, m1 = -1e30f, l0 = 0.f, l1 = 0.f;

    const int trow0 = q0 + wid * 16 + (lane >> 2);

    for (int jt = 0; jt < ntiles; jt++) {
        if (jt + 1 < ntiles) asm volatile("cp.async.wait_group 1;" ::: "memory");
        else                 asm volatile("cp.async.wait_group 0;" ::: "memory");
        __syncthreads();
        const uint32_t S = (jt & 1) ? ST1 : ST0;

        // ---- scores: S = Qpack @ Kpack^T (K=192) ----
        float sc[8][4];
#pragma unroll
        for (int j = 0; j < 8; j++)
#pragma unroll
            for (int e = 0; e < 4; e++) sc[j][e] = 0.f;
#pragma unroll
        for (int kk = 0; kk < 12; kk++) {
            uint32_t kf[4][4];
#pragma unroll
            for (int p = 0; p < 4; p++)
                ldsm4(kf[p], S + (kk >> 2) * 8192 +
                      swz((p * 16 + bRowOff) * 128 + (kk & 3) * 32 + bKHalf));
#pragma unroll
            for (int j = 0; j < 8; j++)
                mma16816(sc[j], qa[kk], &kf[j >> 1][(j & 1) * 2]);
        }

        // ---- causal mask (only near-diagonal tiles) ----
        if (jt >= 2 * qb) {
            int s0c = jt << 6;
#pragma unroll
            for (int j = 0; j < 8; j++) {
                int scol = s0c + 8 * j + ((lane & 3) << 1);
                if (scol     > trow0)     sc[j][0] = -1e30f;
                if (scol + 1 > trow0)     sc[j][1] = -1e30f;
                if (scol     > trow0 + 8) sc[j][2] = -1e30f;
                if (scol + 1 > trow0 + 8) sc[j][3] = -1e30f;
            }
        }

        // ---- online softmax (rows warp-local; quad shuffle) ----
        float r0 = -1e30f, r1 = -1e30f;
#pragma unroll
        for (int j = 0; j < 8; j++) {
            r0 = fmaxf(r0, fmaxf(sc[j][0], sc[j][1]));
            r1 = fmaxf(r1, fmaxf(sc[j][2], sc[j][3]));
        }
        r0 = fmaxf(r0, __shfl_xor_sync(0xffffffffu, r0, 1));
        r0 = fmaxf(r0, __shfl_xor_sync(0xffffffffu, r0, 2));
        r1 = fmaxf(r1, __shfl_xor_sync(0xffffffffu, r1, 1));
        r1 = fmaxf(r1, __shfl_xor_sync(0xffffffffu, r1, 2));
        float mn0 = fmaxf(m0, r0), mn1 = fmaxf(m1, r1);
        float a0 = __expf(m0 - mn0), a1 = __expf(m1 - mn1);
        float s0 = 0.f, s1 = 0.f;
#pragma unroll
        for (int j = 0; j < 8; j++) {
            sc[j][0] = __expf(sc[j][0] - mn0); sc[j][1] = __expf(sc[j][1] - mn0);
            sc[j][2] = __expf(sc[j][2] - mn1); sc[j][3] = __expf(sc[j][3] - mn1);
            s0 += sc[j][0] + sc[j][1];         s1 += sc[j][2] + sc[j][3];
        }
        s0 += __shfl_xor_sync(0xffffffffu, s0, 1);
        s0 += __shfl_xor_sync(0xffffffffu, s0, 2);
        s1 += __shfl_xor_sync(0xffffffffu, s1, 1);
        s1 += __shfl_xor_sync(0xffffffffu, s1, 2);
        l0 = l0 * a0 + s0; l1 = l1 * a1 + s1; m0 = mn0; m1 = mn1;
#pragma unroll
        for (int j = 0; j < 8; j++) {
            oc[j][0] *= a0; oc[j][1] *= a0; oc[j][2] *= a1; oc[j][3] *= a1;
        }

        // ---- pack P hi/lo (C-frag -> A-frag, register-only) ----
        uint32_t ph[8][2], pl_[8][2];
#pragma unroll
        for (int j = 0; j < 8; j++) {
            __nv_bfloat16 h0 = __float2bfloat16(sc[j][0]), h1 = __float2bfloat16(sc[j][1]);
            __nv_bfloat16 h2 = __float2bfloat16(sc[j][2]), h3 = __float2bfloat16(sc[j][3]);
            __nv_bfloat162 t01{h0, h1}, t23{h2, h3};
            ph[j][0] = *(uint32_t*)&t01; ph[j][1] = *(uint32_t*)&t23;
            __nv_bfloat16 g0 = __float2bfloat16(sc[j][0] - __bfloat162float(h0));
            __nv_bfloat16 g1 = __float2bfloat16(sc[j][1] - __bfloat162float(h1));
            __nv_bfloat16 g2 = __float2bfloat16(sc[j][2] - __bfloat162float(h2));
            __nv_bfloat16 g3 = __float2bfloat16(sc[j][3] - __bfloat162float(h3));
            __nv_bfloat162 u01{g0, g1}, u23{g2, g3};
            pl_[j][0] = *(uint32_t*)&u01; pl_[j][1] = *(uint32_t*)&u23;
        }

        // ---- PV: O += Phi@Vhi + Phi@Vlo + Plo@Vhi ----
#pragma unroll
        for (int kc = 0; kc < 4; kc++) {
            uint32_t pah[4] = {ph[2*kc][0],  ph[2*kc][1],  ph[2*kc+1][0],  ph[2*kc+1][1]};
            uint32_t pal[4] = {pl_[2*kc][0], pl_[2*kc][1], pl_[2*kc+1][0], pl_[2*kc+1][1]};
            uint32_t vhf[4][4], vlf[4][4];
#pragma unroll
            for (int p = 0; p < 4; p++) {
                ldsm4(vhf[p], S + 24576 + swz((p * 16 + bRowOff) * 128 + kc * 32 + bKHalf));
                ldsm4(vlf[p], S + 32768 + swz((p * 16 + bRowOff) * 128 + kc * 32 + bKHalf));
            }
#pragma unroll
            for (int j = 0; j < 8; j++) {
                mma16816(oc[j], pah, &vhf[j >> 1][(j & 1) * 2]);
                mma16816(oc[j], pah, &vlf[j >> 1][(j & 1) * 2]);
                mma16816(oc[j], pal, &vhf[j >> 1][(j & 1) * 2]);
            }
        }
        __syncthreads();
        if (jt + 2 < ntiles) load_kv(jt + 2);
    }

    float i0 = 1.f / l0, i1 = 1.f / l1;
    size_t rb0 = (size_t)(b * TT + trow0) * DDIM + h * HDD;
    size_t rb1 = rb0 + (size_t)8 * DDIM;
#pragma unroll
    for (int j = 0; j < 8; j++) {
        int col = 8 * j + ((lane & 3) << 1);
        *(float2*)&Oo[rb0 + col] = make_float2(oc[j][0] * i0, oc[j][1] * i0);
        *(float2*)&Oo[rb1 + col] = make_float2(oc[j][2] * i1, oc[j][3] * i1);
    }
}

// ---------------------------------------------------------------------------
extern "C" void kernel_launch(void* const* d_in, const int* in_sizes, int n_in,
                              void* d_out, int out_size) {
    const float* x  = (const float*)d_in[0];
    const float* Wq = (const float*)d_in[1];
    const float* Wk = (const float*)d_in[2];
    const float* Wv = (const float*)d_in[3];
    const float* Wo = (const float*)d_in[4];
    float* out = (float*)d_out;

    float *qb, *kb, *vb, *ab;
    __nv_bfloat16 *xs, *ats, *wqs, *wks, *wvs, *wos, *qp, *kp, *vth, *vtl;
    cudaGetSymbolAddress((void**)&qb, g_q);
    cudaGetSymbolAddress((void**)&kb, g_k);
    cudaGetSymbolAddress((void**)&vb, g_v);
    cudaGetSymbolAddress((void**)&ab, g_att);
    cudaGetSymbolAddress((void**)&xs, g_xs);
    cudaGetSymbolAddress((void**)&ats, g_atts);
    cudaGetSymbolAddress((void**)&wqs, g_wqs);
    cudaGetSymbolAddress((void**)&wks, g_wks);
    cudaGetSymbolAddress((void**)&wvs, g_wvs);
    cudaGetSymbolAddress((void**)&wos, g_wos);
    cudaGetSymbolAddress((void**)&qp, g_qp);
    cudaGetSymbolAddress((void**)&kp, g_kp);
    cudaGetSymbolAddress((void**)&vth, g_vth);
    cudaGetSymbolAddress((void**)&vtl, g_vtl);

    cudaFuncSetAttribute(gemm_mma, cudaFuncAttributeMaxDynamicSharedMemorySize, GEMM_DYN);
    cudaFuncSetAttribute(attn_mma, cudaFuncAttributeMaxDynamicSharedMemorySize, ATT_DYN);

    // fp32 -> bf16 hi/lo packed K=3072 (projection GEMM operands)
    split3<<<MM,   256>>>(x,  xs,  1);
    split3<<<DDIM, 256>>>(Wq, wqs, 0);
    split3<<<DDIM, 256>>>(Wk, wks, 0);
    split3<<<DDIM, 256>>>(Wv, wvs, 0);
    split3<<<DDIM, 256>>>(Wo, wos, 0);

    dim3 ggrid(DDIM / 128, MM / 128);   // (8, 32)
    gemm_mma<<<ggrid, 256, GEMM_DYN>>>(xs, wqs, qb);
    gemm_mma<<<ggrid, 256, GEMM_DYN>>>(xs, wks, kb);
    gemm_mma<<<ggrid, 256, GEMM_DYN>>>(xs, wvs, vb);

    // attention operand prep
    pack_qk<<<MM * DDIM / 1024, 256>>>(qb, qp, 1);
    pack_qk<<<MM * DDIM / 1024, 256>>>(kb, kp, 0);
    dim3 vgrid(TT / 64, HH, BB);
    vtrans<<<vgrid, 256>>>(vb, vth, vtl);

    dim3 agrid(TT / 128, HH, BB);       // (16, 16, 2)
    attn_mma<<<agrid, 256, ATT_DYN>>>(qp, kp, vth, vtl, ab);

    split3<<<MM, 256>>>(ab, ats, 1);
    gemm_mma<<<ggrid, 256, GEMM_DYN>>>(ats, wos, out);
}

// round 5
// speedup vs baseline: 7.0271x; 1.0351x over previous
#include <cuda_runtime.h>
#include <cuda_bf16.h>
#include <cstdint>

// Problem constants
#define BB   2
#define TT   2048
#define DDIM 1024
#define HH   16
#define HDD  64
#define MM   (BB*TT)   // 4096 rows
#define K3   3072      // GEMM split-K: [hi | hi/lo | lo/hi]
#define DKP  192       // attention packed head dim (64*3)

// Scratch (__device__ globals; no allocations allowed)
__device__ float g_v[MM*DDIM];
__device__ __nv_bfloat16 g_xs[MM*K3];
__device__ __nv_bfloat16 g_atts[MM*K3];
__device__ __nv_bfloat16 g_wqs[DDIM*K3];
__device__ __nv_bfloat16 g_wks[DDIM*K3];
__device__ __nv_bfloat16 g_wvs[DDIM*K3];
__device__ __nv_bfloat16 g_wos[DDIM*K3];
__device__ __nv_bfloat16 g_qp[BB*HH*TT*DKP];
__device__ __nv_bfloat16 g_kp[BB*HH*TT*DKP];
__device__ __nv_bfloat16 g_vth[BB*HH*HDD*TT];
__device__ __nv_bfloat16 g_vtl[BB*HH*HDD*TT];

// ---------------------------------------------------------------------------
__device__ __forceinline__ uint32_t s2u(const void* p) {
    uint32_t a;
    asm("{ .reg .u64 t; cvta.to.shared.u64 t, %1; cvt.u32.u64 %0, t; }" : "=r"(a) : "l"(p));
    return a;
}
__device__ __forceinline__ uint32_t swz(uint32_t o) { return o ^ ((o >> 3) & 0x70); }
__device__ __forceinline__ void cp16(uint32_t dst, const void* src) {
    asm volatile("cp.async.cg.shared.global [%0], [%1], 16;" :: "r"(dst), "l"(src));
}
__device__ __forceinline__ void ldsm4(uint32_t* r, uint32_t addr) {
    asm volatile("ldmatrix.sync.aligned.m8n8.x4.shared.b16 {%0,%1,%2,%3}, [%4];"
                 : "=r"(r[0]), "=r"(r[1]), "=r"(r[2]), "=r"(r[3]) : "r"(addr));
}
__device__ __forceinline__ void mma16816(float* c, const uint32_t* a, const uint32_t* b) {
    asm volatile("mma.sync.aligned.m16n8k16.row.col.f32.bf16.bf16.f32 "
                 "{%0,%1,%2,%3}, {%4,%5,%6,%7}, {%8,%9}, {%0,%1,%2,%3};"
                 : "+f"(c[0]), "+f"(c[1]), "+f"(c[2]), "+f"(c[3])
                 : "r"(a[0]), "r"(a[1]), "r"(a[2]), "r"(a[3]), "r"(b[0]), "r"(b[1]));
}
// split v into bf16 hi + lo packed as bf16x2 words
__device__ __forceinline__ void split_pair(float v0, float v1, uint32_t& hi2, uint32_t& lo2,
                                           float scale) {
    __nv_bfloat16 h0 = __float2bfloat16(v0), h1 = __float2bfloat16(v1);
    __nv_bfloat16 l0 = __float2bfloat16(v0 - __bfloat162float(h0));
    __nv_bfloat16 l1 = __float2bfloat16(v1 - __bfloat162float(h1));
    if (scale != 1.f) {   // exact power-of-two rescale
        h0 = __float2bfloat16(__bfloat162float(h0) * scale);
        h1 = __float2bfloat16(__bfloat162float(h1) * scale);
        l0 = __float2bfloat16(__bfloat162float(l0) * scale);
        l1 = __float2bfloat16(__bfloat162float(l1) * scale);
    }
    __nv_bfloat162 hp{h0, h1}, lp{l0, l1};
    hi2 = *(uint32_t*)&hp; lo2 = *(uint32_t*)&lp;
}

// ---------------------------------------------------------------------------
// split3: fp32 [rows,1024] -> bf16 [rows,3072]  (activation: [hi | hi | lo])
// ---------------------------------------------------------------------------
__global__ __launch_bounds__(256) void split3(const float* __restrict__ in,
                                              __nv_bfloat16* __restrict__ out) {
    int idx = (blockIdx.x * 256 + threadIdx.x) * 4;
    int r = idx >> 10, c = idx & 1023;
    float4 v = *(const float4*)(in + idx);
    uint32_t h01, l01, h23, l23;
    split_pair(v.x, v.y, h01, l01, 1.f);
    split_pair(v.z, v.w, h23, l23, 1.f);
    size_t base = (size_t)r * K3 + c;
    *(uint32_t*)((__nv_bfloat16*)out + base)            = h01;
    *(uint32_t*)((__nv_bfloat16*)out + base + 2)        = h23;
    *(uint32_t*)((__nv_bfloat16*)out + base + 1024)     = h01;
    *(uint32_t*)((__nv_bfloat16*)out + base + 1024 + 2) = h23;
    *(uint32_t*)((__nv_bfloat16*)out + base + 2048)     = l01;
    *(uint32_t*)((__nv_bfloat16*)out + base + 2048 + 2) = l23;
}

// wsplit4: all four weights in one launch (weight layout: [hi | lo | hi])
__global__ __launch_bounds__(256) void wsplit4(const float* __restrict__ w0,
                                               const float* __restrict__ w1,
                                               const float* __restrict__ w2,
                                               const float* __restrict__ w3,
                                               __nv_bfloat16* __restrict__ o0,
                                               __nv_bfloat16* __restrict__ o1,
                                               __nv_bfloat16* __restrict__ o2,
                                               __nv_bfloat16* __restrict__ o3) {
    const float* in; __nv_bfloat16* out;
    switch (blockIdx.y) {
        case 0: in = w0; out = o0; break;
        case 1: in = w1; out = o1; break;
        case 2: in = w2; out = o2; break;
        default: in = w3; out = o3; break;
    }
    int idx = (blockIdx.x * 256 + threadIdx.x) * 4;
    int r = idx >> 10, c = idx & 1023;
    float4 v = *(const float4*)(in + idx);
    uint32_t h01, l01, h23, l23;
    split_pair(v.x, v.y, h01, l01, 1.f);
    split_pair(v.z, v.w, h23, l23, 1.f);
    size_t base = (size_t)r * K3 + c;
    *(uint32_t*)(out + base)            = h01;
    *(uint32_t*)(out + base + 2)        = h23;
    *(uint32_t*)(out + base + 1024)     = l01;
    *(uint32_t*)(out + base + 1024 + 2) = l23;
    *(uint32_t*)(out + base + 2048)     = h01;
    *(uint32_t*)(out + base + 2048 + 2) = h23;
}

// ---------------------------------------------------------------------------
// vtrans: fp32 V [B*T,1024] -> Vt hi/lo bf16 [B,H,64,T]
// ---------------------------------------------------------------------------
__global__ __launch_bounds__(256) void vtrans(const float* __restrict__ vsrc,
                                              __nv_bfloat16* __restrict__ vh,
                                              __nv_bfloat16* __restrict__ vl) {
    __shared__ float tile[64][65];
    int t0 = blockIdx.x << 6, h = blockIdx.y, b = blockIdx.z;
    int tid = threadIdx.x;
#pragma unroll
    for (int it = 0; it < 4; it++) {
        int idx = tid + it * 256;
        int r = idx >> 4, c4 = (idx & 15) << 2;
        float4 v = *(const float4*)&vsrc[(size_t)(b * TT + t0 + r) * DDIM + h * HDD + c4];
        tile[r][c4] = v.x; tile[r][c4 + 1] = v.y; tile[r][c4 + 2] = v.z; tile[r][c4 + 3] = v.w;
    }
    __syncthreads();
    size_t obase = (size_t)(b * HH + h) * HDD;
#pragma unroll
    for (int it = 0; it < 2; it++) {
        int idx = tid + it * 256;
        int d = idx >> 3, ts = (idx & 7) << 3;
        uint32_t hw[4], lw[4];
#pragma unroll
        for (int i = 0; i < 4; i++)
            split_pair(tile[ts + 2 * i][d], tile[ts + 2 * i + 1][d], hw[i], lw[i], 1.f);
        size_t o = (obase + d) * TT + t0 + ts;
        *(uint4*)(vh + o) = make_uint4(hw[0], hw[1], hw[2], hw[3]);
        *(uint4*)(vl + o) = make_uint4(lw[0], lw[1], lw[2], lw[3]);
    }
}

// ---------------------------------------------------------------------------
// mma.sync bf16 NT GEMM: C[4096,1024] = A[4096,3072] @ B[1024,3072]^T
// CTA tile 128x256, warp tile 64x64 (8 warps), BK=64, 3-stage cp.async.
// mode 0: fp32 C out.  mode 1: Q-pack -> [b,h,t,192] [hi/8|hi/8|lo/8].
// mode 2: K-pack -> [hi|lo|hi].
// ---------------------------------------------------------------------------
#define BK      64
#define STAGES  3
#define NCHUNK  (K3 / BK)                 // 48
#define STG_A   (128 * 128)               // 16 KB
#define STG_B   (256 * 128)               // 32 KB
#define STG_SZ  (STG_A + STG_B)           // 48 KB
#define GEMM_DYN (STAGES * STG_SZ + 1024)

__global__ __launch_bounds__(256, 1) void gemm_mma(const __nv_bfloat16* __restrict__ A,
                                                   const __nv_bfloat16* __restrict__ B,
                                                   void* __restrict__ Cout, int mode) {
    extern __shared__ char dyn[];
    const int tid  = threadIdx.x;
    const int wid  = tid >> 5, lane = tid & 31;
    const int wm   = wid >> 2;            // 0..1 (64-row slab)
    const int wn   = wid & 3;             // 0..3 (64-col slab)
    const int m0   = blockIdx.y << 7;
    const int n0   = blockIdx.x << 8;

    const uint32_t sbase = (s2u(dyn) + 1023) & ~1023u;
    const int lrow = tid >> 3;
    const int ls16 = tid & 7;

    float acc[4][8][4];
#pragma unroll
    for (int mi = 0; mi < 4; mi++)
#pragma unroll
        for (int ni = 0; ni < 8; ni++)
#pragma unroll
            for (int j = 0; j < 4; j++) acc[mi][ni][j] = 0.f;

    const int sub  = lane >> 3;
    const int lr8  = lane & 7;
    const int aRowOff = ((sub & 1) << 3) + lr8;
    const int aKHalf  = (sub >> 1) << 4;
    const int bRowOff = ((sub >> 1) << 3) + lr8;
    const int bKHalf  = (sub & 1) << 4;

#define LOAD_CHUNK(c)                                                            \
    {                                                                            \
        const int s_ = (c) % STAGES;                                             \
        const uint32_t sA_ = sbase + s_ * STG_SZ;                                \
        const uint32_t sB_ = sA_ + STG_A;                                        \
        _Pragma("unroll")                                                        \
        for (int it = 0; it < 4; it++) {                                         \
            int row = lrow + (it << 5);                                          \
            cp16(sA_ + swz(row * 128 + ls16 * 16),                               \
                 A + (size_t)(m0 + row) * K3 + (c) * BK + ls16 * 8);             \
        }                                                                        \
        _Pragma("unroll")                                                        \
        for (int it = 0; it < 8; it++) {                                         \
            int row = lrow + (it << 5);                                          \
            cp16(sB_ + swz(row * 128 + ls16 * 16),                               \
                 B + (size_t)(n0 + row) * K3 + (c) * BK + ls16 * 8);             \
        }                                                                        \
        asm volatile("cp.async.commit_group;" ::: "memory");                     \
    }

    LOAD_CHUNK(0);
    LOAD_CHUNK(1);

    for (int i = 0; i < NCHUNK; i++) {
        if (i < NCHUNK - 1) asm volatile("cp.async.wait_group 1;" ::: "memory");
        else                asm volatile("cp.async.wait_group 0;" ::: "memory");
        __syncthreads();

        if (i + 2 < NCHUNK) LOAD_CHUNK(i + 2);

        const int s = i % STAGES;
        const uint32_t sA = sbase + s * STG_SZ;
        const uint32_t sB = sA + STG_A;

#pragma unroll
        for (int kk = 0; kk < 4; kk++) {
            uint32_t af[4][4], bf[4][4];
#pragma unroll
            for (int mi = 0; mi < 4; mi++) {
                int row = wm * 64 + mi * 16 + aRowOff;
                ldsm4(af[mi], sA + swz(row * 128 + kk * 32 + aKHalf));
            }
#pragma unroll
            for (int p = 0; p < 4; p++) {
                int row = wn * 64 + p * 16 + bRowOff;
                ldsm4(bf[p], sB + swz(row * 128 + kk * 32 + bKHalf));
            }
#pragma unroll
            for (int mi = 0; mi < 4; mi++)
#pragma unroll
                for (int nj = 0; nj < 8; nj++)
                    mma16816(acc[mi][nj], af[mi], &bf[nj >> 1][(nj & 1) * 2]);
        }
    }

    const int lr = lane >> 2, lc = (lane & 3) << 1;
    if (mode == 0) {
        float* C = (float*)Cout;
#pragma unroll
        for (int mi = 0; mi < 4; mi++)
#pragma unroll
            for (int nj = 0; nj < 8; nj++) {
                int grow = m0 + wm * 64 + mi * 16 + lr;
                int gcol = n0 + wn * 64 + nj * 8 + lc;
                *(float2*)&C[(size_t)grow * DDIM + gcol] =
                    make_float2(acc[mi][nj][0], acc[mi][nj][1]);
                *(float2*)&C[(size_t)(grow + 8) * DDIM + gcol] =
                    make_float2(acc[mi][nj][2], acc[mi][nj][3]);
            }
    } else {
        __nv_bfloat16* P = (__nv_bfloat16*)Cout;
        const float sc = (mode == 1) ? 0.125f : 1.f;
        const int hh = (n0 >> 6) + wn;   // warp slab == one head
#pragma unroll
        for (int mi = 0; mi < 4; mi++)
#pragma unroll
            for (int nj = 0; nj < 8; nj++) {
                int grow = m0 + wm * 64 + mi * 16 + lr;
                int d    = nj * 8 + lc;
#pragma unroll
                for (int half = 0; half < 2; half++) {
                    int row = grow + half * 8;
                    int b = row >> 11, t = row & 2047;
                    size_t base = ((size_t)(b * HH + hh) * TT + t) * DKP + d;
                    uint32_t hi2, lo2;
                    split_pair(acc[mi][nj][half * 2], acc[mi][nj][half * 2 + 1], hi2, lo2, sc);
                    if (mode == 1) {          // Q: [hi | hi | lo]
                        *(uint32_t*)(P + base)       = hi2;
                        *(uint32_t*)(P + base + 64)  = hi2;
                        *(uint32_t*)(P + base + 128) = lo2;
                    } else {                  // K: [hi | lo | hi]
                        *(uint32_t*)(P + base)       = hi2;
                        *(uint32_t*)(P + base + 64)  = lo2;
                        *(uint32_t*)(P + base + 128) = hi2;
                    }
                }
            }
    }
#undef LOAD_CHUNK
}

// ---------------------------------------------------------------------------
// Tensor-core flash attention. Writes split-K3 bf16 activation directly.
// Grid (T/128, H, B), 256 threads, 8 warps x 16 q-rows.
// ---------------------------------------------------------------------------
#define ATT_QSZ   49152                    // 3 planes x (128 x 128B)
#define ATT_STG   40960                    // K 3x8KB + Vh 8KB + Vl 8KB
#define ATT_DYN   (ATT_QSZ + 2*ATT_STG + 1024)

__global__ __launch_bounds__(256, 1) void attn_mma(const __nv_bfloat16* __restrict__ Qp,
                                                   const __nv_bfloat16* __restrict__ Kp,
                                                   const __nv_bfloat16* __restrict__ Vth,
                                                   const __nv_bfloat16* __restrict__ Vtl,
                                                   __nv_bfloat16* __restrict__ Osplit) {
    extern __shared__ char dyn[];
    const int tid = threadIdx.x, wid = tid >> 5, lane = tid & 31;
    const int qb = blockIdx.x, h = blockIdx.y, b = blockIdx.z;
    const int q0 = qb << 7;
    const int ntiles = 2 * qb + 2;

    const uint32_t sb = (s2u(dyn) + 1023) & ~1023u;
    const uint32_t QS = sb;
    const uint32_t ST0 = sb + ATT_QSZ;
    const uint32_t ST1 = ST0 + ATT_STG;

    const int sub = lane >> 3, lr8 = lane & 7;
    const int aRowOff = ((sub & 1) << 3) + lr8;
    const int aKHalf  = (sub >> 1) << 4;
    const int bRowOff = ((sub >> 1) << 3) + lr8;
    const int bKHalf  = (sub & 1) << 4;

    const size_t bh = (size_t)(b * HH + h);
    const __nv_bfloat16* Qg  = Qp  + (bh * TT + q0) * DKP;
    const __nv_bfloat16* Kg  = Kp  + bh * TT * DKP;
    const __nv_bfloat16* Vhg = Vth + bh * HDD * TT;
    const __nv_bfloat16* Vlg = Vtl + bh * HDD * TT;

#pragma unroll
    for (int it = 0; it < 12; it++) {
        int idx = tid + it * 256;
        int pl = idx >> 10, rem = idx & 1023, row = rem >> 3, seg = rem & 7;
        cp16(QS + pl * 16384 + swz(row * 128 + seg * 16),
             Qg + (size_t)row * DKP + pl * 64 + seg * 8);
    }
    asm volatile("cp.async.commit_group;" ::: "memory");

    auto load_kv = [&](int jt) {
        const uint32_t S = (jt & 1) ? ST1 : ST0;
        const int kv0 = jt << 6;
#pragma unroll
        for (int it = 0; it < 6; it++) {
            int idx = tid + it * 256;
            int pl = idx >> 9, rem = idx & 511, row = rem >> 3, seg = rem & 7;
            cp16(S + pl * 8192 + swz(row * 128 + seg * 16),
                 Kg + (size_t)(kv0 + row) * DKP + pl * 64 + seg * 8);
        }
#pragma unroll
        for (int it = 0; it < 2; it++) {
            int idx = tid + it * 256;
            int row = idx >> 3, seg = idx & 7;
            cp16(S + 24576 + swz(row * 128 + seg * 16),
                 Vhg + (size_t)row * TT + kv0 + seg * 8);
        }
#pragma unroll
        for (int it = 0; it < 2; it++) {
            int idx = tid + it * 256;
            int row = idx >> 3, seg = idx & 7;
            cp16(S + 32768 + swz(row * 128 + seg * 16),
                 Vlg + (size_t)row * TT + kv0 + seg * 8);
        }
        asm volatile("cp.async.commit_group;" ::: "memory");
    };
    load_kv(0);
    load_kv(1);

    asm volatile("cp.async.wait_group 2;" ::: "memory");
    __syncthreads();

    uint32_t qa[12][4];
#pragma unroll
    for (int kk = 0; kk < 12; kk++) {
        int row = wid * 16 + aRowOff;
        ldsm4(qa[kk], QS + (kk >> 2) * 16384 + swz(row * 128 + (kk & 3) * 32 + aKHalf));
    }

    float oc[8][4];
#pragma unroll
    for (int j = 0; j < 8; j++)
#pragma unroll
        for (int e = 0; e < 4; e++) oc[j][e] = 0.f;
    float m0 = -1e30f, m1 = -1e30f, l0 = 0.f, l1 = 0.f;

    const int trow0 = q0 + wid * 16 + (lane >> 2);

    for (int jt = 0; jt < ntiles; jt++) {
        if (jt + 1 < ntiles) asm volatile("cp.async.wait_group 1;" ::: "memory");
        else                 asm volatile("cp.async.wait_group 0;" ::: "memory");
        __syncthreads();
        const uint32_t S = (jt & 1) ? ST1 : ST0;

        float sc[8][4];
#pragma unroll
        for (int j = 0; j < 8; j++)
#pragma unroll
            for (int e = 0; e < 4; e++) sc[j][e] = 0.f;
#pragma unroll
        for (int kk = 0; kk < 12; kk++) {
            uint32_t kf[4][4];
#pragma unroll
            for (int p = 0; p < 4; p++)
                ldsm4(kf[p], S + (kk >> 2) * 8192 +
                      swz((p * 16 + bRowOff) * 128 + (kk & 3) * 32 + bKHalf));
#pragma unroll
            for (int j = 0; j < 8; j++)
                mma16816(sc[j], qa[kk], &kf[j >> 1][(j & 1) * 2]);
        }

        if (jt >= 2 * qb) {
            int s0c = jt << 6;
#pragma unroll
            for (int j = 0; j < 8; j++) {
                int scol = s0c + 8 * j + ((lane & 3) << 1);
                if (scol     > trow0)     sc[j][0] = -1e30f;
                if (scol + 1 > trow0)     sc[j][1] = -1e30f;
                if (scol     > trow0 + 8) sc[j][2] = -1e30f;
                if (scol + 1 > trow0 + 8) sc[j][3] = -1e30f;
            }
        }

        float r0 = -1e30f, r1 = -1e30f;
#pragma unroll
        for (int j = 0; j < 8; j++) {
            r0 = fmaxf(r0, fmaxf(sc[j][0], sc[j][1]));
            r1 = fmaxf(r1, fmaxf(sc[j][2], sc[j][3]));
        }
        r0 = fmaxf(r0, __shfl_xor_sync(0xffffffffu, r0, 1));
        r0 = fmaxf(r0, __shfl_xor_sync(0xffffffffu, r0, 2));
        r1 = fmaxf(r1, __shfl_xor_sync(0xffffffffu, r1, 1));
        r1 = fmaxf(r1, __shfl_xor_sync(0xffffffffu, r1, 2));
        float mn0 = fmaxf(m0, r0), mn1 = fmaxf(m1, r1);
        float a0 = __expf(m0 - mn0), a1 = __expf(m1 - mn1);
        float s0 = 0.f, s1 = 0.f;
#pragma unroll
        for (int j = 0; j < 8; j++) {
            sc[j][0] = __expf(sc[j][0] - mn0); sc[j][1] = __expf(sc[j][1] - mn0);
            sc[j][2] = __expf(sc[j][2] - mn1); sc[j][3] = __expf(sc[j][3] - mn1);
            s0 += sc[j][0] + sc[j][1];         s1 += sc[j][2] + sc[j][3];
        }
        s0 += __shfl_xor_sync(0xffffffffu, s0, 1);
        s0 += __shfl_xor_sync(0xffffffffu, s0, 2);
        s1 += __shfl_xor_sync(0xffffffffu, s1, 1);
        s1 += __shfl_xor_sync(0xffffffffu, s1, 2);
        l0 = l0 * a0 + s0; l1 = l1 * a1 + s1; m0 = mn0; m1 = mn1;
#pragma unroll
        for (int j = 0; j < 8; j++) {
            oc[j][0] *= a0; oc[j][1] *= a0; oc[j][2] *= a1; oc[j][3] *= a1;
        }

        uint32_t ph[8][2], pl_[8][2];
#pragma unroll
        for (int j = 0; j < 8; j++) {
            split_pair(sc[j][0], sc[j][1], ph[j][0], pl_[j][0], 1.f);
            split_pair(sc[j][2], sc[j][3], ph[j][1], pl_[j][1], 1.f);
        }

#pragma unroll
        for (int kc = 0; kc < 4; kc++) {
            uint32_t pah[4] = {ph[2*kc][0],  ph[2*kc][1],  ph[2*kc+1][0],  ph[2*kc+1][1]};
            uint32_t pal[4] = {pl_[2*kc][0], pl_[2*kc][1], pl_[2*kc+1][0], pl_[2*kc+1][1]};
            uint32_t vhf[4][4], vlf[4][4];
#pragma unroll
            for (int p = 0; p < 4; p++) {
                ldsm4(vhf[p], S + 24576 + swz((p * 16 + bRowOff) * 128 + kc * 32 + bKHalf));
                ldsm4(vlf[p], S + 32768 + swz((p * 16 + bRowOff) * 128 + kc * 32 + bKHalf));
            }
#pragma unroll
            for (int j = 0; j < 8; j++) {
                mma16816(oc[j], pah, &vhf[j >> 1][(j & 1) * 2]);
                mma16816(oc[j], pah, &vlf[j >> 1][(j & 1) * 2]);
                mma16816(oc[j], pal, &vhf[j >> 1][(j & 1) * 2]);
            }
        }
        __syncthreads();
        if (jt + 2 < ntiles) load_kv(jt + 2);
    }

    // Epilogue: normalize + split to [hi | hi | lo] K3 layout directly
    float i0 = 1.f / l0, i1 = 1.f / l1;
    size_t rA = (size_t)(b * TT + trow0) * K3 + h * HDD;
    size_t rB = rA + (size_t)8 * K3;
#pragma unroll
    for (int j = 0; j < 8; j++) {
        int col = 8 * j + ((lane & 3) << 1);
        uint32_t hi2, lo2;
        split_pair(oc[j][0] * i0, oc[j][1] * i0, hi2, lo2, 1.f);
        *(uint32_t*)(Osplit + rA + col)        = hi2;
        *(uint32_t*)(Osplit + rA + col + 1024) = hi2;
        *(uint32_t*)(Osplit + rA + col + 2048) = lo2;
        split_pair(oc[j][2] * i1, oc[j][3] * i1, hi2, lo2, 1.f);
        *(uint32_t*)(Osplit + rB + col)        = hi2;
        *(uint32_t*)(Osplit + rB + col + 1024) = hi2;
        *(uint32_t*)(Osplit + rB + col + 2048) = lo2;
    }
}

// ---------------------------------------------------------------------------
extern "C" void kernel_launch(void* const* d_in, const int* in_sizes, int n_in,
                              void* d_out, int out_size) {
    const float* x  = (const float*)d_in[0];
    const float* Wq = (const float*)d_in[1];
    const float* Wk = (const float*)d_in[2];
    const float* Wv = (const float*)d_in[3];
    const float* Wo = (const float*)d_in[4];
    float* out = (float*)d_out;

    float *vb;
    __nv_bfloat16 *xs, *ats, *wqs, *wks, *wvs, *wos, *qp, *kp, *vth, *vtl;
    cudaGetSymbolAddress((void**)&vb, g_v);
    cudaGetSymbolAddress((void**)&xs, g_xs);
    cudaGetSymbolAddress((void**)&ats, g_atts);
    cudaGetSymbolAddress((void**)&wqs, g_wqs);
    cudaGetSymbolAddress((void**)&wks, g_wks);
    cudaGetSymbolAddress((void**)&wvs, g_wvs);
    cudaGetSymbolAddress((void**)&wos, g_wos);
    cudaGetSymbolAddress((void**)&qp, g_qp);
    cudaGetSymbolAddress((void**)&kp, g_kp);
    cudaGetSymbolAddress((void**)&vth, g_vth);
    cudaGetSymbolAddress((void**)&vtl, g_vtl);

    cudaFuncSetAttribute(gemm_mma, cudaFuncAttributeMaxDynamicSharedMemorySize, GEMM_DYN);
    cudaFuncSetAttribute(attn_mma, cudaFuncAttributeMaxDynamicSharedMemorySize, ATT_DYN);

    // operand prep
    split3<<<MM, 256>>>(x, xs);
    dim3 wgrid(DDIM, 4);
    wsplit4<<<wgrid, 256>>>(Wq, Wk, Wv, Wo, wqs, wks, wvs, wos);

    // projections (Q/K epilogues emit packed attention operands directly)
    dim3 ggrid(DDIM / 256, MM / 128);   // (4, 32)
    gemm_mma<<<ggrid, 256, GEMM_DYN>>>(xs, wqs, qp, 1);
    gemm_mma<<<ggrid, 256, GEMM_DYN>>>(xs, wks, kp, 2);
    gemm_mma<<<ggrid, 256, GEMM_DYN>>>(xs, wvs, vb, 0);

    dim3 vgrid(TT / 64, HH, BB);
    vtrans<<<vgrid, 256>>>(vb, vth, vtl);

    dim3 agrid(TT / 128, HH, BB);       // (16, 16, 2)
    attn_mma<<<agrid, 256, ATT_DYN>>>(qp, kp, vth, vtl, ats);

    gemm_mma<<<ggrid, 256, GEMM_DYN>>>(ats, wos, out, 0);
}

// round 6
// speedup vs baseline: 7.2573x; 1.0328x over previous
#include <cuda_runtime.h>
#include <cuda_bf16.h>
#include <cstdint>

// Problem constants
#define BB   2
#define TT   2048
#define DDIM 1024
#define HH   16
#define HDD  64
#define MM   (BB*TT)   // 4096 rows
#define K3   3072      // GEMM split-K: [hi | hi/lo | lo/hi]
#define DKP  192       // attention packed head dim (64*3)

// Scratch (__device__ globals; no allocations allowed)
__device__ float g_v[MM*DDIM];
__device__ __nv_bfloat16 g_xs[MM*K3];
__device__ __nv_bfloat16 g_atts[MM*K3];
__device__ __nv_bfloat16 g_wqs[DDIM*K3];
__device__ __nv_bfloat16 g_wks[DDIM*K3];
__device__ __nv_bfloat16 g_wvs[DDIM*K3];
__device__ __nv_bfloat16 g_wos[DDIM*K3];
__device__ __nv_bfloat16 g_qp[BB*HH*TT*DKP];
__device__ __nv_bfloat16 g_kp[BB*HH*TT*DKP];
__device__ __nv_bfloat16 g_vth[BB*HH*HDD*TT];
__device__ __nv_bfloat16 g_vtl[BB*HH*HDD*TT];

// ---------------------------------------------------------------------------
__device__ __forceinline__ uint32_t s2u(const void* p) {
    uint32_t a;
    asm("{ .reg .u64 t; cvta.to.shared.u64 t, %1; cvt.u32.u64 %0, t; }" : "=r"(a) : "l"(p));
    return a;
}
__device__ __forceinline__ uint32_t swz(uint32_t o) { return o ^ ((o >> 3) & 0x70); }
__device__ __forceinline__ void cp16(uint32_t dst, const void* src) {
    asm volatile("cp.async.cg.shared.global [%0], [%1], 16;" :: "r"(dst), "l"(src));
}
__device__ __forceinline__ void ldsm4(uint32_t* r, uint32_t addr) {
    asm volatile("ldmatrix.sync.aligned.m8n8.x4.shared.b16 {%0,%1,%2,%3}, [%4];"
                 : "=r"(r[0]), "=r"(r[1]), "=r"(r[2]), "=r"(r[3]) : "r"(addr));
}
__device__ __forceinline__ void mma16816(float* c, const uint32_t* a, const uint32_t* b) {
    asm volatile("mma.sync.aligned.m16n8k16.row.col.f32.bf16.bf16.f32 "
                 "{%0,%1,%2,%3}, {%4,%5,%6,%7}, {%8,%9}, {%0,%1,%2,%3};"
                 : "+f"(c[0]), "+f"(c[1]), "+f"(c[2]), "+f"(c[3])
                 : "r"(a[0]), "r"(a[1]), "r"(a[2]), "r"(a[3]), "r"(b[0]), "r"(b[1]));
}
// split v into bf16 hi + lo packed as bf16x2 words
__device__ __forceinline__ void split_pair(float v0, float v1, uint32_t& hi2, uint32_t& lo2,
                                           float scale) {
    __nv_bfloat16 h0 = __float2bfloat16(v0), h1 = __float2bfloat16(v1);
    __nv_bfloat16 l0 = __float2bfloat16(v0 - __bfloat162float(h0));
    __nv_bfloat16 l1 = __float2bfloat16(v1 - __bfloat162float(h1));
    if (scale != 1.f) {   // exact power-of-two rescale
        h0 = __float2bfloat16(__bfloat162float(h0) * scale);
        h1 = __float2bfloat16(__bfloat162float(h1) * scale);
        l0 = __float2bfloat16(__bfloat162float(l0) * scale);
        l1 = __float2bfloat16(__bfloat162float(l1) * scale);
    }
    __nv_bfloat162 hp{h0, h1}, lp{l0, l1};
    hi2 = *(uint32_t*)&hp; lo2 = *(uint32_t*)&lp;
}

// ---------------------------------------------------------------------------
// split3: fp32 [rows,1024] -> bf16 [rows,3072]  (activation: [hi | hi | lo])
// ---------------------------------------------------------------------------
__global__ __launch_bounds__(256) void split3(const float* __restrict__ in,
                                              __nv_bfloat16* __restrict__ out) {
    int idx = (blockIdx.x * 256 + threadIdx.x) * 4;
    int r = idx >> 10, c = idx & 1023;
    float4 v = *(const float4*)(in + idx);
    uint32_t h01, l01, h23, l23;
    split_pair(v.x, v.y, h01, l01, 1.f);
    split_pair(v.z, v.w, h23, l23, 1.f);
    size_t base = (size_t)r * K3 + c;
    *(uint32_t*)((__nv_bfloat16*)out + base)            = h01;
    *(uint32_t*)((__nv_bfloat16*)out + base + 2)        = h23;
    *(uint32_t*)((__nv_bfloat16*)out + base + 1024)     = h01;
    *(uint32_t*)((__nv_bfloat16*)out + base + 1024 + 2) = h23;
    *(uint32_t*)((__nv_bfloat16*)out + base + 2048)     = l01;
    *(uint32_t*)((__nv_bfloat16*)out + base + 2048 + 2) = l23;
}

// wsplit4: all four weights in one launch (weight layout: [hi | lo | hi])
__global__ __launch_bounds__(256) void wsplit4(const float* __restrict__ w0,
                                               const float* __restrict__ w1,
                                               const float* __restrict__ w2,
                                               const float* __restrict__ w3,
                                               __nv_bfloat16* __restrict__ o0,
                                               __nv_bfloat16* __restrict__ o1,
                                               __nv_bfloat16* __restrict__ o2,
                                               __nv_bfloat16* __restrict__ o3) {
    const float* in; __nv_bfloat16* out;
    switch (blockIdx.y) {
        case 0: in = w0; out = o0; break;
        case 1: in = w1; out = o1; break;
        case 2: in = w2; out = o2; break;
        default: in = w3; out = o3; break;
    }
    int idx = (blockIdx.x * 256 + threadIdx.x) * 4;
    int r = idx >> 10, c = idx & 1023;
    float4 v = *(const float4*)(in + idx);
    uint32_t h01, l01, h23, l23;
    split_pair(v.x, v.y, h01, l01, 1.f);
    split_pair(v.z, v.w, h23, l23, 1.f);
    size_t base = (size_t)r * K3 + c;
    *(uint32_t*)(out + base)            = h01;
    *(uint32_t*)(out + base + 2)        = h23;
    *(uint32_t*)(out + base + 1024)     = l01;
    *(uint32_t*)(out + base + 1024 + 2) = l23;
    *(uint32_t*)(out + base + 2048)     = h01;
    *(uint32_t*)(out + base + 2048 + 2) = h23;
}

// ---------------------------------------------------------------------------
// vtrans: fp32 V [B*T,1024] -> Vt hi/lo bf16 [B,H,64,T]
// ---------------------------------------------------------------------------
__global__ __launch_bounds__(256) void vtrans(const float* __restrict__ vsrc,
                                              __nv_bfloat16* __restrict__ vh,
                                              __nv_bfloat16* __restrict__ vl) {
    __shared__ float tile[64][65];
    int t0 = blockIdx.x << 6, h = blockIdx.y, b = blockIdx.z;
    int tid = threadIdx.x;
#pragma unroll
    for (int it = 0; it < 4; it++) {
        int idx = tid + it * 256;
        int r = idx >> 4, c4 = (idx & 15) << 2;
        float4 v = *(const float4*)&vsrc[(size_t)(b * TT + t0 + r) * DDIM + h * HDD + c4];
        tile[r][c4] = v.x; tile[r][c4 + 1] = v.y; tile[r][c4 + 2] = v.z; tile[r][c4 + 3] = v.w;
    }
    __syncthreads();
    size_t obase = (size_t)(b * HH + h) * HDD;
#pragma unroll
    for (int it = 0; it < 2; it++) {
        int idx = tid + it * 256;
        int d = idx >> 3, ts = (idx & 7) << 3;
        uint32_t hw[4], lw[4];
#pragma unroll
        for (int i = 0; i < 4; i++)
            split_pair(tile[ts + 2 * i][d], tile[ts + 2 * i + 1][d], hw[i], lw[i], 1.f);
        size_t o = (obase + d) * TT + t0 + ts;
        *(uint4*)(vh + o) = make_uint4(hw[0], hw[1], hw[2], hw[3]);
        *(uint4*)(vl + o) = make_uint4(lw[0], lw[1], lw[2], lw[3]);
    }
}

// ---------------------------------------------------------------------------
// mma.sync bf16 NT GEMM: C[4096,1024] = A[4096,3072] @ B[1024,3072]^T
// CTA tile 128x128, 4 warps (2x2), warp tile 64x64, BK=64, 3-stage cp.async.
// 2 CTAs/SM co-residency: grid (8,32)=256 CTAs ~= one wave at occ 2.
// mode 0: fp32 C out.  mode 1: Q-pack [hi/8|hi/8|lo/8].  mode 2: K-pack [hi|lo|hi].
// ---------------------------------------------------------------------------
#define BK      64
#define STAGES  3
#define NCHUNK  (K3 / BK)                 // 48
#define STG_A   (128 * 128)               // 16 KB
#define STG_B   (128 * 128)               // 16 KB
#define STG_SZ  (STG_A + STG_B)           // 32 KB
#define GEMM_DYN (STAGES * STG_SZ + 1024) // ~97 KB

__global__ __launch_bounds__(128, 2) void gemm_mma(const __nv_bfloat16* __restrict__ A,
                                                   const __nv_bfloat16* __restrict__ B,
                                                   void* __restrict__ Cout, int mode) {
    extern __shared__ char dyn[];
    const int tid  = threadIdx.x;
    const int wid  = tid >> 5, lane = tid & 31;
    const int wm   = wid >> 1;            // 0..1 (64-row slab)
    const int wn   = wid & 1;             // 0..1 (64-col slab)
    const int m0   = blockIdx.y << 7;
    const int n0   = blockIdx.x << 7;

    const uint32_t sbase = (s2u(dyn) + 1023) & ~1023u;
    const int lrow = tid >> 3;            // 0..15 base load row
    const int ls16 = tid & 7;

    float acc[4][8][4];
#pragma unroll
    for (int mi = 0; mi < 4; mi++)
#pragma unroll
        for (int ni = 0; ni < 8; ni++)
#pragma unroll
            for (int j = 0; j < 4; j++) acc[mi][ni][j] = 0.f;

    const int sub  = lane >> 3;
    const int lr8  = lane & 7;
    const int aRowOff = ((sub & 1) << 3) + lr8;
    const int aKHalf  = (sub >> 1) << 4;
    const int bRowOff = ((sub >> 1) << 3) + lr8;
    const int bKHalf  = (sub & 1) << 4;

#define LOAD_CHUNK(c)                                                            \
    {                                                                            \
        const int s_ = (c) % STAGES;                                             \
        const uint32_t sA_ = sbase + s_ * STG_SZ;                                \
        const uint32_t sB_ = sA_ + STG_A;                                        \
        _Pragma("unroll")                                                        \
        for (int it = 0; it < 8; it++) {                                         \
            int row = lrow + (it << 4);                                          \
            cp16(sA_ + swz(row * 128 + ls16 * 16),                               \
                 A + (size_t)(m0 + row) * K3 + (c) * BK + ls16 * 8);             \
        }                                                                        \
        _Pragma("unroll")                                                        \
        for (int it = 0; it < 8; it++) {                                         \
            int row = lrow + (it << 4);                                          \
            cp16(sB_ + swz(row * 128 + ls16 * 16),                               \
                 B + (size_t)(n0 + row) * K3 + (c) * BK + ls16 * 8);             \
        }                                                                        \
        asm volatile("cp.async.commit_group;" ::: "memory");                     \
    }

    LOAD_CHUNK(0);
    LOAD_CHUNK(1);

    for (int i = 0; i < NCHUNK; i++) {
        if (i < NCHUNK - 1) asm volatile("cp.async.wait_group 1;" ::: "memory");
        else                asm volatile("cp.async.wait_group 0;" ::: "memory");
        __syncthreads();

        if (i + 2 < NCHUNK) LOAD_CHUNK(i + 2);

        const int s = i % STAGES;
        const uint32_t sA = sbase + s * STG_SZ;
        const uint32_t sB = sA + STG_A;

#pragma unroll
        for (int kk = 0; kk < 4; kk++) {
            uint32_t af[4][4], bf[4][4];
#pragma unroll
            for (int mi = 0; mi < 4; mi++) {
                int row = wm * 64 + mi * 16 + aRowOff;
                ldsm4(af[mi], sA + swz(row * 128 + kk * 32 + aKHalf));
            }
#pragma unroll
            for (int p = 0; p < 4; p++) {
                int row = wn * 64 + p * 16 + bRowOff;
                ldsm4(bf[p], sB + swz(row * 128 + kk * 32 + bKHalf));
            }
#pragma unroll
            for (int mi = 0; mi < 4; mi++)
#pragma unroll
                for (int nj = 0; nj < 8; nj++)
                    mma16816(acc[mi][nj], af[mi], &bf[nj >> 1][(nj & 1) * 2]);
        }
    }

    const int lr = lane >> 2, lc = (lane & 3) << 1;
    if (mode == 0) {
        float* C = (float*)Cout;
#pragma unroll
        for (int mi = 0; mi < 4; mi++)
#pragma unroll
            for (int nj = 0; nj < 8; nj++) {
                int grow = m0 + wm * 64 + mi * 16 + lr;
                int gcol = n0 + wn * 64 + nj * 8 + lc;
                *(float2*)&C[(size_t)grow * DDIM + gcol] =
                    make_float2(acc[mi][nj][0], acc[mi][nj][1]);
                *(float2*)&C[(size_t)(grow + 8) * DDIM + gcol] =
                    make_float2(acc[mi][nj][2], acc[mi][nj][3]);
            }
    } else {
        __nv_bfloat16* P = (__nv_bfloat16*)Cout;
        const float sc = (mode == 1) ? 0.125f : 1.f;
        const int hh = (n0 >> 6) + wn;   // warp's 64-col slab == one head
#pragma unroll
        for (int mi = 0; mi < 4; mi++)
#pragma unroll
            for (int nj = 0; nj < 8; nj++) {
                int grow = m0 + wm * 64 + mi * 16 + lr;
                int d    = nj * 8 + lc;
#pragma unroll
                for (int half = 0; half < 2; half++) {
                    int row = grow + half * 8;
                    int b = row >> 11, t = row & 2047;
                    size_t base = ((size_t)(b * HH + hh) * TT + t) * DKP + d;
                    uint32_t hi2, lo2;
                    split_pair(acc[mi][nj][half * 2], acc[mi][nj][half * 2 + 1], hi2, lo2, sc);
                    if (mode == 1) {          // Q: [hi | hi | lo]
                        *(uint32_t*)(P + base)       = hi2;
                        *(uint32_t*)(P + base + 64)  = hi2;
                        *(uint32_t*)(P + base + 128) = lo2;
                    } else {                  // K: [hi | lo | hi]
                        *(uint32_t*)(P + base)       = hi2;
                        *(uint32_t*)(P + base + 64)  = lo2;
                        *(uint32_t*)(P + base + 128) = hi2;
                    }
                }
            }
    }
#undef LOAD_CHUNK
}

// ---------------------------------------------------------------------------
// Tensor-core flash attention. Writes split-K3 bf16 activation directly.
// Grid (T/128, H, B), 256 threads, 8 warps x 16 q-rows.
// ---------------------------------------------------------------------------
#define ATT_QSZ   49152                    // 3 planes x (128 x 128B)
#define ATT_STG   40960                    // K 3x8KB + Vh 8KB + Vl 8KB
#define ATT_DYN   (ATT_QSZ + 2*ATT_STG + 1024)

__global__ __launch_bounds__(256, 1) void attn_mma(const __nv_bfloat16* __restrict__ Qp,
                                                   const __nv_bfloat16* __restrict__ Kp,
                                                   const __nv_bfloat16* __restrict__ Vth,
                                                   const __nv_bfloat16* __restrict__ Vtl,
                                                   __nv_bfloat16* __restrict__ Osplit) {
    extern __shared__ char dyn[];
    const int tid = threadIdx.x, wid = tid >> 5, lane = tid & 31;
    const int qb = blockIdx.x, h = blockIdx.y, b = blockIdx.z;
    const int q0 = qb << 7;
    const int ntiles = 2 * qb + 2;

    const uint32_t sb = (s2u(dyn) + 1023) & ~1023u;
    const uint32_t QS = sb;
    const uint32_t ST0 = sb + ATT_QSZ;
    const uint32_t ST1 = ST0 + ATT_STG;

    const int sub = lane >> 3, lr8 = lane & 7;
    const int aRowOff = ((sub & 1) << 3) + lr8;
    const int aKHalf  = (sub >> 1) << 4;
    const int bRowOff = ((sub >> 1) << 3) + lr8;
    const int bKHalf  = (sub & 1) << 4;

    const size_t bh = (size_t)(b * HH + h);
    const __nv_bfloat16* Qg  = Qp  + (bh * TT + q0) * DKP;
    const __nv_bfloat16* Kg  = Kp  + bh * TT * DKP;
    const __nv_bfloat16* Vhg = Vth + bh * HDD * TT;
    const __nv_bfloat16* Vlg = Vtl + bh * HDD * TT;

#pragma unroll
    for (int it = 0; it < 12; it++) {
        int idx = tid + it * 256;
        int pl = idx >> 10, rem = idx & 1023, row = rem >> 3, seg = rem & 7;
        cp16(QS + pl * 16384 + swz(row * 128 + seg * 16),
             Qg + (size_t)row * DKP + pl * 64 + seg * 8);
    }
    asm volatile("cp.async.commit_group;" ::: "memory");

    auto load_kv = [&](int jt) {
        const uint32_t S = (jt & 1) ? ST1 : ST0;
        const int kv0 = jt << 6;
#pragma unroll
        for (int it = 0; it < 6; it++) {
            int idx = tid + it * 256;
            int pl = idx >> 9, rem = idx & 511, row = rem >> 3, seg = rem & 7;
            cp16(S + pl * 8192 + swz(row * 128 + seg * 16),
                 Kg + (size_t)(kv0 + row) * DKP + pl * 64 + seg * 8);
        }
#pragma unroll
        for (int it = 0; it < 2; it++) {
            int idx = tid + it * 256;
            int row = idx >> 3, seg = idx & 7;
            cp16(S + 24576 + swz(row * 128 + seg * 16),
                 Vhg + (size_t)row * TT + kv0 + seg * 8);
        }
#pragma unroll
        for (int it = 0; it < 2; it++) {
            int idx = tid + it * 256;
            int row = idx >> 3, seg = idx & 7;
            cp16(S + 32768 + swz(row * 128 + seg * 16),
                 Vlg + (size_t)row * TT + kv0 + seg * 8);
        }
        asm volatile("cp.async.commit_group;" ::: "memory");
    };
    load_kv(0);
    load_kv(1);

    asm volatile("cp.async.wait_group 2;" ::: "memory");
    __syncthreads();

    uint32_t qa[12][4];
#pragma unroll
    for (int kk = 0; kk < 12; kk++) {
        int row = wid * 16 + aRowOff;
        ldsm4(qa[kk], QS + (kk >> 2) * 16384 + swz(row * 128 + (kk & 3) * 32 + aKHalf));
    }

    float oc[8][4];
#pragma unroll
    for (int j = 0; j < 8; j++)
#pragma unroll
        for (int e = 0; e < 4; e++) oc[j][e] = 0.f;
    float m0 = -1e30f, m1 = -1e30f, l0 = 0.f, l1 = 0.f;

    const int trow0 = q0 + wid * 16 + (lane >> 2);

    for (int jt = 0; jt < ntiles; jt++) {
        if (jt + 1 < ntiles) asm volatile("cp.async.wait_group 1;" ::: "memory");
        else                 asm volatile("cp.async.wait_group 0;" ::: "memory");
        __syncthreads();
        const uint32_t S = (jt & 1) ? ST1 : ST0;

        float sc[8][4];
#pragma unroll
        for (int j = 0; j < 8; j++)
#pragma unroll
            for (int e = 0; e < 4; e++) sc[j][e] = 0.f;
#pragma unroll
        for (int kk = 0; kk < 12; kk++) {
            uint32_t kf[4][4];
#pragma unroll
            for (int p = 0; p < 4; p++)
                ldsm4(kf[p], S + (kk >> 2) * 8192 +
                      swz((p * 16 + bRowOff) * 128 + (kk & 3) * 32 + bKHalf));
#pragma unroll
            for (int j = 0; j < 8; j++)
                mma16816(sc[j], qa[kk], &kf[j >> 1][(j & 1) * 2]);
        }

        if (jt >= 2 * qb) {
            int s0c = jt << 6;
#pragma unroll
            for (int j = 0; j < 8; j++) {
                int scol = s0c + 8 * j + ((lane & 3) << 1);
                if (scol     > trow0)     sc[j][0] = -1e30f;
                if (scol + 1 > trow0)     sc[j][1] = -1e30f;
                if (scol     > trow0 + 8) sc[j][2] = -1e30f;
                if (scol + 1 > trow0 + 8) sc[j][3] = -1e30f;
            }
        }

        float r0 = -1e30f, r1 = -1e30f;
#pragma unroll
        for (int j = 0; j < 8; j++) {
            r0 = fmaxf(r0, fmaxf(sc[j][0], sc[j][1]));
            r1 = fmaxf(r1, fmaxf(sc[j][2], sc[j][3]));
        }
        r0 = fmaxf(r0, __shfl_xor_sync(0xffffffffu, r0, 1));
        r0 = fmaxf(r0, __shfl_xor_sync(0xffffffffu, r0, 2));
        r1 = fmaxf(r1, __shfl_xor_sync(0xffffffffu, r1, 1));
        r1 = fmaxf(r1, __shfl_xor_sync(0xffffffffu, r1, 2));
        float mn0 = fmaxf(m0, r0), mn1 = fmaxf(m1, r1);
        float a0 = __expf(m0 - mn0), a1 = __expf(m1 - mn1);
        float s0 = 0.f, s1 = 0.f;
#pragma unroll
        for (int j = 0; j < 8; j++) {
            sc[j][0] = __expf(sc[j][0] - mn0); sc[j][1] = __expf(sc[j][1] - mn0);
            sc[j][2] = __expf(sc[j][2] - mn1); sc[j][3] = __expf(sc[j][3] - mn1);
            s0 += sc[j][0] + sc[j][1];         s1 += sc[j][2] + sc[j][3];
        }
        s0 += __shfl_xor_sync(0xffffffffu, s0, 1);
        s0 += __shfl_xor_sync(0xffffffffu, s0, 2);
        s1 += __shfl_xor_sync(0xffffffffu, s1, 1);
        s1 += __shfl_xor_sync(0xffffffffu, s1, 2);
        l0 = l0 * a0 + s0; l1 = l1 * a1 + s1; m0 = mn0; m1 = mn1;
#pragma unroll
        for (int j = 0; j < 8; j++) {
            oc[j][0] *= a0; oc[j][1] *= a0; oc[j][2] *= a1; oc[j][3] *= a1;
        }

        uint32_t ph[8][2], pl_[8][2];
#pragma unroll
        for (int j = 0; j < 8; j++) {
            split_pair(sc[j][0], sc[j][1], ph[j][0], pl_[j][0], 1.f);
            split_pair(sc[j][2], sc[j][3], ph[j][1], pl_[j][1], 1.f);
        }

#pragma unroll
        for (int kc = 0; kc < 4; kc++) {
            uint32_t pah[4] = {ph[2*kc][0],  ph[2*kc][1],  ph[2*kc+1][0],  ph[2*kc+1][1]};
            uint32_t pal[4] = {pl_[2*kc][0], pl_[2*kc][1], pl_[2*kc+1][0], pl_[2*kc+1][1]};
            uint32_t vhf[4][4], vlf[4][4];
#pragma unroll
            for (int p = 0; p < 4; p++) {
                ldsm4(vhf[p], S + 24576 + swz((p * 16 + bRowOff) * 128 + kc * 32 + bKHalf));
                ldsm4(vlf[p], S + 32768 + swz((p * 16 + bRowOff) * 128 + kc * 32 + bKHalf));
            }
#pragma unroll
            for (int j = 0; j < 8; j++) {
                mma16816(oc[j], pah, &vhf[j >> 1][(j & 1) * 2]);
                mma16816(oc[j], pah, &vlf[j >> 1][(j & 1) * 2]);
                mma16816(oc[j], pal, &vhf[j >> 1][(j & 1) * 2]);
            }
        }
        __syncthreads();
        if (jt + 2 < ntiles) load_kv(jt + 2);
    }

    // Epilogue: normalize + split to [hi | hi | lo] K3 layout directly
    float i0 = 1.f / l0, i1 = 1.f / l1;
    size_t rA = (size_t)(b * TT + trow0) * K3 + h * HDD;
    size_t rB = rA + (size_t)8 * K3;
#pragma unroll
    for (int j = 0; j < 8; j++) {
        int col = 8 * j + ((lane & 3) << 1);
        uint32_t hi2, lo2;
        split_pair(oc[j][0] * i0, oc[j][1] * i0, hi2, lo2, 1.f);
        *(uint32_t*)(Osplit + rA + col)        = hi2;
        *(uint32_t*)(Osplit + rA + col + 1024) = hi2;
        *(uint32_t*)(Osplit + rA + col + 2048) = lo2;
        split_pair(oc[j][2] * i1, oc[j][3] * i1, hi2, lo2, 1.f);
        *(uint32_t*)(Osplit + rB + col)        = hi2;
        *(uint32_t*)(Osplit + rB + col + 1024) = hi2;
        *(uint32_t*)(Osplit + rB + col + 2048) = lo2;
    }
}

// ---------------------------------------------------------------------------
extern "C" void kernel_launch(void* const* d_in, const int* in_sizes, int n_in,
                              void* d_out, int out_size) {
    const float* x  = (const float*)d_in[0];
    const float* Wq = (const float*)d_in[1];
    const float* Wk = (const float*)d_in[2];
    const float* Wv = (const float*)d_in[3];
    const float* Wo = (const float*)d_in[4];
    float* out = (float*)d_out;

    float *vb;
    __nv_bfloat16 *xs, *ats, *wqs, *wks, *wvs, *wos, *qp, *kp, *vth, *vtl;
    cudaGetSymbolAddress((void**)&vb, g_v);
    cudaGetSymbolAddress((void**)&xs, g_xs);
    cudaGetSymbolAddress((void**)&ats, g_atts);
    cudaGetSymbolAddress((void**)&wqs, g_wqs);
    cudaGetSymbolAddress((void**)&wks, g_wks);
    cudaGetSymbolAddress((void**)&wvs, g_wvs);
    cudaGetSymbolAddress((void**)&wos, g_wos);
    cudaGetSymbolAddress((void**)&qp, g_qp);
    cudaGetSymbolAddress((void**)&kp, g_kp);
    cudaGetSymbolAddress((void**)&vth, g_vth);
    cudaGetSymbolAddress((void**)&vtl, g_vtl);

    cudaFuncSetAttribute(gemm_mma, cudaFuncAttributeMaxDynamicSharedMemorySize, GEMM_DYN);
    cudaFuncSetAttribute(attn_mma, cudaFuncAttributeMaxDynamicSharedMemorySize, ATT_DYN);

    // operand prep
    split3<<<MM, 256>>>(x, xs);
    dim3 wgrid(DDIM, 4);
    wsplit4<<<wgrid, 256>>>(Wq, Wk, Wv, Wo, wqs, wks, wvs, wos);

    // projections (Q/K epilogues emit packed attention operands directly)
    dim3 ggrid(DDIM / 128, MM / 128);   // (8, 32) = 256 CTAs, 2/SM
    gemm_mma<<<ggrid, 128, GEMM_DYN>>>(xs, wqs, qp, 1);
    gemm_mma<<<ggrid, 128, GEMM_DYN>>>(xs, wks, kp, 2);
    gemm_mma<<<ggrid, 128, GEMM_DYN>>>(xs, wvs, vb, 0);

    dim3 vgrid(TT / 64, HH, BB);
    vtrans<<<vgrid, 256>>>(vb, vth, vtl);

    dim3 agrid(TT / 128, HH, BB);       // (16, 16, 2)
    attn_mma<<<agrid, 256, ATT_DYN>>>(qp, kp, vth, vtl, ats);

    gemm_mma<<<ggrid, 128, GEMM_DYN>>>(ats, wos, out, 0);
}

// round 7
// speedup vs baseline: 9.4140x; 1.2972x over previous
#include <cuda_runtime.h>
#include <cuda_fp16.h>
#include <cstdint>

// Problem constants
#define BB   2
#define TT   2048
#define DDIM 1024
#define HH   16
#define HDD  64
#define MM   (BB*TT)   // 4096 rows
#define K2   2048      // QKV GEMM split-K: [xhi | xlo] (W plane reused)
#define K3   3072      // Wo GEMM split-K: [hi | hi | lo] x [Whi | Wlo | Whi]
#define DKQ  128       // attention packed Q dim (hi|lo)
#define DKK  64        // attention K dim (hi only)

// Scratch (__device__ globals; no allocations allowed)
__device__ float g_v[MM*DDIM];
__device__ __half g_xs[MM*K2];
__device__ __half g_atts[MM*K3];
__device__ __half g_wq16[DDIM*DDIM];
__device__ __half g_wk16[DDIM*DDIM];
__device__ __half g_wv16[DDIM*DDIM];
__device__ __half g_wos[DDIM*K3];
__device__ __half g_qp[BB*HH*TT*DKQ];
__device__ __half g_kp[BB*HH*TT*DKK];
__device__ __half g_vth[BB*HH*HDD*TT];
__device__ __half g_vtl[BB*HH*HDD*TT];

// ---------------------------------------------------------------------------
__device__ __forceinline__ uint32_t s2u(const void* p) {
    uint32_t a;
    asm("{ .reg .u64 t; cvta.to.shared.u64 t, %1; cvt.u32.u64 %0, t; }" : "=r"(a) : "l"(p));
    return a;
}
__device__ __forceinline__ uint32_t swz(uint32_t o) { return o ^ ((o >> 3) & 0x70); }
__device__ __forceinline__ void cp16(uint32_t dst, const void* src) {
    asm volatile("cp.async.cg.shared.global [%0], [%1], 16;" :: "r"(dst), "l"(src));
}
__device__ __forceinline__ void ldsm4(uint32_t* r, uint32_t addr) {
    asm volatile("ldmatrix.sync.aligned.m8n8.x4.shared.b16 {%0,%1,%2,%3}, [%4];"
                 : "=r"(r[0]), "=r"(r[1]), "=r"(r[2]), "=r"(r[3]) : "r"(addr));
}
__device__ __forceinline__ void mma16816(float* c, const uint32_t* a, const uint32_t* b) {
    asm volatile("mma.sync.aligned.m16n8k16.row.col.f32.f16.f16.f32 "
                 "{%0,%1,%2,%3}, {%4,%5,%6,%7}, {%8,%9}, {%0,%1,%2,%3};"
                 : "+f"(c[0]), "+f"(c[1]), "+f"(c[2]), "+f"(c[3])
                 : "r"(a[0]), "r"(a[1]), "r"(a[2]), "r"(a[3]), "r"(b[0]), "r"(b[1]));
}
// split (v0,v1) into fp16 hi + lo packed as half2 words; optional exact pow2 scale
__device__ __forceinline__ void split_pair(float v0, float v1, uint32_t& hi2, uint32_t& lo2,
                                           float scale) {
    __half h0 = __float2half_rn(v0), h1 = __float2half_rn(v1);
    __half l0 = __float2half_rn(v0 - __half2float(h0));
    __half l1 = __float2half_rn(v1 - __half2float(h1));
    if (scale != 1.f) {
        h0 = __float2half_rn(__half2float(h0) * scale);
        h1 = __float2half_rn(__half2float(h1) * scale);
        l0 = __float2half_rn(__half2float(l0) * scale);
        l1 = __float2half_rn(__half2float(l1) * scale);
    }
    __half2 hp{h0, h1}, lp{l0, l1};
    hi2 = *(uint32_t*)&hp; lo2 = *(uint32_t*)&lp;
}

// ---------------------------------------------------------------------------
// split2: fp32 x [rows,1024] -> fp16 [rows,2048]  [hi | lo]
// ---------------------------------------------------------------------------
__global__ __launch_bounds__(256) void split2(const float* __restrict__ in,
                                              __half* __restrict__ out) {
    int idx = (blockIdx.x * 256 + threadIdx.x) * 4;
    int r = idx >> 10, c = idx & 1023;
    float4 v = *(const float4*)(in + idx);
    uint32_t h01, l01, h23, l23;
    split_pair(v.x, v.y, h01, l01, 1.f);
    split_pair(v.z, v.w, h23, l23, 1.f);
    size_t base = (size_t)r * K2 + c;
    *(uint32_t*)(out + base)            = h01;
    *(uint32_t*)(out + base + 2)        = h23;
    *(uint32_t*)(out + base + 1024)     = l01;
    *(uint32_t*)(out + base + 1024 + 2) = l23;
}

// wconv3: Wq/Wk/Wv fp32 -> single fp16 plane each (one launch)
__global__ __launch_bounds__(256) void wconv3(const float* __restrict__ w0,
                                              const float* __restrict__ w1,
                                              const float* __restrict__ w2,
                                              __half* __restrict__ o0,
                                              __half* __restrict__ o1,
                                              __half* __restrict__ o2) {
    const float* in; __half* out;
    switch (blockIdx.y) {
        case 0: in = w0; out = o0; break;
        case 1: in = w1; out = o1; break;
        default: in = w2; out = o2; break;
    }
    int idx = (blockIdx.x * 256 + threadIdx.x) * 4;
    float4 v = *(const float4*)(in + idx);
    __half2 a{__float2half_rn(v.x), __float2half_rn(v.y)};
    __half2 b{__float2half_rn(v.z), __float2half_rn(v.w)};
    *(uint32_t*)(out + idx)     = *(uint32_t*)&a;
    *(uint32_t*)(out + idx + 2) = *(uint32_t*)&b;
}

// wsplit3: Wo fp32 -> fp16 [hi | lo | hi] K3 planes
__global__ __launch_bounds__(256) void wsplit3(const float* __restrict__ in,
                                               __half* __restrict__ out) {
    int idx = (blockIdx.x * 256 + threadIdx.x) * 4;
    int r = idx >> 10, c = idx & 1023;
    float4 v = *(const float4*)(in + idx);
    uint32_t h01, l01, h23, l23;
    split_pair(v.x, v.y, h01, l01, 1.f);
    split_pair(v.z, v.w, h23, l23, 1.f);
    size_t base = (size_t)r * K3 + c;
    *(uint32_t*)(out + base)            = h01;
    *(uint32_t*)(out + base + 2)        = h23;
    *(uint32_t*)(out + base + 1024)     = l01;
    *(uint32_t*)(out + base + 1024 + 2) = l23;
    *(uint32_t*)(out + base + 2048)     = h01;
    *(uint32_t*)(out + base + 2048 + 2) = h23;
}

// ---------------------------------------------------------------------------
// vtrans: fp32 V [B*T,1024] -> Vt hi/lo fp16 [B,H,64,T]
// ---------------------------------------------------------------------------
__global__ __launch_bounds__(256) void vtrans(const float* __restrict__ vsrc,
                                              __half* __restrict__ vh,
                                              __half* __restrict__ vl) {
    __shared__ float tile[64][65];
    int t0 = blockIdx.x << 6, h = blockIdx.y, b = blockIdx.z;
    int tid = threadIdx.x;
#pragma unroll
    for (int it = 0; it < 4; it++) {
        int idx = tid + it * 256;
        int r = idx >> 4, c4 = (idx & 15) << 2;
        float4 v = *(const float4*)&vsrc[(size_t)(b * TT + t0 + r) * DDIM + h * HDD + c4];
        tile[r][c4] = v.x; tile[r][c4 + 1] = v.y; tile[r][c4 + 2] = v.z; tile[r][c4 + 3] = v.w;
    }
    __syncthreads();
    size_t obase = (size_t)(b * HH + h) * HDD;
#pragma unroll
    for (int it = 0; it < 2; it++) {
        int idx = tid + it * 256;
        int d = idx >> 3, ts = (idx & 7) << 3;
        uint32_t hw[4], lw[4];
#pragma unroll
        for (int i = 0; i < 4; i++)
            split_pair(tile[ts + 2 * i][d], tile[ts + 2 * i + 1][d], hw[i], lw[i], 1.f);
        size_t o = (obase + d) * TT + t0 + ts;
        *(uint4*)(vh + o) = make_uint4(hw[0], hw[1], hw[2], hw[3]);
        *(uint4*)(vl + o) = make_uint4(lw[0], lw[1], lw[2], lw[3]);
    }
}

// ---------------------------------------------------------------------------
// fp16 HMMA NT GEMM, templated on K length and B plane period.
// C[4096,1024] = A[4096,KLEN] @ Bplanes^T.  B col for chunk c = (c % BMOD)*64.
// CTA 128x128, 4 warps (2x2), warp tile 64x64, BK=64, 3-stage cp.async, 2 CTA/SM.
// mode 0: fp32 C.  mode 1: Q pack [hi/8|lo/8].  mode 2: K pack [hi].
// ---------------------------------------------------------------------------
#define BK      64
#define STAGES  3
#define STG_A   (128 * 128)               // 16 KB
#define STG_B   (128 * 128)               // 16 KB
#define STG_SZ  (STG_A + STG_B)           // 32 KB
#define GEMM_DYN (STAGES * STG_SZ + 1024) // ~97 KB

template<int KLEN, int BMOD>
__global__ __launch_bounds__(128, 2) void gemm_hmma(const __half* __restrict__ A,
                                                    const __half* __restrict__ B,
                                                    void* __restrict__ Cout, int mode) {
    constexpr int NCHUNK = KLEN / BK;
    constexpr int BSTRIDE = BMOD * BK;
    extern __shared__ char dyn[];
    const int tid  = threadIdx.x;
    const int wid  = tid >> 5, lane = tid & 31;
    const int wm   = wid >> 1;
    const int wn   = wid & 1;
    const int m0   = blockIdx.y << 7;
    const int n0   = blockIdx.x << 7;

    const uint32_t sbase = (s2u(dyn) + 1023) & ~1023u;
    const int lrow = tid >> 3;
    const int ls16 = tid & 7;

    float acc[4][8][4];
#pragma unroll
    for (int mi = 0; mi < 4; mi++)
#pragma unroll
        for (int ni = 0; ni < 8; ni++)
#pragma unroll
            for (int j = 0; j < 4; j++) acc[mi][ni][j] = 0.f;

    const int sub  = lane >> 3;
    const int lr8  = lane & 7;
    const int aRowOff = ((sub & 1) << 3) + lr8;
    const int aKHalf  = (sub >> 1) << 4;
    const int bRowOff = ((sub >> 1) << 3) + lr8;
    const int bKHalf  = (sub & 1) << 4;

    auto load_chunk = [&](int c) {
        const int s_ = c % STAGES;
        const uint32_t sA_ = sbase + s_ * STG_SZ;
        const uint32_t sB_ = sA_ + STG_A;
        const int bc = (c % BMOD) * BK;
#pragma unroll
        for (int it = 0; it < 8; it++) {
            int row = lrow + (it << 4);
            cp16(sA_ + swz(row * 128 + ls16 * 16),
                 A + (size_t)(m0 + row) * KLEN + c * BK + ls16 * 8);
        }
#pragma unroll
        for (int it = 0; it < 8; it++) {
            int row = lrow + (it << 4);
            cp16(sB_ + swz(row * 128 + ls16 * 16),
                 B + (size_t)(n0 + row) * BSTRIDE + bc + ls16 * 8);
        }
        asm volatile("cp.async.commit_group;" ::: "memory");
    };

    load_chunk(0);
    load_chunk(1);

    for (int i = 0; i < NCHUNK; i++) {
        if (i < NCHUNK - 1) asm volatile("cp.async.wait_group 1;" ::: "memory");
        else                asm volatile("cp.async.wait_group 0;" ::: "memory");
        __syncthreads();

        if (i + 2 < NCHUNK) load_chunk(i + 2);

        const int s = i % STAGES;
        const uint32_t sA = sbase + s * STG_SZ;
        const uint32_t sB = sA + STG_A;

#pragma unroll
        for (int kk = 0; kk < 4; kk++) {
            uint32_t af[4][4], bf[4][4];
#pragma unroll
            for (int mi = 0; mi < 4; mi++) {
                int row = wm * 64 + mi * 16 + aRowOff;
                ldsm4(af[mi], sA + swz(row * 128 + kk * 32 + aKHalf));
            }
#pragma unroll
            for (int p = 0; p < 4; p++) {
                int row = wn * 64 + p * 16 + bRowOff;
                ldsm4(bf[p], sB + swz(row * 128 + kk * 32 + bKHalf));
            }
#pragma unroll
            for (int mi = 0; mi < 4; mi++)
#pragma unroll
                for (int nj = 0; nj < 8; nj++)
                    mma16816(acc[mi][nj], af[mi], &bf[nj >> 1][(nj & 1) * 2]);
        }
    }

    const int lr = lane >> 2, lc = (lane & 3) << 1;
    if (mode == 0) {
        float* C = (float*)Cout;
#pragma unroll
        for (int mi = 0; mi < 4; mi++)
#pragma unroll
            for (int nj = 0; nj < 8; nj++) {
                int grow = m0 + wm * 64 + mi * 16 + lr;
                int gcol = n0 + wn * 64 + nj * 8 + lc;
                *(float2*)&C[(size_t)grow * DDIM + gcol] =
                    make_float2(acc[mi][nj][0], acc[mi][nj][1]);
                *(float2*)&C[(size_t)(grow + 8) * DDIM + gcol] =
                    make_float2(acc[mi][nj][2], acc[mi][nj][3]);
            }
    } else {
        __half* P = (__half*)Cout;
        const float sc = (mode == 1) ? 0.125f : 1.f;
        const int hh = (n0 >> 6) + wn;   // warp's 64-col slab == one head
#pragma unroll
        for (int mi = 0; mi < 4; mi++)
#pragma unroll
            for (int nj = 0; nj < 8; nj++) {
                int grow = m0 + wm * 64 + mi * 16 + lr;
                int d    = nj * 8 + lc;
#pragma unroll
                for (int half_ = 0; half_ < 2; half_++) {
                    int row = grow + half_ * 8;
                    int b = row >> 11, t = row & 2047;
                    uint32_t hi2, lo2;
                    split_pair(acc[mi][nj][half_ * 2], acc[mi][nj][half_ * 2 + 1], hi2, lo2, sc);
                    if (mode == 1) {          // Q: [hi/8 | lo/8], width 128
                        size_t base = ((size_t)(b * HH + hh) * TT + t) * DKQ + d;
                        *(uint32_t*)(P + base)      = hi2;
                        *(uint32_t*)(P + base + 64) = lo2;
                    } else {                  // K: [hi], width 64
                        size_t base = ((size_t)(b * HH + hh) * TT + t) * DKK + d;
                        *(uint32_t*)(P + base)      = hi2;
                    }
                }
            }
    }
}

// ---------------------------------------------------------------------------
// fp16 tensor-core flash attention. Q 2-plane (exact), K 1-plane, PV 3-term.
// Writes [hi | hi | lo] fp16 K3 activation for the Wo GEMM.
// Grid (T/128, H, B), 256 threads, 8 warps x 16 q-rows.
// ---------------------------------------------------------------------------
#define ATT_QSZ   32768                    // 2 planes x (128 x 128B)
#define ATT_STG   24576                    // K 8KB + Vh 8KB + Vl 8KB
#define ATT_DYN   (ATT_QSZ + 2*ATT_STG + 1024)

__global__ __launch_bounds__(256, 1) void attn_mma(const __half* __restrict__ Qp,
                                                   const __half* __restrict__ Kp,
                                                   const __half* __restrict__ Vth,
                                                   const __half* __restrict__ Vtl,
                                                   __half* __restrict__ Osplit) {
    extern __shared__ char dyn[];
    const int tid = threadIdx.x, wid = tid >> 5, lane = tid & 31;
    const int qb = blockIdx.x, h = blockIdx.y, b = blockIdx.z;
    const int q0 = qb << 7;
    const int ntiles = 2 * qb + 2;

    const uint32_t sb = (s2u(dyn) + 1023) & ~1023u;
    const uint32_t QS = sb;
    const uint32_t ST0 = sb + ATT_QSZ;
    const uint32_t ST1 = ST0 + ATT_STG;

    const int sub = lane >> 3, lr8 = lane & 7;
    const int aRowOff = ((sub & 1) << 3) + lr8;
    const int aKHalf  = (sub >> 1) << 4;
    const int bRowOff = ((sub >> 1) << 3) + lr8;
    const int bKHalf  = (sub & 1) << 4;

    const size_t bh = (size_t)(b * HH + h);
    const __half* Qg  = Qp  + (bh * TT + q0) * DKQ;
    const __half* Kg  = Kp  + bh * TT * DKK;
    const __half* Vhg = Vth + bh * HDD * TT;
    const __half* Vlg = Vtl + bh * HDD * TT;

    // Q tile: 128 rows x 128 halfs = 2048 16B units, two 16KB plane regions
#pragma unroll
    for (int it = 0; it < 8; it++) {
        int idx = tid + it * 256;
        int row = idx >> 4, s16 = idx & 15;
        int pl = s16 >> 3, seg = s16 & 7;
        cp16(QS + pl * 16384 + swz(row * 128 + seg * 16),
             Qg + (size_t)row * DKQ + pl * 64 + seg * 8);
    }
    asm volatile("cp.async.commit_group;" ::: "memory");

    auto load_kv = [&](int jt) {
        const uint32_t S = (jt & 1) ? ST1 : ST0;
        const int kv0 = jt << 6;
#pragma unroll
        for (int it = 0; it < 2; it++) {       // K: 512 units
            int idx = tid + it * 256;
            int row = idx >> 3, seg = idx & 7;
            cp16(S + swz(row * 128 + seg * 16),
                 Kg + (size_t)(kv0 + row) * DKK + seg * 8);
        }
#pragma unroll
        for (int it = 0; it < 2; it++) {       // Vh
            int idx = tid + it * 256;
            int row = idx >> 3, seg = idx & 7;
            cp16(S + 8192 + swz(row * 128 + seg * 16),
                 Vhg + (size_t)row * TT + kv0 + seg * 8);
        }
#pragma unroll
        for (int it = 0; it < 2; it++) {       // Vl
            int idx = tid + it * 256;
            int row = idx >> 3, seg = idx & 7;
            cp16(S + 16384 + swz(row * 128 + seg * 16),
                 Vlg + (size_t)row * TT + kv0 + seg * 8);
        }
        asm volatile("cp.async.commit_group;" ::: "memory");
    };
    load_kv(0);
    load_kv(1);

    asm volatile("cp.async.wait_group 2;" ::: "memory");
    __syncthreads();

    uint32_t qa[8][4];
#pragma unroll
    for (int kk = 0; kk < 8; kk++) {
        int row = wid * 16 + aRowOff;
        ldsm4(qa[kk], QS + (kk >> 2) * 16384 + swz(row * 128 + (kk & 3) * 32 + aKHalf));
    }

    float oc[8][4];
#pragma unroll
    for (int j = 0; j < 8; j++)
#pragma unroll
        for (int e = 0; e < 4; e++) oc[j][e] = 0.f;
    float m0 = -1e30f, m1 = -1e30f, l0 = 0.f, l1 = 0.f;

    const int trow0 = q0 + wid * 16 + (lane >> 2);

    for (int jt = 0; jt < ntiles; jt++) {
        if (jt + 1 < ntiles) asm volatile("cp.async.wait_group 1;" ::: "memory");
        else                 asm volatile("cp.async.wait_group 0;" ::: "memory");
        __syncthreads();
        const uint32_t S = (jt & 1) ? ST1 : ST0;

        // scores: (Qhi + Qlo) @ Khi^T over 8 kk (K frag repeats per plane)
        float sc[8][4];
#pragma unroll
        for (int j = 0; j < 8; j++)
#pragma unroll
            for (int e = 0; e < 4; e++) sc[j][e] = 0.f;
#pragma unroll
        for (int kk = 0; kk < 8; kk++) {
            uint32_t kf[4][4];
#pragma unroll
            for (int p = 0; p < 4; p++)
                ldsm4(kf[p], S + swz((p * 16 + bRowOff) * 128 + (kk & 3) * 32 + bKHalf));
#pragma unroll
            for (int j = 0; j < 8; j++)
                mma16816(sc[j], qa[kk], &kf[j >> 1][(j & 1) * 2]);
        }

        if (jt >= 2 * qb) {
            int s0c = jt << 6;
#pragma unroll
            for (int j = 0; j < 8; j++) {
                int scol = s0c + 8 * j + ((lane & 3) << 1);
                if (scol     > trow0)     sc[j][0] = -1e30f;
                if (scol + 1 > trow0)     sc[j][1] = -1e30f;
                if (scol     > trow0 + 8) sc[j][2] = -1e30f;
                if (scol + 1 > trow0 + 8) sc[j][3] = -1e30f;
            }
        }

        float r0 = -1e30f, r1 = -1e30f;
#pragma unroll
        for (int j = 0; j < 8; j++) {
            r0 = fmaxf(r0, fmaxf(sc[j][0], sc[j][1]));
            r1 = fmaxf(r1, fmaxf(sc[j][2], sc[j][3]));
        }
        r0 = fmaxf(r0, __shfl_xor_sync(0xffffffffu, r0, 1));
        r0 = fmaxf(r0, __shfl_xor_sync(0xffffffffu, r0, 2));
        r1 = fmaxf(r1, __shfl_xor_sync(0xffffffffu, r1, 1));
        r1 = fmaxf(r1, __shfl_xor_sync(0xffffffffu, r1, 2));
        float mn0 = fmaxf(m0, r0), mn1 = fmaxf(m1, r1);
        float a0 = __expf(m0 - mn0), a1 = __expf(m1 - mn1);
        float s0 = 0.f, s1 = 0.f;
#pragma unroll
        for (int j = 0; j < 8; j++) {
            sc[j][0] = __expf(sc[j][0] - mn0); sc[j][1] = __expf(sc[j][1] - mn0);
            sc[j][2] = __expf(sc[j][2] - mn1); sc[j][3] = __expf(sc[j][3] - mn1);
            s0 += sc[j][0] + sc[j][1];         s1 += sc[j][2] + sc[j][3];
        }
        s0 += __shfl_xor_sync(0xffffffffu, s0, 1);
        s0 += __shfl_xor_sync(0xffffffffu, s0, 2);
        s1 += __shfl_xor_sync(0xffffffffu, s1, 1);
        s1 += __shfl_xor_sync(0xffffffffu, s1, 2);
        l0 = l0 * a0 + s0; l1 = l1 * a1 + s1; m0 = mn0; m1 = mn1;
#pragma unroll
        for (int j = 0; j < 8; j++) {
            oc[j][0] *= a0; oc[j][1] *= a0; oc[j][2] *= a1; oc[j][3] *= a1;
        }

        uint32_t ph[8][2], pl_[8][2];
#pragma unroll
        for (int j = 0; j < 8; j++) {
            split_pair(sc[j][0], sc[j][1], ph[j][0], pl_[j][0], 1.f);
            split_pair(sc[j][2], sc[j][3], ph[j][1], pl_[j][1], 1.f);
        }

        // PV: O += Phi@Vhi + Phi@Vlo + Plo@Vhi
#pragma unroll
        for (int kc = 0; kc < 4; kc++) {
            uint32_t pah[4] = {ph[2*kc][0],  ph[2*kc][1],  ph[2*kc+1][0],  ph[2*kc+1][1]};
            uint32_t pal[4] = {pl_[2*kc][0], pl_[2*kc][1], pl_[2*kc+1][0], pl_[2*kc+1][1]};
            uint32_t vhf[4][4], vlf[4][4];
#pragma unroll
            for (int p = 0; p < 4; p++) {
                ldsm4(vhf[p], S + 8192  + swz((p * 16 + bRowOff) * 128 + kc * 32 + bKHalf));
                ldsm4(vlf[p], S + 16384 + swz((p * 16 + bRowOff) * 128 + kc * 32 + bKHalf));
            }
#pragma unroll
            for (int j = 0; j < 8; j++) {
                mma16816(oc[j], pah, &vhf[j >> 1][(j & 1) * 2]);
                mma16816(oc[j], pah, &vlf[j >> 1][(j & 1) * 2]);
                mma16816(oc[j], pal, &vhf[j >> 1][(j & 1) * 2]);
            }
        }
        __syncthreads();
        if (jt + 2 < ntiles) load_kv(jt + 2);
    }

    // Epilogue: normalize + split to [hi | hi | lo] K3 fp16 layout
    float i0 = 1.f / l0, i1 = 1.f / l1;
    size_t rA = (size_t)(b * TT + trow0) * K3 + h * HDD;
    size_t rB = rA + (size_t)8 * K3;
#pragma unroll
    for (int j = 0; j < 8; j++) {
        int col = 8 * j + ((lane & 3) << 1);
        uint32_t hi2, lo2;
        split_pair(oc[j][0] * i0, oc[j][1] * i0, hi2, lo2, 1.f);
        *(uint32_t*)(Osplit + rA + col)        = hi2;
        *(uint32_t*)(Osplit + rA + col + 1024) = hi2;
        *(uint32_t*)(Osplit + rA + col + 2048) = lo2;
        split_pair(oc[j][2] * i1, oc[j][3] * i1, hi2, lo2, 1.f);
        *(uint32_t*)(Osplit + rB + col)        = hi2;
        *(uint32_t*)(Osplit + rB + col + 1024) = hi2;
        *(uint32_t*)(Osplit + rB + col + 2048) = lo2;
    }
}

// ---------------------------------------------------------------------------
extern "C" void kernel_launch(void* const* d_in, const int* in_sizes, int n_in,
                              void* d_out, int out_size) {
    const float* x  = (const float*)d_in[0];
    const float* Wq = (const float*)d_in[1];
    const float* Wk = (const float*)d_in[2];
    const float* Wv = (const float*)d_in[3];
    const float* Wo = (const float*)d_in[4];
    float* out = (float*)d_out;

    float *vb;
    __half *xs, *ats, *wq16, *wk16, *wv16, *wos, *qp, *kp, *vth, *vtl;
    cudaGetSymbolAddress((void**)&vb, g_v);
    cudaGetSymbolAddress((void**)&xs, g_xs);
    cudaGetSymbolAddress((void**)&ats, g_atts);
    cudaGetSymbolAddress((void**)&wq16, g_wq16);
    cudaGetSymbolAddress((void**)&wk16, g_wk16);
    cudaGetSymbolAddress((void**)&wv16, g_wv16);
    cudaGetSymbolAddress((void**)&wos, g_wos);
    cudaGetSymbolAddress((void**)&qp, g_qp);
    cudaGetSymbolAddress((void**)&kp, g_kp);
    cudaGetSymbolAddress((void**)&vth, g_vth);
    cudaGetSymbolAddress((void**)&vtl, g_vtl);

    cudaFuncSetAttribute(gemm_hmma<K2,16>, cudaFuncAttributeMaxDynamicSharedMemorySize, GEMM_DYN);
    cudaFuncSetAttribute(gemm_hmma<K3,48>, cudaFuncAttributeMaxDynamicSharedMemorySize, GEMM_DYN);
    cudaFuncSetAttribute(attn_mma, cudaFuncAttributeMaxDynamicSharedMemorySize, ATT_DYN);

    // operand prep
    split2<<<MM, 256>>>(x, xs);
    dim3 wgrid(DDIM, 3);
    wconv3<<<wgrid, 256>>>(Wq, Wk, Wv, wq16, wk16, wv16);
    wsplit3<<<DDIM, 256>>>(Wo, wos);

    // Q/K/V projections: 2-term fp16, W plane reused (BMOD=16)
    dim3 ggrid(DDIM / 128, MM / 128);   // (8, 32)
    gemm_hmma<K2,16><<<ggrid, 128, GEMM_DYN>>>(xs, wq16, qp, 1);
    gemm_hmma<K2,16><<<ggrid, 128, GEMM_DYN>>>(xs, wk16, kp, 2);
    gemm_hmma<K2,16><<<ggrid, 128, GEMM_DYN>>>(xs, wv16, vb, 0);

    dim3 vgrid(TT / 64, HH, BB);
    vtrans<<<vgrid, 256>>>(vb, vth, vtl);

    dim3 agrid(TT / 128, HH, BB);       // (16, 16, 2)
    attn_mma<<<agrid, 256, ATT_DYN>>>(qp, kp, vth, vtl, ats);

    // Wo: 3-term fp16 (error 2^-22, protects final output)
    gemm_hmma<K3,48><<<ggrid, 128, GEMM_DYN>>>(ats, wos, out, 0);
}

// round 8
// speedup vs baseline: 11.2852x; 1.1988x over previous
#include <cuda_runtime.h>
#include <cuda_fp16.h>
#include <cstdint>

// Problem constants
#define BB   2
#define TT   2048
#define DDIM 1024
#define HH   16
#define HDD  64
#define MM   (BB*TT)   // 4096 rows
#define K2   2048      // split-K: [hi | lo] activations, W plane reused
#define DKQ  128       // attention packed Q dim (hi|lo)
#define DKK  64        // attention K dim (hi only)

// Scratch (__device__ globals; no allocations allowed)
__device__ float g_v[MM*DDIM];
__device__ __half g_xs[MM*K2];
__device__ __half g_atts[MM*K2];
__device__ __half g_w16[3*DDIM*DDIM];    // [Wq | Wk | Wv] fp16 planes
__device__ __half g_wo16[DDIM*DDIM];
__device__ __half g_qp[BB*HH*TT*DKQ];
__device__ __half g_kp[BB*HH*TT*DKK];
__device__ __half g_vth[BB*HH*HDD*TT];
__device__ __half g_vtl[BB*HH*HDD*TT];

// ---------------------------------------------------------------------------
__device__ __forceinline__ uint32_t s2u(const void* p) {
    uint32_t a;
    asm("{ .reg .u64 t; cvta.to.shared.u64 t, %1; cvt.u32.u64 %0, t; }" : "=r"(a) : "l"(p));
    return a;
}
__device__ __forceinline__ uint32_t swz(uint32_t o) { return o ^ ((o >> 3) & 0x70); }
__device__ __forceinline__ void cp16(uint32_t dst, const void* src) {
    asm volatile("cp.async.cg.shared.global [%0], [%1], 16;" :: "r"(dst), "l"(src));
}
__device__ __forceinline__ void ldsm4(uint32_t* r, uint32_t addr) {
    asm volatile("ldmatrix.sync.aligned.m8n8.x4.shared.b16 {%0,%1,%2,%3}, [%4];"
                 : "=r"(r[0]), "=r"(r[1]), "=r"(r[2]), "=r"(r[3]) : "r"(addr));
}
__device__ __forceinline__ void mma16816(float* c, const uint32_t* a, const uint32_t* b) {
    asm volatile("mma.sync.aligned.m16n8k16.row.col.f32.f16.f16.f32 "
                 "{%0,%1,%2,%3}, {%4,%5,%6,%7}, {%8,%9}, {%0,%1,%2,%3};"
                 : "+f"(c[0]), "+f"(c[1]), "+f"(c[2]), "+f"(c[3])
                 : "r"(a[0]), "r"(a[1]), "r"(a[2]), "r"(a[3]), "r"(b[0]), "r"(b[1]));
}
// split (v0,v1) into fp16 hi + lo packed as half2 words; optional exact pow2 scale
__device__ __forceinline__ void split_pair(float v0, float v1, uint32_t& hi2, uint32_t& lo2,
                                           float scale) {
    __half h0 = __float2half_rn(v0), h1 = __float2half_rn(v1);
    __half l0 = __float2half_rn(v0 - __half2float(h0));
    __half l1 = __float2half_rn(v1 - __half2float(h1));
    if (scale != 1.f) {
        h0 = __float2half_rn(__half2float(h0) * scale);
        h1 = __float2half_rn(__half2float(h1) * scale);
        l0 = __float2half_rn(__half2float(l0) * scale);
        l1 = __float2half_rn(__half2float(l1) * scale);
    }
    __half2 hp{h0, h1}, lp{l0, l1};
    hi2 = *(uint32_t*)&hp; lo2 = *(uint32_t*)&lp;
}

// ---------------------------------------------------------------------------
// split2: fp32 x [rows,1024] -> fp16 [rows,2048]  [hi | lo]
// ---------------------------------------------------------------------------
__global__ __launch_bounds__(256) void split2(const float* __restrict__ in,
                                              __half* __restrict__ out) {
    int idx = (blockIdx.x * 256 + threadIdx.x) * 4;
    int r = idx >> 10, c = idx & 1023;
    float4 v = *(const float4*)(in + idx);
    uint32_t h01, l01, h23, l23;
    split_pair(v.x, v.y, h01, l01, 1.f);
    split_pair(v.z, v.w, h23, l23, 1.f);
    size_t base = (size_t)r * K2 + c;
    *(uint32_t*)(out + base)            = h01;
    *(uint32_t*)(out + base + 2)        = h23;
    *(uint32_t*)(out + base + 1024)     = l01;
    *(uint32_t*)(out + base + 1024 + 2) = l23;
}

// wconv4: Wq/Wk/Wv -> merged fp16 buffer; Wo -> own plane. One launch.
__global__ __launch_bounds__(256) void wconv4(const float* __restrict__ w0,
                                              const float* __restrict__ w1,
                                              const float* __restrict__ w2,
                                              const float* __restrict__ w3,
                                              __half* __restrict__ wqkv,
                                              __half* __restrict__ wo) {
    const float* in; __half* out;
    switch (blockIdx.y) {
        case 0: in = w0; out = wqkv; break;
        case 1: in = w1; out = wqkv + DDIM*DDIM; break;
        case 2: in = w2; out = wqkv + 2*DDIM*DDIM; break;
        default: in = w3; out = wo; break;
    }
    int idx = (blockIdx.x * 256 + threadIdx.x) * 4;
    float4 v = *(const float4*)(in + idx);
    __half2 a{__float2half_rn(v.x), __float2half_rn(v.y)};
    __half2 b{__float2half_rn(v.z), __float2half_rn(v.w)};
    *(uint32_t*)(out + idx)     = *(uint32_t*)&a;
    *(uint32_t*)(out + idx + 2) = *(uint32_t*)&b;
}

// ---------------------------------------------------------------------------
// vtrans: fp32 V [B*T,1024] -> Vt hi/lo fp16 [B,H,64,T]
// ---------------------------------------------------------------------------
__global__ __launch_bounds__(256) void vtrans(const float* __restrict__ vsrc,
                                              __half* __restrict__ vh,
                                              __half* __restrict__ vl) {
    __shared__ float tile[64][65];
    int t0 = blockIdx.x << 6, h = blockIdx.y, b = blockIdx.z;
    int tid = threadIdx.x;
#pragma unroll
    for (int it = 0; it < 4; it++) {
        int idx = tid + it * 256;
        int r = idx >> 4, c4 = (idx & 15) << 2;
        float4 v = *(const float4*)&vsrc[(size_t)(b * TT + t0 + r) * DDIM + h * HDD + c4];
        tile[r][c4] = v.x; tile[r][c4 + 1] = v.y; tile[r][c4 + 2] = v.z; tile[r][c4 + 3] = v.w;
    }
    __syncthreads();
    size_t obase = (size_t)(b * HH + h) * HDD;
#pragma unroll
    for (int it = 0; it < 2; it++) {
        int idx = tid + it * 256;
        int d = idx >> 3, ts = (idx & 7) << 3;
        uint32_t hw[4], lw[4];
#pragma unroll
        for (int i = 0; i < 4; i++)
            split_pair(tile[ts + 2 * i][d], tile[ts + 2 * i + 1][d], hw[i], lw[i], 1.f);
        size_t o = (obase + d) * TT + t0 + ts;
        *(uint4*)(vh + o) = make_uint4(hw[0], hw[1], hw[2], hw[3]);
        *(uint4*)(vl + o) = make_uint4(lw[0], lw[1], lw[2], lw[3]);
    }
}

// ---------------------------------------------------------------------------
// fp16 HMMA NT GEMM, 2-term split-K (A=[hi|lo], B plane reused c%16).
// CTA 128x128, 4 warps (2x2), warp tile 64x64, BK=64, 3-stage, 2 CTA/SM.
// NWIDTH = B logical col count. mode 0: fp32 C (width DDIM).
// mode 3: merged QKV — section n0>>10: 0 -> Q pack, 1 -> K pack, 2 -> V fp32.
// ---------------------------------------------------------------------------
#define BK      64
#define STAGES  3
#define NCHUNK  (K2 / BK)                 // 32
#define STG_A   (128 * 128)               // 16 KB
#define STG_B   (128 * 128)               // 16 KB
#define STG_SZ  (STG_A + STG_B)           // 32 KB
#define GEMM_DYN (STAGES * STG_SZ + 1024) // ~97 KB

__global__ __launch_bounds__(128, 2) void gemm_hmma(const __half* __restrict__ A,
                                                    const __half* __restrict__ B,
                                                    void* __restrict__ Cout, int mode) {
    extern __shared__ char dyn[];
    const int tid  = threadIdx.x;
    const int wid  = tid >> 5, lane = tid & 31;
    const int wm   = wid >> 1;
    const int wn   = wid & 1;
    const int m0   = blockIdx.y << 7;
    const int n0   = blockIdx.x << 7;

    const uint32_t sbase = (s2u(dyn) + 1023) & ~1023u;
    const int lrow = tid >> 3;
    const int ls16 = tid & 7;

    float acc[4][8][4];
#pragma unroll
    for (int mi = 0; mi < 4; mi++)
#pragma unroll
        for (int ni = 0; ni < 8; ni++)
#pragma unroll
            for (int j = 0; j < 4; j++) acc[mi][ni][j] = 0.f;

    const int sub  = lane >> 3;
    const int lr8  = lane & 7;
    const int aRowOff = ((sub & 1) << 3) + lr8;
    const int aKHalf  = (sub >> 1) << 4;
    const int bRowOff = ((sub >> 1) << 3) + lr8;
    const int bKHalf  = (sub & 1) << 4;

    auto load_chunk = [&](int c) {
        const int s_ = c % STAGES;
        const uint32_t sA_ = sbase + s_ * STG_SZ;
        const uint32_t sB_ = sA_ + STG_A;
        const int bc = (c & 15) * BK;     // W plane reuse: hi chunks 0-15, lo 16-31
#pragma unroll
        for (int it = 0; it < 8; it++) {
            int row = lrow + (it << 4);
            cp16(sA_ + swz(row * 128 + ls16 * 16),
                 A + (size_t)(m0 + row) * K2 + c * BK + ls16 * 8);
        }
#pragma unroll
        for (int it = 0; it < 8; it++) {
            int row = lrow + (it << 4);
            cp16(sB_ + swz(row * 128 + ls16 * 16),
                 B + (size_t)(n0 + row) * DDIM + bc + ls16 * 8);
        }
        asm volatile("cp.async.commit_group;" ::: "memory");
    };

    load_chunk(0);
    load_chunk(1);

    for (int i = 0; i < NCHUNK; i++) {
        if (i < NCHUNK - 1) asm volatile("cp.async.wait_group 1;" ::: "memory");
        else                asm volatile("cp.async.wait_group 0;" ::: "memory");
        __syncthreads();

        if (i + 2 < NCHUNK) load_chunk(i + 2);

        const int s = i % STAGES;
        const uint32_t sA = sbase + s * STG_SZ;
        const uint32_t sB = sA + STG_A;

#pragma unroll
        for (int kk = 0; kk < 4; kk++) {
            uint32_t af[4][4], bf[4][4];
#pragma unroll
            for (int mi = 0; mi < 4; mi++) {
                int row = wm * 64 + mi * 16 + aRowOff;
                ldsm4(af[mi], sA + swz(row * 128 + kk * 32 + aKHalf));
            }
#pragma unroll
            for (int p = 0; p < 4; p++) {
                int row = wn * 64 + p * 16 + bRowOff;
                ldsm4(bf[p], sB + swz(row * 128 + kk * 32 + bKHalf));
            }
#pragma unroll
            for (int mi = 0; mi < 4; mi++)
#pragma unroll
                for (int nj = 0; nj < 8; nj++)
                    mma16816(acc[mi][nj], af[mi], &bf[nj >> 1][(nj & 1) * 2]);
        }
    }

    const int lr = lane >> 2, lc = (lane & 3) << 1;
    const int sect = (mode == 3) ? (n0 >> 10) : -1;
    if (mode == 0 || sect == 2) {
        float* C = (mode == 0) ? (float*)Cout : g_v;
        const int ncol = n0 & 1023;
#pragma unroll
        for (int mi = 0; mi < 4; mi++)
#pragma unroll
            for (int nj = 0; nj < 8; nj++) {
                int grow = m0 + wm * 64 + mi * 16 + lr;
                int gcol = ncol + wn * 64 + nj * 8 + lc;
                *(float2*)&C[(size_t)grow * DDIM + gcol] =
                    make_float2(acc[mi][nj][0], acc[mi][nj][1]);
                *(float2*)&C[(size_t)(grow + 8) * DDIM + gcol] =
                    make_float2(acc[mi][nj][2], acc[mi][nj][3]);
            }
    } else {
        const bool isq = (sect == 0);
        const float sc = isq ? 0.125f : 1.f;
        const int hh = ((n0 & 1023) >> 6) + wn;   // warp's 64-col slab == one head
#pragma unroll
        for (int mi = 0; mi < 4; mi++)
#pragma unroll
            for (int nj = 0; nj < 8; nj++) {
                int grow = m0 + wm * 64 + mi * 16 + lr;
                int d    = nj * 8 + lc;
#pragma unroll
                for (int half_ = 0; half_ < 2; half_++) {
                    int row = grow + half_ * 8;
                    int b = row >> 11, t = row & 2047;
                    uint32_t hi2, lo2;
                    split_pair(acc[mi][nj][half_ * 2], acc[mi][nj][half_ * 2 + 1], hi2, lo2, sc);
                    if (isq) {                // Q: [hi/8 | lo/8], width 128
                        size_t base = ((size_t)(b * HH + hh) * TT + t) * DKQ + d;
                        *(uint32_t*)(g_qp + base)      = hi2;
                        *(uint32_t*)(g_qp + base + 64) = lo2;
                    } else {                  // K: [hi], width 64
                        size_t base = ((size_t)(b * HH + hh) * TT + t) * DKK + d;
                        *(uint32_t*)(g_kp + base)      = hi2;
                    }
                }
            }
    }
}

// ---------------------------------------------------------------------------
// fp16 flash attention. Q 2-plane (exact), K 1-plane. PV: single fp16 P,
// V hi+lo (2 MMAs). K frags loaded once, reused across Q planes.
// Writes [hi | lo] fp16 K2 activation for the Wo GEMM.
// Grid (T/128, H, B), 256 threads, 8 warps x 16 q-rows.
// ---------------------------------------------------------------------------
#define ATT_QSZ   32768                    // 2 planes x (128 x 128B)
#define ATT_STG   24576                    // K 8KB + Vh 8KB + Vl 8KB
#define ATT_DYN   (ATT_QSZ + 2*ATT_STG + 1024)

__global__ __launch_bounds__(256, 1) void attn_mma(const __half* __restrict__ Qp,
                                                   const __half* __restrict__ Kp,
                                                   const __half* __restrict__ Vth,
                                                   const __half* __restrict__ Vtl,
                                                   __half* __restrict__ Osplit) {
    extern __shared__ char dyn[];
    const int tid = threadIdx.x, wid = tid >> 5, lane = tid & 31;
    const int qb = blockIdx.x, h = blockIdx.y, b = blockIdx.z;
    const int q0 = qb << 7;
    const int ntiles = 2 * qb + 2;

    const uint32_t sb = (s2u(dyn) + 1023) & ~1023u;
    const uint32_t QS = sb;
    const uint32_t ST0 = sb + ATT_QSZ;
    const uint32_t ST1 = ST0 + ATT_STG;

    const int sub = lane >> 3, lr8 = lane & 7;
    const int aRowOff = ((sub & 1) << 3) + lr8;
    const int aKHalf  = (sub >> 1) << 4;
    const int bRowOff = ((sub >> 1) << 3) + lr8;
    const int bKHalf  = (sub & 1) << 4;

    const size_t bh = (size_t)(b * HH + h);
    const __half* Qg  = Qp  + (bh * TT + q0) * DKQ;
    const __half* Kg  = Kp  + bh * TT * DKK;
    const __half* Vhg = Vth + bh * HDD * TT;
    const __half* Vlg = Vtl + bh * HDD * TT;

#pragma unroll
    for (int it = 0; it < 8; it++) {
        int idx = tid + it * 256;
        int row = idx >> 4, s16 = idx & 15;
        int pl = s16 >> 3, seg = s16 & 7;
        cp16(QS + pl * 16384 + swz(row * 128 + seg * 16),
             Qg + (size_t)row * DKQ + pl * 64 + seg * 8);
    }
    asm volatile("cp.async.commit_group;" ::: "memory");

    auto load_kv = [&](int jt) {
        const uint32_t S = (jt & 1) ? ST1 : ST0;
        const int kv0 = jt << 6;
#pragma unroll
        for (int it = 0; it < 2; it++) {       // K
            int idx = tid + it * 256;
            int row = idx >> 3, seg = idx & 7;
            cp16(S + swz(row * 128 + seg * 16),
                 Kg + (size_t)(kv0 + row) * DKK + seg * 8);
        }
#pragma unroll
        for (int it = 0; it < 2; it++) {       // Vh
            int idx = tid + it * 256;
            int row = idx >> 3, seg = idx & 7;
            cp16(S + 8192 + swz(row * 128 + seg * 16),
                 Vhg + (size_t)row * TT + kv0 + seg * 8);
        }
#pragma unroll
        for (int it = 0; it < 2; it++) {       // Vl
            int idx = tid + it * 256;
            int row = idx >> 3, seg = idx & 7;
            cp16(S + 16384 + swz(row * 128 + seg * 16),
                 Vlg + (size_t)row * TT + kv0 + seg * 8);
        }
        asm volatile("cp.async.commit_group;" ::: "memory");
    };
    load_kv(0);
    load_kv(1);

    asm volatile("cp.async.wait_group 2;" ::: "memory");
    __syncthreads();

    uint32_t qa[8][4];
#pragma unroll
    for (int kk = 0; kk < 8; kk++) {
        int row = wid * 16 + aRowOff;
        ldsm4(qa[kk], QS + (kk >> 2) * 16384 + swz(row * 128 + (kk & 3) * 32 + aKHalf));
    }

    float oc[8][4];
#pragma unroll
    for (int j = 0; j < 8; j++)
#pragma unroll
        for (int e = 0; e < 4; e++) oc[j][e] = 0.f;
    float m0 = -1e30f, m1 = -1e30f, l0 = 0.f, l1 = 0.f;

    const int trow0 = q0 + wid * 16 + (lane >> 2);

    for (int jt = 0; jt < ntiles; jt++) {
        if (jt + 1 < ntiles) asm volatile("cp.async.wait_group 1;" ::: "memory");
        else                 asm volatile("cp.async.wait_group 0;" ::: "memory");
        __syncthreads();
        const uint32_t S = (jt & 1) ? ST1 : ST0;

        // scores: K frags loaded once per kk, used for both Q planes
        float sc[8][4];
#pragma unroll
        for (int j = 0; j < 8; j++)
#pragma unroll
            for (int e = 0; e < 4; e++) sc[j][e] = 0.f;
#pragma unroll
        for (int kk = 0; kk < 4; kk++) {
            uint32_t kf[4][4];
#pragma unroll
            for (int p = 0; p < 4; p++)
                ldsm4(kf[p], S + swz((p * 16 + bRowOff) * 128 + kk * 32 + bKHalf));
#pragma unroll
            for (int j = 0; j < 8; j++) {
                mma16816(sc[j], qa[kk],     &kf[j >> 1][(j & 1) * 2]);
                mma16816(sc[j], qa[kk + 4], &kf[j >> 1][(j & 1) * 2]);
            }
        }

        if (jt >= 2 * qb) {
            int s0c = jt << 6;
#pragma unroll
            for (int j = 0; j < 8; j++) {
                int scol = s0c + 8 * j + ((lane & 3) << 1);
                if (scol     > trow0)     sc[j][0] = -1e30f;
                if (scol + 1 > trow0)     sc[j][1] = -1e30f;
                if (scol     > trow0 + 8) sc[j][2] = -1e30f;
                if (scol + 1 > trow0 + 8) sc[j][3] = -1e30f;
            }
        }

        float r0 = -1e30f, r1 = -1e30f;
#pragma unroll
        for (int j = 0; j < 8; j++) {
            r0 = fmaxf(r0, fmaxf(sc[j][0], sc[j][1]));
            r1 = fmaxf(r1, fmaxf(sc[j][2], sc[j][3]));
        }
        r0 = fmaxf(r0, __shfl_xor_sync(0xffffffffu, r0, 1));
        r0 = fmaxf(r0, __shfl_xor_sync(0xffffffffu, r0, 2));
        r1 = fmaxf(r1, __shfl_xor_sync(0xffffffffu, r1, 1));
        r1 = fmaxf(r1, __shfl_xor_sync(0xffffffffu, r1, 2));
        float mn0 = fmaxf(m0, r0), mn1 = fmaxf(m1, r1);
        float a0 = __expf(m0 - mn0), a1 = __expf(m1 - mn1);
        float s0 = 0.f, s1 = 0.f;
#pragma unroll
        for (int j = 0; j < 8; j++) {
            sc[j][0] = __expf(sc[j][0] - mn0); sc[j][1] = __expf(sc[j][1] - mn0);
            sc[j][2] = __expf(sc[j][2] - mn1); sc[j][3] = __expf(sc[j][3] - mn1);
            s0 += sc[j][0] + sc[j][1];         s1 += sc[j][2] + sc[j][3];
        }
        s0 += __shfl_xor_sync(0xffffffffu, s0, 1);
        s0 += __shfl_xor_sync(0xffffffffu, s0, 2);
        s1 += __shfl_xor_sync(0xffffffffu, s1, 1);
        s1 += __shfl_xor_sync(0xffffffffu, s1, 2);
        l0 = l0 * a0 + s0; l1 = l1 * a1 + s1; m0 = mn0; m1 = mn1;
#pragma unroll
        for (int j = 0; j < 8; j++) {
            oc[j][0] *= a0; oc[j][1] *= a0; oc[j][2] *= a1; oc[j][3] *= a1;
        }

        // single fp16 P (C-frag -> A-frag packing, register-only)
        uint32_t ph[8][2];
#pragma unroll
        for (int j = 0; j < 8; j++) {
            __half2 t01{__float2half_rn(sc[j][0]), __float2half_rn(sc[j][1])};
            __half2 t23{__float2half_rn(sc[j][2]), __float2half_rn(sc[j][3])};
            ph[j][0] = *(uint32_t*)&t01; ph[j][1] = *(uint32_t*)&t23;
        }

        // PV: O += P@Vhi + P@Vlo
#pragma unroll
        for (int kc = 0; kc < 4; kc++) {
            uint32_t pah[4] = {ph[2*kc][0], ph[2*kc][1], ph[2*kc+1][0], ph[2*kc+1][1]};
            uint32_t vhf[4][4], vlf[4][4];
#pragma unroll
            for (int p = 0; p < 4; p++) {
                ldsm4(vhf[p], S + 8192  + swz((p * 16 + bRowOff) * 128 + kc * 32 + bKHalf));
                ldsm4(vlf[p], S + 16384 + swz((p * 16 + bRowOff) * 128 + kc * 32 + bKHalf));
            }
#pragma unroll
            for (int j = 0; j < 8; j++) {
                mma16816(oc[j], pah, &vhf[j >> 1][(j & 1) * 2]);
                mma16816(oc[j], pah, &vlf[j >> 1][(j & 1) * 2]);
            }
        }
        __syncthreads();
        if (jt + 2 < ntiles) load_kv(jt + 2);
    }

    // Epilogue: normalize + split to [hi | lo] K2 fp16 layout
    float i0 = 1.f / l0, i1 = 1.f / l1;
    size_t rA = (size_t)(b * TT + trow0) * K2 + h * HDD;
    size_t rB = rA + (size_t)8 * K2;
#pragma unroll
    for (int j = 0; j < 8; j++) {
        int col = 8 * j + ((lane & 3) << 1);
        uint32_t hi2, lo2;
        split_pair(oc[j][0] * i0, oc[j][1] * i0, hi2, lo2, 1.f);
        *(uint32_t*)(Osplit + rA + col)        = hi2;
        *(uint32_t*)(Osplit + rA + col + 1024) = lo2;
        split_pair(oc[j][2] * i1, oc[j][3] * i1, hi2, lo2, 1.f);
        *(uint32_t*)(Osplit + rB + col)        = hi2;
        *(uint32_t*)(Osplit + rB + col + 1024) = lo2;
    }
}

// ---------------------------------------------------------------------------
extern "C" void kernel_launch(void* const* d_in, const int* in_sizes, int n_in,
                              void* d_out, int out_size) {
    const float* x  = (const float*)d_in[0];
    const float* Wq = (const float*)d_in[1];
    const float* Wk = (const float*)d_in[2];
    const float* Wv = (const float*)d_in[3];
    const float* Wo = (const float*)d_in[4];
    float* out = (float*)d_out;

    float *vb;
    __half *xs, *ats, *w16, *wo16, *qp, *kp, *vth, *vtl;
    cudaGetSymbolAddress((void**)&vb, g_v);
    cudaGetSymbolAddress((void**)&xs, g_xs);
    cudaGetSymbolAddress((void**)&ats, g_atts);
    cudaGetSymbolAddress((void**)&w16, g_w16);
    cudaGetSymbolAddress((void**)&wo16, g_wo16);
    cudaGetSymbolAddress((void**)&qp, g_qp);
    cudaGetSymbolAddress((void**)&kp, g_kp);
    cudaGetSymbolAddress((void**)&vth, g_vth);
    cudaGetSymbolAddress((void**)&vtl, g_vtl);

    cudaFuncSetAttribute(gemm_hmma, cudaFuncAttributeMaxDynamicSharedMemorySize, GEMM_DYN);
    cudaFuncSetAttribute(attn_mma, cudaFuncAttributeMaxDynamicSharedMemorySize, ATT_DYN);

    // operand prep
    split2<<<MM, 256>>>(x, xs);
    dim3 wgrid(DDIM, 4);
    wconv4<<<wgrid, 256>>>(Wq, Wk, Wv, Wo, w16, wo16);

    // merged Q/K/V projection: one launch, N=3072
    dim3 qkvgrid(3 * DDIM / 128, MM / 128);   // (24, 32) = 768 CTAs
    gemm_hmma<<<qkvgrid, 128, GEMM_DYN>>>(xs, w16, nullptr, 3);

    dim3 vgrid(TT / 64, HH, BB);
    vtrans<<<vgrid, 256>>>(vb, vth, vtl);

    dim3 agrid(TT / 128, HH, BB);             // (16, 16, 2)
    attn_mma<<<agrid, 256, ATT_DYN>>>(qp, kp, vth, vtl, ats);

    // Wo: 2-term fp16
    dim3 ogrid(DDIM / 128, MM / 128);         // (8, 32)
    gemm_hmma<<<ogrid, 128, GEMM_DYN>>>(ats, wo16, out, 0);
}

// round 9
// speedup vs baseline: 12.3639x; 1.0956x over previous
#include <cuda_runtime.h>
#include <cuda_fp16.h>
#include <cstdint>

// Problem constants
#define BB   2
#define TT   2048
#define DDIM 1024
#define HH   16
#define HDD  64
#define MM   (BB*TT)   // 4096 rows
#define K2   2048      // split-K: [hi | lo] activations, W plane reused
#define DKQ  128       // attention packed Q dim (hi|lo)
#define DKK  64        // attention K/V dim (hi only)

// Scratch (__device__ globals; no allocations allowed)
__device__ __half g_xs[MM*K2];
__device__ __half g_atts[MM*K2];
__device__ __half g_w16[3*DDIM*DDIM];    // [Wq | Wk | Wv] fp16 planes
__device__ __half g_wo16[DDIM*DDIM];
__device__ __half g_qp[BB*HH*TT*DKQ];
__device__ __half g_kp[BB*HH*TT*DKK];
__device__ __half g_vp[BB*HH*TT*DKK];

// ---------------------------------------------------------------------------
__device__ __forceinline__ uint32_t s2u(const void* p) {
    uint32_t a;
    asm("{ .reg .u64 t; cvta.to.shared.u64 t, %1; cvt.u32.u64 %0, t; }" : "=r"(a) : "l"(p));
    return a;
}
__device__ __forceinline__ uint32_t swz(uint32_t o) { return o ^ ((o >> 3) & 0x70); }
__device__ __forceinline__ void cp16(uint32_t dst, const void* src) {
    asm volatile("cp.async.cg.shared.global [%0], [%1], 16;" :: "r"(dst), "l"(src));
}
__device__ __forceinline__ void ldsm4(uint32_t* r, uint32_t addr) {
    asm volatile("ldmatrix.sync.aligned.m8n8.x4.shared.b16 {%0,%1,%2,%3}, [%4];"
                 : "=r"(r[0]), "=r"(r[1]), "=r"(r[2]), "=r"(r[3]) : "r"(addr));
}
__device__ __forceinline__ void ldsm4t(uint32_t* r, uint32_t addr) {
    asm volatile("ldmatrix.sync.aligned.m8n8.x4.trans.shared.b16 {%0,%1,%2,%3}, [%4];"
                 : "=r"(r[0]), "=r"(r[1]), "=r"(r[2]), "=r"(r[3]) : "r"(addr));
}
__device__ __forceinline__ void mma16816(float* c, const uint32_t* a, const uint32_t* b) {
    asm volatile("mma.sync.aligned.m16n8k16.row.col.f32.f16.f16.f32 "
                 "{%0,%1,%2,%3}, {%4,%5,%6,%7}, {%8,%9}, {%0,%1,%2,%3};"
                 : "+f"(c[0]), "+f"(c[1]), "+f"(c[2]), "+f"(c[3])
                 : "r"(a[0]), "r"(a[1]), "r"(a[2]), "r"(a[3]), "r"(b[0]), "r"(b[1]));
}
// split (v0,v1) into fp16 hi + lo packed as half2 words; optional exact pow2 scale
__device__ __forceinline__ void split_pair(float v0, float v1, uint32_t& hi2, uint32_t& lo2,
                                           float scale) {
    __half h0 = __float2half_rn(v0), h1 = __float2half_rn(v1);
    __half l0 = __float2half_rn(v0 - __half2float(h0));
    __half l1 = __float2half_rn(v1 - __half2float(h1));
    if (scale != 1.f) {
        h0 = __float2half_rn(__half2float(h0) * scale);
        h1 = __float2half_rn(__half2float(h1) * scale);
        l0 = __float2half_rn(__half2float(l0) * scale);
        l1 = __float2half_rn(__half2float(l1) * scale);
    }
    __half2 hp{h0, h1}, lp{l0, l1};
    hi2 = *(uint32_t*)&hp; lo2 = *(uint32_t*)&lp;
}

// ---------------------------------------------------------------------------
// split2: fp32 x [rows,1024] -> fp16 [rows,2048]  [hi | lo]
// ---------------------------------------------------------------------------
__global__ __launch_bounds__(256) void split2(const float* __restrict__ in,
                                              __half* __restrict__ out) {
    int idx = (blockIdx.x * 256 + threadIdx.x) * 4;
    int r = idx >> 10, c = idx & 1023;
    float4 v = *(const float4*)(in + idx);
    uint32_t h01, l01, h23, l23;
    split_pair(v.x, v.y, h01, l01, 1.f);
    split_pair(v.z, v.w, h23, l23, 1.f);
    size_t base = (size_t)r * K2 + c;
    *(uint32_t*)(out + base)            = h01;
    *(uint32_t*)(out + base + 2)        = h23;
    *(uint32_t*)(out + base + 1024)     = l01;
    *(uint32_t*)(out + base + 1024 + 2) = l23;
}

// wconv4: Wq/Wk/Wv -> merged fp16 buffer; Wo -> own plane. One launch.
__global__ __launch_bounds__(256) void wconv4(const float* __restrict__ w0,
                                              const float* __restrict__ w1,
                                              const float* __restrict__ w2,
                                              const float* __restrict__ w3,
                                              __half* __restrict__ wqkv,
                                              __half* __restrict__ wo) {
    const float* in; __half* out;
    switch (blockIdx.y) {
        case 0: in = w0; out = wqkv; break;
        case 1: in = w1; out = wqkv + DDIM*DDIM; break;
        case 2: in = w2; out = wqkv + 2*DDIM*DDIM; break;
        default: in = w3; out = wo; break;
    }
    int idx = (blockIdx.x * 256 + threadIdx.x) * 4;
    float4 v = *(const float4*)(in + idx);
    __half2 a{__float2half_rn(v.x), __float2half_rn(v.y)};
    __half2 b{__float2half_rn(v.z), __float2half_rn(v.w)};
    *(uint32_t*)(out + idx)     = *(uint32_t*)&a;
    *(uint32_t*)(out + idx + 2) = *(uint32_t*)&b;
}

// ---------------------------------------------------------------------------
// fp16 HMMA NT GEMM, 2-term split-K (A=[hi|lo], B plane reused c%16).
// CTA 128x128, 4 warps (2x2), warp tile 64x64, BK=64, 3-stage, 2 CTA/SM.
// mode 0: fp32 C out (width DDIM).
// mode 3: merged QKV — section n0>>10: 0 -> Q 2-plane pack, 1 -> K pack, 2 -> V pack.
// ---------------------------------------------------------------------------
#define BK      64
#define STAGES  3
#define NCHUNK  (K2 / BK)                 // 32
#define STG_A   (128 * 128)               // 16 KB
#define STG_B   (128 * 128)               // 16 KB
#define STG_SZ  (STG_A + STG_B)           // 32 KB
#define GEMM_DYN (STAGES * STG_SZ + 1024) // ~97 KB

__global__ __launch_bounds__(128, 2) void gemm_hmma(const __half* __restrict__ A,
                                                    const __half* __restrict__ B,
                                                    void* __restrict__ Cout, int mode) {
    extern __shared__ char dyn[];
    const int tid  = threadIdx.x;
    const int wid  = tid >> 5, lane = tid & 31;
    const int wm   = wid >> 1;
    const int wn   = wid & 1;
    const int m0   = blockIdx.y << 7;
    const int n0   = blockIdx.x << 7;

    const uint32_t sbase = (s2u(dyn) + 1023) & ~1023u;
    const int lrow = tid >> 3;
    const int ls16 = tid & 7;

    float acc[4][8][4];
#pragma unroll
    for (int mi = 0; mi < 4; mi++)
#pragma unroll
        for (int ni = 0; ni < 8; ni++)
#pragma unroll
            for (int j = 0; j < 4; j++) acc[mi][ni][j] = 0.f;

    const int sub  = lane >> 3;
    const int lr8  = lane & 7;
    const int aRowOff = ((sub & 1) << 3) + lr8;
    const int aKHalf  = (sub >> 1) << 4;
    const int bRowOff = ((sub >> 1) << 3) + lr8;
    const int bKHalf  = (sub & 1) << 4;

    auto load_chunk = [&](int c) {
        const int s_ = c % STAGES;
        const uint32_t sA_ = sbase + s_ * STG_SZ;
        const uint32_t sB_ = sA_ + STG_A;
        const int bc = (c & 15) * BK;     // W plane reuse: hi chunks 0-15, lo 16-31
#pragma unroll
        for (int it = 0; it < 8; it++) {
            int row = lrow + (it << 4);
            cp16(sA_ + swz(row * 128 + ls16 * 16),
                 A + (size_t)(m0 + row) * K2 + c * BK + ls16 * 8);
        }
#pragma unroll
        for (int it = 0; it < 8; it++) {
            int row = lrow + (it << 4);
            cp16(sB_ + swz(row * 128 + ls16 * 16),
                 B + (size_t)(n0 + row) * DDIM + bc + ls16 * 8);
        }
        asm volatile("cp.async.commit_group;" ::: "memory");
    };

    load_chunk(0);
    load_chunk(1);

    for (int i = 0; i < NCHUNK; i++) {
        if (i < NCHUNK - 1) asm volatile("cp.async.wait_group 1;" ::: "memory");
        else                asm volatile("cp.async.wait_group 0;" ::: "memory");
        __syncthreads();

        if (i + 2 < NCHUNK) load_chunk(i + 2);

        const int s = i % STAGES;
        const uint32_t sA = sbase + s * STG_SZ;
        const uint32_t sB = sA + STG_A;

#pragma unroll
        for (int kk = 0; kk < 4; kk++) {
            uint32_t af[4][4], bf[4][4];
#pragma unroll
            for (int mi = 0; mi < 4; mi++) {
                int row = wm * 64 + mi * 16 + aRowOff;
                ldsm4(af[mi], sA + swz(row * 128 + kk * 32 + aKHalf));
            }
#pragma unroll
            for (int p = 0; p < 4; p++) {
                int row = wn * 64 + p * 16 + bRowOff;
                ldsm4(bf[p], sB + swz(row * 128 + kk * 32 + bKHalf));
            }
#pragma unroll
            for (int mi = 0; mi < 4; mi++)
#pragma unroll
                for (int nj = 0; nj < 8; nj++)
                    mma16816(acc[mi][nj], af[mi], &bf[nj >> 1][(nj & 1) * 2]);
        }
    }

    const int lr = lane >> 2, lc = (lane & 3) << 1;
    if (mode == 0) {
        float* C = (float*)Cout;
#pragma unroll
        for (int mi = 0; mi < 4; mi++)
#pragma unroll
            for (int nj = 0; nj < 8; nj++) {
                int grow = m0 + wm * 64 + mi * 16 + lr;
                int gcol = n0 + wn * 64 + nj * 8 + lc;
                *(float2*)&C[(size_t)grow * DDIM + gcol] =
                    make_float2(acc[mi][nj][0], acc[mi][nj][1]);
                *(float2*)&C[(size_t)(grow + 8) * DDIM + gcol] =
                    make_float2(acc[mi][nj][2], acc[mi][nj][3]);
            }
    } else {
        const int sect = n0 >> 10;                // 0=Q, 1=K, 2=V
        const float sc = (sect == 0) ? 0.125f : 1.f;
        const int hh = ((n0 & 1023) >> 6) + wn;   // warp's 64-col slab == one head
        __half* Psingle = (sect == 1) ? g_kp : g_vp;
#pragma unroll
        for (int mi = 0; mi < 4; mi++)
#pragma unroll
            for (int nj = 0; nj < 8; nj++) {
                int grow = m0 + wm * 64 + mi * 16 + lr;
                int d    = nj * 8 + lc;
#pragma unroll
                for (int half_ = 0; half_ < 2; half_++) {
                    int row = grow + half_ * 8;
                    int b = row >> 11, t = row & 2047;
                    uint32_t hi2, lo2;
                    split_pair(acc[mi][nj][half_ * 2], acc[mi][nj][half_ * 2 + 1], hi2, lo2, sc);
                    if (sect == 0) {          // Q: [hi/8 | lo/8], width 128
                        size_t base = ((size_t)(b * HH + hh) * TT + t) * DKQ + d;
                        *(uint32_t*)(g_qp + base)      = hi2;
                        *(uint32_t*)(g_qp + base + 64) = lo2;
                    } else {                  // K/V: [hi], width 64
                        size_t base = ((size_t)(b * HH + hh) * TT + t) * DKK + d;
                        *(uint32_t*)(Psingle + base)   = hi2;
                    }
                }
            }
    }
}

// ---------------------------------------------------------------------------
// fp16 flash attention. Q 2-plane (exact), K 1-plane, V 1-plane via
// trans-ldmatrix (row-major V tiles, no pre-transpose).
// Writes [hi | lo] fp16 K2 activation for the Wo GEMM.
// Grid (T/128, H, B), 256 threads, 8 warps x 16 q-rows.
// ---------------------------------------------------------------------------
#define ATT_QSZ   32768                    // 2 planes x (128 x 128B)
#define ATT_STG   16384                    // K 8KB + V 8KB
#define ATT_DYN   (ATT_QSZ + 2*ATT_STG + 1024)

__global__ __launch_bounds__(256, 1) void attn_mma(const __half* __restrict__ Qp,
                                                   const __half* __restrict__ Kp,
                                                   const __half* __restrict__ Vp,
                                                   __half* __restrict__ Osplit) {
    extern __shared__ char dyn[];
    const int tid = threadIdx.x, wid = tid >> 5, lane = tid & 31;
    const int qb = blockIdx.x, h = blockIdx.y, b = blockIdx.z;
    const int q0 = qb << 7;
    const int ntiles = 2 * qb + 2;

    const uint32_t sb = (s2u(dyn) + 1023) & ~1023u;
    const uint32_t QS = sb;
    const uint32_t ST0 = sb + ATT_QSZ;
    const uint32_t ST1 = ST0 + ATT_STG;

    const int sub = lane >> 3, lr8 = lane & 7;
    const int aRowOff = ((sub & 1) << 3) + lr8;   // also trans-ldsm row offset
    const int aKHalf  = (sub >> 1) << 4;          // also trans-ldsm col offset
    const int bRowOff = ((sub >> 1) << 3) + lr8;
    const int bKHalf  = (sub & 1) << 4;

    const size_t bh = (size_t)(b * HH + h);
    const __half* Qg = Qp + (bh * TT + q0) * DKQ;
    const __half* Kg = Kp + bh * TT * DKK;
    const __half* Vg = Vp + bh * TT * DKK;

#pragma unroll
    for (int it = 0; it < 8; it++) {
        int idx = tid + it * 256;
        int row = idx >> 4, s16 = idx & 15;
        int pl = s16 >> 3, seg = s16 & 7;
        cp16(QS + pl * 16384 + swz(row * 128 + seg * 16),
             Qg + (size_t)row * DKQ + pl * 64 + seg * 8);
    }
    asm volatile("cp.async.commit_group;" ::: "memory");

    auto load_kv = [&](int jt) {
        const uint32_t S = (jt & 1) ? ST1 : ST0;
        const int kv0 = jt << 6;
#pragma unroll
        for (int it = 0; it < 2; it++) {       // K [s][d] 64x128B
            int idx = tid + it * 256;
            int row = idx >> 3, seg = idx & 7;
            cp16(S + swz(row * 128 + seg * 16),
                 Kg + (size_t)(kv0 + row) * DKK + seg * 8);
        }
#pragma unroll
        for (int it = 0; it < 2; it++) {       // V [s][d] 64x128B
            int idx = tid + it * 256;
            int row = idx >> 3, seg = idx & 7;
            cp16(S + 8192 + swz(row * 128 + seg * 16),
                 Vg + (size_t)(kv0 + row) * DKK + seg * 8);
        }
        asm volatile("cp.async.commit_group;" ::: "memory");
    };
    load_kv(0);
    load_kv(1);

    asm volatile("cp.async.wait_group 2;" ::: "memory");
    __syncthreads();

    uint32_t qa[8][4];
#pragma unroll
    for (int kk = 0; kk < 8; kk++) {
        int row = wid * 16 + aRowOff;
        ldsm4(qa[kk], QS + (kk >> 2) * 16384 + swz(row * 128 + (kk & 3) * 32 + aKHalf));
    }

    float oc[8][4];
#pragma unroll
    for (int j = 0; j < 8; j++)
#pragma unroll
        for (int e = 0; e < 4; e++) oc[j][e] = 0.f;
    float m0 = -1e30f, m1 = -1e30f, l0 = 0.f, l1 = 0.f;

    const int trow0 = q0 + wid * 16 + (lane >> 2);

    for (int jt = 0; jt < ntiles; jt++) {
        if (jt + 1 < ntiles) asm volatile("cp.async.wait_group 1;" ::: "memory");
        else                 asm volatile("cp.async.wait_group 0;" ::: "memory");
        __syncthreads();
        const uint32_t S = (jt & 1) ? ST1 : ST0;

        // scores: K frags loaded once per kk, used for both Q planes
        float sc[8][4];
#pragma unroll
        for (int j = 0; j < 8; j++)
#pragma unroll
            for (int e = 0; e < 4; e++) sc[j][e] = 0.f;
#pragma unroll
        for (int kk = 0; kk < 4; kk++) {
            uint32_t kf[4][4];
#pragma unroll
            for (int p = 0; p < 4; p++)
                ldsm4(kf[p], S + swz((p * 16 + bRowOff) * 128 + kk * 32 + bKHalf));
#pragma unroll
            for (int j = 0; j < 8; j++) {
                mma16816(sc[j], qa[kk],     &kf[j >> 1][(j & 1) * 2]);
                mma16816(sc[j], qa[kk + 4], &kf[j >> 1][(j & 1) * 2]);
            }
        }

        if (jt >= 2 * qb) {
            int s0c = jt << 6;
#pragma unroll
            for (int j = 0; j < 8; j++) {
                int scol = s0c + 8 * j + ((lane & 3) << 1);
                if (scol     > trow0)     sc[j][0] = -1e30f;
                if (scol + 1 > trow0)     sc[j][1] = -1e30f;
                if (scol     > trow0 + 8) sc[j][2] = -1e30f;
                if (scol + 1 > trow0 + 8) sc[j][3] = -1e30f;
            }
        }

        float r0 = -1e30f, r1 = -1e30f;
#pragma unroll
        for (int j = 0; j < 8; j++) {
            r0 = fmaxf(r0, fmaxf(sc[j][0], sc[j][1]));
            r1 = fmaxf(r1, fmaxf(sc[j][2], sc[j][3]));
        }
        r0 = fmaxf(r0, __shfl_xor_sync(0xffffffffu, r0, 1));
        r0 = fmaxf(r0, __shfl_xor_sync(0xffffffffu, r0, 2));
        r1 = fmaxf(r1, __shfl_xor_sync(0xffffffffu, r1, 1));
        r1 = fmaxf(r1, __shfl_xor_sync(0xffffffffu, r1, 2));
        float mn0 = fmaxf(m0, r0), mn1 = fmaxf(m1, r1);
        float a0 = __expf(m0 - mn0), a1 = __expf(m1 - mn1);
        float s0 = 0.f, s1 = 0.f;
#pragma unroll
        for (int j = 0; j < 8; j++) {
            sc[j][0] = __expf(sc[j][0] - mn0); sc[j][1] = __expf(sc[j][1] - mn0);
            sc[j][2] = __expf(sc[j][2] - mn1); sc[j][3] = __expf(sc[j][3] - mn1);
            s0 += sc[j][0] + sc[j][1];         s1 += sc[j][2] + sc[j][3];
        }
        s0 += __shfl_xor_sync(0xffffffffu, s0, 1);
        s0 += __shfl_xor_sync(0xffffffffu, s0, 2);
        s1 += __shfl_xor_sync(0xffffffffu, s1, 1);
        s1 += __shfl_xor_sync(0xffffffffu, s1, 2);
        l0 = l0 * a0 + s0; l1 = l1 * a1 + s1; m0 = mn0; m1 = mn1;
#pragma unroll
        for (int j = 0; j < 8; j++) {
            oc[j][0] *= a0; oc[j][1] *= a0; oc[j][2] *= a1; oc[j][3] *= a1;
        }

        // single fp16 P (C-frag -> A-frag packing, register-only)
        uint32_t ph[8][2];
#pragma unroll
        for (int j = 0; j < 8; j++) {
            __half2 t01{__float2half_rn(sc[j][0]), __float2half_rn(sc[j][1])};
            __half2 t23{__float2half_rn(sc[j][2]), __float2half_rn(sc[j][3])};
            ph[j][0] = *(uint32_t*)&t01; ph[j][1] = *(uint32_t*)&t23;
        }

        // PV: O += P@V, V frags via trans-ldmatrix from row-major [s][d] tile
#pragma unroll
        for (int kc = 0; kc < 4; kc++) {
            uint32_t pah[4] = {ph[2*kc][0], ph[2*kc][1], ph[2*kc+1][0], ph[2*kc+1][1]};
            uint32_t vf[4][4];
#pragma unroll
            for (int p = 0; p < 4; p++)
                ldsm4t(vf[p], S + 8192 +
                       swz((kc * 16 + aRowOff) * 128 + p * 32 + aKHalf));
#pragma unroll
            for (int j = 0; j < 8; j++)
                mma16816(oc[j], pah, &vf[j >> 1][(j & 1) * 2]);
        }
        __syncthreads();
        if (jt + 2 < ntiles) load_kv(jt + 2);
    }

    // Epilogue: normalize + split to [hi | lo] K2 fp16 layout
    float i0 = 1.f / l0, i1 = 1.f / l1;
    size_t rA = (size_t)(b * TT + trow0) * K2 + h * HDD;
    size_t rB = rA + (size_t)8 * K2;
#pragma unroll
    for (int j = 0; j < 8; j++) {
        int col = 8 * j + ((lane & 3) << 1);
        uint32_t hi2, lo2;
        split_pair(oc[j][0] * i0, oc[j][1] * i0, hi2, lo2, 1.f);
        *(uint32_t*)(Osplit + rA + col)        = hi2;
        *(uint32_t*)(Osplit + rA + col + 1024) = lo2;
        split_pair(oc[j][2] * i1, oc[j][3] * i1, hi2, lo2, 1.f);
        *(uint32_t*)(Osplit + rB + col)        = hi2;
        *(uint32_t*)(Osplit + rB + col + 1024) = lo2;
    }
}

// ---------------------------------------------------------------------------
extern "C" void kernel_launch(void* const* d_in, const int* in_sizes, int n_in,
                              void* d_out, int out_size) {
    const float* x  = (const float*)d_in[0];
    const float* Wq = (const float*)d_in[1];
    const float* Wk = (const float*)d_in[2];
    const float* Wv = (const float*)d_in[3];
    const float* Wo = (const float*)d_in[4];
    float* out = (float*)d_out;

    __half *xs, *ats, *w16, *wo16, *qp, *kp, *vp;
    cudaGetSymbolAddress((void**)&xs, g_xs);
    cudaGetSymbolAddress((void**)&ats, g_atts);
    cudaGetSymbolAddress((void**)&w16, g_w16);
    cudaGetSymbolAddress((void**)&wo16, g_wo16);
    cudaGetSymbolAddress((void**)&qp, g_qp);
    cudaGetSymbolAddress((void**)&kp, g_kp);
    cudaGetSymbolAddress((void**)&vp, g_vp);

    cudaFuncSetAttribute(gemm_hmma, cudaFuncAttributeMaxDynamicSharedMemorySize, GEMM_DYN);
    cudaFuncSetAttribute(attn_mma, cudaFuncAttributeMaxDynamicSharedMemorySize, ATT_DYN);

    // operand prep
    split2<<<MM, 256>>>(x, xs);
    dim3 wgrid(DDIM, 4);
    wconv4<<<wgrid, 256>>>(Wq, Wk, Wv, Wo, w16, wo16);

    // merged Q/K/V projection: one launch, N=3072, packed epilogues
    dim3 qkvgrid(3 * DDIM / 128, MM / 128);   // (24, 32) = 768 CTAs
    gemm_hmma<<<qkvgrid, 128, GEMM_DYN>>>(xs, w16, nullptr, 3);

    dim3 agrid(TT / 128, HH, BB);             // (16, 16, 2)
    attn_mma<<<agrid, 256, ATT_DYN>>>(qp, kp, vp, ats);

    // Wo: 2-term fp16
    dim3 ogrid(DDIM / 128, MM / 128);         // (8, 32)
    gemm_hmma<<<ogrid, 128, GEMM_DYN>>>(ats, wo16, out, 0);
}

// round 12
// speedup vs baseline: 12.8397x; 1.0385x over previous
#include <cuda_runtime.h>
#include <cuda_fp16.h>
#include <cstdint>

// Problem constants
#define BB   2
#define TT   2048
#define DDIM 1024
#define HH   16
#define HDD  64
#define MM   (BB*TT)   // 4096 rows
#define K2   2048      // split-K: [hi | lo] activations, W plane reused
#define DKQ  128       // attention packed Q dim (hi|lo)
#define DKK  64        // attention K/V dim (hi only)

// Scratch (__device__ globals; no allocations allowed)
__device__ __half g_xs[MM*K2];
__device__ __half g_atts[MM*K2];
__device__ __half g_w16[3*DDIM*DDIM];    // [Wq | Wk | Wv] fp16 planes
__device__ __half g_wo16[DDIM*DDIM];
__device__ __half g_qp[BB*HH*TT*DKQ];
__device__ __half g_kp[BB*HH*TT*DKK];
__device__ __half g_vp[BB*HH*TT*DKK];

// ---------------------------------------------------------------------------
__device__ __forceinline__ uint32_t s2u(const void* p) {
    uint32_t a;
    asm("{ .reg .u64 t; cvta.to.shared.u64 t, %1; cvt.u32.u64 %0, t; }" : "=r"(a) : "l"(p));
    return a;
}
__device__ __forceinline__ uint32_t swz(uint32_t o) { return o ^ ((o >> 3) & 0x70); }
__device__ __forceinline__ void cp16(uint32_t dst, const void* src) {
    asm volatile("cp.async.cg.shared.global [%0], [%1], 16;" :: "r"(dst), "l"(src));
}
__device__ __forceinline__ void ldsm4(uint32_t* r, uint32_t addr) {
    asm volatile("ldmatrix.sync.aligned.m8n8.x4.shared.b16 {%0,%1,%2,%3}, [%4];"
                 : "=r"(r[0]), "=r"(r[1]), "=r"(r[2]), "=r"(r[3]) : "r"(addr));
}
__device__ __forceinline__ void ldsm4t(uint32_t* r, uint32_t addr) {
    asm volatile("ldmatrix.sync.aligned.m8n8.x4.trans.shared.b16 {%0,%1,%2,%3}, [%4];"
                 : "=r"(r[0]), "=r"(r[1]), "=r"(r[2]), "=r"(r[3]) : "r"(addr));
}
__device__ __forceinline__ void mma16816(float* c, const uint32_t* a, const uint32_t* b) {
    asm volatile("mma.sync.aligned.m16n8k16.row.col.f32.f16.f16.f32 "
                 "{%0,%1,%2,%3}, {%4,%5,%6,%7}, {%8,%9}, {%0,%1,%2,%3};"
                 : "+f"(c[0]), "+f"(c[1]), "+f"(c[2]), "+f"(c[3])
                 : "r"(a[0]), "r"(a[1]), "r"(a[2]), "r"(a[3]), "r"(b[0]), "r"(b[1]));
}
// split (v0,v1) into fp16 hi + lo packed as half2 words; optional exact pow2 scale
__device__ __forceinline__ void split_pair(float v0, float v1, uint32_t& hi2, uint32_t& lo2,
                                           float scale) {
    __half h0 = __float2half_rn(v0), h1 = __float2half_rn(v1);
    __half l0 = __float2half_rn(v0 - __half2float(h0));
    __half l1 = __float2half_rn(v1 - __half2float(h1));
    if (scale != 1.f) {
        h0 = __float2half_rn(__half2float(h0) * scale);
        h1 = __float2half_rn(__half2float(h1) * scale);
        l0 = __float2half_rn(__half2float(l0) * scale);
        l1 = __float2half_rn(__half2float(l1) * scale);
    }
    __half2 hp{h0, h1}, lp{l0, l1};
    hi2 = *(uint32_t*)&hp; lo2 = *(uint32_t*)&lp;
}

// ---------------------------------------------------------------------------
// split2: fp32 x [rows,1024] -> fp16 [rows,2048]  [hi | lo]
// ---------------------------------------------------------------------------
__global__ __launch_bounds__(256) void split2(const float* __restrict__ in,
                                              __half* __restrict__ out) {
    int idx = (blockIdx.x * 256 + threadIdx.x) * 4;
    int r = idx >> 10, c = idx & 1023;
    float4 v = *(const float4*)(in + idx);
    uint32_t h01, l01, h23, l23;
    split_pair(v.x, v.y, h01, l01, 1.f);
    split_pair(v.z, v.w, h23, l23, 1.f);
    size_t base = (size_t)r * K2 + c;
    *(uint32_t*)(out + base)            = h01;
    *(uint32_t*)(out + base + 2)        = h23;
    *(uint32_t*)(out + base + 1024)     = l01;
    *(uint32_t*)(out + base + 1024 + 2) = l23;
}

// wconv4: Wq/Wk/Wv -> merged fp16 buffer; Wo -> own plane. One launch.
__global__ __launch_bounds__(256) void wconv4(const float* __restrict__ w0,
                                              const float* __restrict__ w1,
                                              const float* __restrict__ w2,
                                              const float* __restrict__ w3,
                                              __half* __restrict__ wqkv,
                                              __half* __restrict__ wo) {
    const float* in; __half* out;
    switch (blockIdx.y) {
        case 0: in = w0; out = wqkv; break;
        case 1: in = w1; out = wqkv + DDIM*DDIM; break;
        case 2: in = w2; out = wqkv + 2*DDIM*DDIM; break;
        default: in = w3; out = wo; break;
    }
    int idx = (blockIdx.x * 256 + threadIdx.x) * 4;
    float4 v = *(const float4*)(in + idx);
    __half2 a{__float2half_rn(v.x), __float2half_rn(v.y)};
    __half2 b{__float2half_rn(v.z), __float2half_rn(v.w)};
    *(uint32_t*)(out + idx)     = *(uint32_t*)&a;
    *(uint32_t*)(out + idx + 2) = *(uint32_t*)&b;
}

// ---------------------------------------------------------------------------
// fp16 HMMA NT GEMM, 2-term split-K (A=[hi|lo], B plane reused c%16).
// CTA 128x128, 4 warps (2x2), warp tile 64x64, BK=64, 3-stage, 2 CTA/SM.
// mode 0: fp32 C out (width DDIM).
// mode 3: merged QKV — section n0>>10: 0 -> Q 2-plane pack, 1 -> K pack, 2 -> V pack.
// ---------------------------------------------------------------------------
#define BK      64
#define STAGES  3
#define NCHUNK  (K2 / BK)                 // 32
#define STG_A   (128 * 128)               // 16 KB
#define STG_B   (128 * 128)               // 16 KB
#define STG_SZ  (STG_A + STG_B)           // 32 KB
#define GEMM_DYN (STAGES * STG_SZ + 1024) // ~97 KB

__global__ __launch_bounds__(128, 2) void gemm_hmma(const __half* __restrict__ A,
                                                    const __half* __restrict__ B,
                                                    void* __restrict__ Cout, int mode) {
    extern __shared__ char dyn[];
    const int tid  = threadIdx.x;
    const int wid  = tid >> 5, lane = tid & 31;
    const int wm   = wid >> 1;
    const int wn   = wid & 1;
    const int m0   = blockIdx.y << 7;
    const int n0   = blockIdx.x << 7;

    const uint32_t sbase = (s2u(dyn) + 1023) & ~1023u;
    const int lrow = tid >> 3;
    const int ls16 = tid & 7;

    float acc[4][8][4];
#pragma unroll
    for (int mi = 0; mi < 4; mi++)
#pragma unroll
        for (int ni = 0; ni < 8; ni++)
#pragma unroll
            for (int j = 0; j < 4; j++) acc[mi][ni][j] = 0.f;

    const int sub  = lane >> 3;
    const int lr8  = lane & 7;
    const int aRowOff = ((sub & 1) << 3) + lr8;
    const int aKHalf  = (sub >> 1) << 4;
    const int bRowOff = ((sub >> 1) << 3) + lr8;
    const int bKHalf  = (sub & 1) << 4;

    auto load_chunk = [&](int c) {
        const int s_ = c % STAGES;
        const uint32_t sA_ = sbase + s_ * STG_SZ;
        const uint32_t sB_ = sA_ + STG_A;
        const int bc = (c & 15) * BK;     // W plane reuse: hi chunks 0-15, lo 16-31
#pragma unroll
        for (int it = 0; it < 8; it++) {
            int row = lrow + (it << 4);
            cp16(sA_ + swz(row * 128 + ls16 * 16),
                 A + (size_t)(m0 + row) * K2 + c * BK + ls16 * 8);
        }
#pragma unroll
        for (int it = 0; it < 8; it++) {
            int row = lrow + (it << 4);
            cp16(sB_ + swz(row * 128 + ls16 * 16),
                 B + (size_t)(n0 + row) * DDIM + bc + ls16 * 8);
        }
        asm volatile("cp.async.commit_group;" ::: "memory");
    };

    load_chunk(0);
    load_chunk(1);

    for (int i = 0; i < NCHUNK; i++) {
        if (i < NCHUNK - 1) asm volatile("cp.async.wait_group 1;" ::: "memory");
        else                asm volatile("cp.async.wait_group 0;" ::: "memory");
        __syncthreads();

        if (i + 2 < NCHUNK) load_chunk(i + 2);

        const int s = i % STAGES;
        const uint32_t sA = sbase + s * STG_SZ;
        const uint32_t sB = sA + STG_A;

#pragma unroll
        for (int kk = 0; kk < 4; kk++) {
            uint32_t af[4][4], bf[4][4];
#pragma unroll
            for (int mi = 0; mi < 4; mi++) {
                int row = wm * 64 + mi * 16 + aRowOff;
                ldsm4(af[mi], sA + swz(row * 128 + kk * 32 + aKHalf));
            }
#pragma unroll
            for (int p = 0; p < 4; p++) {
                int row = wn * 64 + p * 16 + bRowOff;
                ldsm4(bf[p], sB + swz(row * 128 + kk * 32 + bKHalf));
            }
#pragma unroll
            for (int mi = 0; mi < 4; mi++)
#pragma unroll
                for (int nj = 0; nj < 8; nj++)
                    mma16816(acc[mi][nj], af[mi], &bf[nj >> 1][(nj & 1) * 2]);
        }
    }

    const int lr = lane >> 2, lc = (lane & 3) << 1;
    if (mode == 0) {
        float* C = (float*)Cout;
#pragma unroll
        for (int mi = 0; mi < 4; mi++)
#pragma unroll
            for (int nj = 0; nj < 8; nj++) {
                int grow = m0 + wm * 64 + mi * 16 + lr;
                int gcol = n0 + wn * 64 + nj * 8 + lc;
                *(float2*)&C[(size_t)grow * DDIM + gcol] =
                    make_float2(acc[mi][nj][0], acc[mi][nj][1]);
                *(float2*)&C[(size_t)(grow + 8) * DDIM + gcol] =
                    make_float2(acc[mi][nj][2], acc[mi][nj][3]);
            }
    } else {
        const int sect = n0 >> 10;                // 0=Q, 1=K, 2=V
        const float sc = (sect == 0) ? 0.125f : 1.f;
        const int hh = ((n0 & 1023) >> 6) + wn;   // warp's 64-col slab == one head
        __half* Psingle = (sect == 1) ? g_kp : g_vp;
#pragma unroll
        for (int mi = 0; mi < 4; mi++)
#pragma unroll
            for (int nj = 0; nj < 8; nj++) {
                int grow = m0 + wm * 64 + mi * 16 + lr;
                int d    = nj * 8 + lc;
#pragma unroll
                for (int half_ = 0; half_ < 2; half_++) {
                    int row = grow + half_ * 8;
                    int b = row >> 11, t = row & 2047;
                    uint32_t hi2, lo2;
                    split_pair(acc[mi][nj][half_ * 2], acc[mi][nj][half_ * 2 + 1], hi2, lo2, sc);
                    if (sect == 0) {          // Q: [hi/8 | lo/8], width 128
                        size_t base = ((size_t)(b * HH + hh) * TT + t) * DKQ + d;
                        *(uint32_t*)(g_qp + base)      = hi2;
                        *(uint32_t*)(g_qp + base + 64) = lo2;
                    } else {                  // K/V: [hi], width 64
                        size_t base = ((size_t)(b * HH + hh) * TT + t) * DKK + d;
                        *(uint32_t*)(Psingle + base)   = hi2;
                    }
                }
            }
    }
}

// ---------------------------------------------------------------------------
// fp16 flash attention. Q 2-plane (exact), K 1-plane, V 1-plane (trans-ldsm).
// 128 threads (4 warps x 16 q-rows = 64 q-rows/CTA), KV tile 64, 2 CTAs/SM.
// Heavy-first: qb = 31 - blockIdx.x so long CTAs launch first.
// Writes [hi | lo] fp16 K2 activation for the Wo GEMM.
// ---------------------------------------------------------------------------
#define ATT_QSZ   16384                    // 2 planes x (64 x 128B)
#define ATT_STG   16384                    // K 8KB + V 8KB
#define ATT_DYN   (ATT_QSZ + 2*ATT_STG + 1024)   // ~50 KB

__global__ __launch_bounds__(128, 2) void attn_mma(const __half* __restrict__ Qp,
                                                   const __half* __restrict__ Kp,
                                                   const __half* __restrict__ Vp,
                                                   __half* __restrict__ Osplit) {
    extern __shared__ char dyn[];
    const int tid = threadIdx.x, wid = tid >> 5, lane = tid & 31;
    const int qb = (int)(gridDim.x - 1 - blockIdx.x);   // heavy-first
    const int h = blockIdx.y, b = blockIdx.z;
    const int q0 = qb << 6;
    const int ntiles = qb + 1;

    const uint32_t sb = (s2u(dyn) + 1023) & ~1023u;
    const uint32_t QS = sb;
    const uint32_t ST0 = sb + ATT_QSZ;
    const uint32_t ST1 = ST0 + ATT_STG;

    const int sub = lane >> 3, lr8 = lane & 7;
    const int aRowOff = ((sub & 1) << 3) + lr8;   // also trans-ldsm row offset
    const int aKHalf  = (sub >> 1) << 4;          // also trans-ldsm col offset
    const int bRowOff = ((sub >> 1) << 3) + lr8;
    const int bKHalf  = (sub & 1) << 4;

    const size_t bh = (size_t)(b * HH + h);
    const __half* Qg = Qp + (bh * TT + q0) * DKQ;
    const __half* Kg = Kp + bh * TT * DKK;
    const __half* Vg = Vp + bh * TT * DKK;

    // Q tile: 64 rows x 128 halfs = 1024 cp16 / 128 threads = 8 iters
#pragma unroll
    for (int it = 0; it < 8; it++) {
        int idx = tid + it * 128;
        int row = idx >> 4, s16 = idx & 15;
        int pl = s16 >> 3, seg = s16 & 7;
        cp16(QS + pl * 8192 + swz(row * 128 + seg * 16),
             Qg + (size_t)row * DKQ + pl * 64 + seg * 8);
    }
    asm volatile("cp.async.commit_group;" ::: "memory");

    auto load_kv = [&](int jt) {
        const uint32_t S = (jt & 1) ? ST1 : ST0;
        const int kv0 = jt << 6;
#pragma unroll
        for (int it = 0; it < 4; it++) {       // K [s][d] 64x128B
            int idx = tid + it * 128;
            int row = idx >> 3, seg = idx & 7;
            cp16(S + swz(row * 128 + seg * 16),
                 Kg + (size_t)(kv0 + row) * DKK + seg * 8);
        }
#pragma unroll
        for (int it = 0; it < 4; it++) {       // V [s][d] 64x128B
            int idx = tid + it * 128;
            int row = idx >> 3, seg = idx & 7;
            cp16(S + 8192 + swz(row * 128 + seg * 16),
                 Vg + (size_t)(kv0 + row) * DKK + seg * 8);
        }
        asm volatile("cp.async.commit_group;" ::: "memory");
    };
    load_kv(0);
    if (ntiles > 1) load_kv(1);

    // Guarantee Q is complete before ldsm: 3 groups in flight when ntiles>1
    // (Q, kv0, kv1 -> wait 2 leaves kv pending), else 2 groups (Q, kv0 -> wait 1).
    if (ntiles > 1) asm volatile("cp.async.wait_group 2;" ::: "memory");
    else            asm volatile("cp.async.wait_group 1;" ::: "memory");
    __syncthreads();

    uint32_t qa[8][4];
#pragma unroll
    for (int kk = 0; kk < 8; kk++) {
        int row = wid * 16 + aRowOff;
        ldsm4(qa[kk], QS + (kk >> 2) * 8192 + swz(row * 128 + (kk & 3) * 32 + aKHalf));
    }

    float oc[8][4];
#pragma unroll
    for (int j = 0; j < 8; j++)
#pragma unroll
        for (int e = 0; e < 4; e++) oc[j][e] = 0.f;
    float m0 = -1e30f, m1 = -1e30f, l0 = 0.f, l1 = 0.f;

    const int trow0 = q0 + wid * 16 + (lane >> 2);

    for (int jt = 0; jt < ntiles; jt++) {
        if (jt + 1 < ntiles) asm volatile("cp.async.wait_group 1;" ::: "memory");
        else                 asm volatile("cp.async.wait_group 0;" ::: "memory");
        __syncthreads();
        const uint32_t S = (jt & 1) ? ST1 : ST0;

        // scores: K frags loaded once per kk, used for both Q planes
        float sc[8][4];
#pragma unroll
        for (int j = 0; j < 8; j++)
#pragma unroll
            for (int e = 0; e < 4; e++) sc[j][e] = 0.f;
#pragma unroll
        for (int kk = 0; kk < 4; kk++) {
            uint32_t kf[4][4];
#pragma unroll
            for (int p = 0; p < 4; p++)
                ldsm4(kf[p], S + swz((p * 16 + bRowOff) * 128 + kk * 32 + bKHalf));
#pragma unroll
            for (int j = 0; j < 8; j++) {
                mma16816(sc[j], qa[kk],     &kf[j >> 1][(j & 1) * 2]);
                mma16816(sc[j], qa[kk + 4], &kf[j >> 1][(j & 1) * 2]);
            }
        }

        if (jt == ntiles - 1) {   // diagonal tile
            int s0c = jt << 6;
#pragma unroll
            for (int j = 0; j < 8; j++) {
                int scol = s0c + 8 * j + ((lane & 3) << 1);
                if (scol     > trow0)     sc[j][0] = -1e30f;
                if (scol + 1 > trow0)     sc[j][1] = -1e30f;
                if (scol     > trow0 + 8) sc[j][2] = -1e30f;
                if (scol + 1 > trow0 + 8) sc[j][3] = -1e30f;
            }
        }

        float r0 = -1e30f, r1 = -1e30f;
#pragma unroll
        for (int j = 0; j < 8; j++) {
            r0 = fmaxf(r0, fmaxf(sc[j][0], sc[j][1]));
            r1 = fmaxf(r1, fmaxf(sc[j][2], sc[j][3]));
        }
        r0 = fmaxf(r0, __shfl_xor_sync(0xffffffffu, r0, 1));
        r0 = fmaxf(r0, __shfl_xor_sync(0xffffffffu, r0, 2));
        r1 = fmaxf(r1, __shfl_xor_sync(0xffffffffu, r1, 1));
        r1 = fmaxf(r1, __shfl_xor_sync(0xffffffffu, r1, 2));
        float mn0 = fmaxf(m0, r0), mn1 = fmaxf(m1, r1);
        float a0 = __expf(m0 - mn0), a1 = __expf(m1 - mn1);
        float s0 = 0.f, s1 = 0.f;
#pragma unroll
        for (int j = 0; j < 8; j++) {
            sc[j][0] = __expf(sc[j][0] - mn0); sc[j][1] = __expf(sc[j][1] - mn0);
            sc[j][2] = __expf(sc[j][2] - mn1); sc[j][3] = __expf(sc[j][3] - mn1);
            s0 += sc[j][0] + sc[j][1];         s1 += sc[j][2] + sc[j][3];
        }
        s0 += __shfl_xor_sync(0xffffffffu, s0, 1);
        s0 += __shfl_xor_sync(0xffffffffu, s0, 2);
        s1 += __shfl_xor_sync(0xffffffffu, s1, 1);
        s1 += __shfl_xor_sync(0xffffffffu, s1, 2);
        l0 = l0 * a0 + s0; l1 = l1 * a1 + s1; m0 = mn0; m1 = mn1;
#pragma unroll
        for (int j = 0; j < 8; j++) {
            oc[j][0] *= a0; oc[j][1] *= a0; oc[j][2] *= a1; oc[j][3] *= a1;
        }

        // single fp16 P (C-frag -> A-frag packing, register-only)
        uint32_t ph[8][2];
#pragma unroll
        for (int j = 0; j < 8; j++) {
            __half2 t01{__float2half_rn(sc[j][0]), __float2half_rn(sc[j][1])};
            __half2 t23{__float2half_rn(sc[j][2]), __float2half_rn(sc[j][3])};
            ph[j][0] = *(uint32_t*)&t01; ph[j][1] = *(uint32_t*)&t23;
        }

        // PV: O += P@V, V frags via trans-ldmatrix from row-major [s][d] tile
#pragma unroll
        for (int kc = 0; kc < 4; kc++) {
            uint32_t pah[4] = {ph[2*kc][0], ph[2*kc][1], ph[2*kc+1][0], ph[2*kc+1][1]};
            uint32_t vf[4][4];
#pragma unroll
            for (int p = 0; p < 4; p++)
                ldsm4t(vf[p], S + 8192 +
                       swz((kc * 16 + aRowOff) * 128 + p * 32 + aKHalf));
#pragma unroll
            for (int j = 0; j < 8; j++)
                mma16816(oc[j], pah, &vf[j >> 1][(j & 1) * 2]);
        }
        __syncthreads();
        if (jt + 2 < ntiles) load_kv(jt + 2);
    }

    // Epilogue: normalize + split to [hi | lo] K2 fp16 layout
    float i0 = 1.f / l0, i1 = 1.f / l1;
    size_t rA = (size_t)(b * TT + trow0) * K2 + h * HDD;
    size_t rB = rA + (size_t)8 * K2;
#pragma unroll
    for (int j = 0; j < 8; j++) {
        int col = 8 * j + ((lane & 3) << 1);
        uint32_t hi2, lo2;
        split_pair(oc[j][0] * i0, oc[j][1] * i0, hi2, lo2, 1.f);
        *(uint32_t*)(Osplit + rA + col)        = hi2;
        *(uint32_t*)(Osplit + rA + col + 1024) = lo2;
        split_pair(oc[j][2] * i1, oc[j][3] * i1, hi2, lo2, 1.f);
        *(uint32_t*)(Osplit + rB + col)        = hi2;
        *(uint32_t*)(Osplit + rB + col + 1024) = lo2;
    }
}

// ---------------------------------------------------------------------------
extern "C" void kernel_launch(void* const* d_in, const int* in_sizes, int n_in,
                              void* d_out, int out_size) {
    const float* x  = (const float*)d_in[0];
    const float* Wq = (const float*)d_in[1];
    const float* Wk = (const float*)d_in[2];
    const float* Wv = (const float*)d_in[3];
    const float* Wo = (const float*)d_in[4];
    float* out = (float*)d_out;

    __half *xs, *ats, *w16, *wo16, *qp, *kp, *vp;
    cudaGetSymbolAddress((void**)&xs, g_xs);
    cudaGetSymbolAddress((void**)&ats, g_atts);
    cudaGetSymbolAddress((void**)&w16, g_w16);
    cudaGetSymbolAddress((void**)&wo16, g_wo16);
    cudaGetSymbolAddress((void**)&qp, g_qp);
    cudaGetSymbolAddress((void**)&kp, g_kp);
    cudaGetSymbolAddress((void**)&vp, g_vp);

    cudaFuncSetAttribute(gemm_hmma, cudaFuncAttributeMaxDynamicSharedMemorySize, GEMM_DYN);
    cudaFuncSetAttribute(attn_mma, cudaFuncAttributeMaxDynamicSharedMemorySize, ATT_DYN);

    // operand prep
    split2<<<MM, 256>>>(x, xs);
    dim3 wgrid(DDIM, 4);
    wconv4<<<wgrid, 256>>>(Wq, Wk, Wv, Wo, w16, wo16);

    // merged Q/K/V projection: one launch, N=3072, packed epilogues
    dim3 qkvgrid(3 * DDIM / 128, MM / 128);   // (24, 32) = 768 CTAs
    gemm_hmma<<<qkvgrid, 128, GEMM_DYN>>>(xs, w16, nullptr, 3);

    dim3 agrid(TT / 64, HH, BB);              // (32, 16, 2) = 1024 CTAs
    attn_mma<<<agrid, 128, ATT_DYN>>>(qp, kp, vp, ats);

    // Wo: 2-term fp16
    dim3 ogrid(DDIM / 128, MM / 128);         // (8, 32)
    gemm_hmma<<<ogrid, 128, GEMM_DYN>>>(ats, wo16, out, 0);
}

// round 13
// speedup vs baseline: 13.5063x; 1.0519x over previous
#include <cuda_runtime.h>
#include <cuda_fp16.h>
#include <cstdint>

// Problem constants
#define BB   2
#define TT   2048
#define DDIM 1024
#define HH   16
#define HDD  64
#define MM   (BB*TT)   // 4096 rows
#define K2   2048      // split-K: [hi | lo] activations, W plane reused
#define DKK  64        // attention Q/K/V dim (hi only)

// Scratch (__device__ globals; no allocations allowed)
__device__ __half g_xs[MM*K2];
__device__ __half g_atts[MM*K2];
__device__ __half g_w16[3*DDIM*DDIM];    // [Wq | Wk | Wv] fp16 planes
__device__ __half g_wo16[DDIM*DDIM];
__device__ __half g_qp[BB*HH*TT*DKK];
__device__ __half g_kp[BB*HH*TT*DKK];
__device__ __half g_vp[BB*HH*TT*DKK];

// ---------------------------------------------------------------------------
__device__ __forceinline__ uint32_t s2u(const void* p) {
    uint32_t a;
    asm("{ .reg .u64 t; cvta.to.shared.u64 t, %1; cvt.u32.u64 %0, t; }" : "=r"(a) : "l"(p));
    return a;
}
__device__ __forceinline__ uint32_t swz(uint32_t o) { return o ^ ((o >> 3) & 0x70); }
__device__ __forceinline__ void cp16(uint32_t dst, const void* src) {
    asm volatile("cp.async.cg.shared.global [%0], [%1], 16;" :: "r"(dst), "l"(src));
}
__device__ __forceinline__ void ldsm4(uint32_t* r, uint32_t addr) {
    asm volatile("ldmatrix.sync.aligned.m8n8.x4.shared.b16 {%0,%1,%2,%3}, [%4];"
                 : "=r"(r[0]), "=r"(r[1]), "=r"(r[2]), "=r"(r[3]) : "r"(addr));
}
__device__ __forceinline__ void ldsm4t(uint32_t* r, uint32_t addr) {
    asm volatile("ldmatrix.sync.aligned.m8n8.x4.trans.shared.b16 {%0,%1,%2,%3}, [%4];"
                 : "=r"(r[0]), "=r"(r[1]), "=r"(r[2]), "=r"(r[3]) : "r"(addr));
}
__device__ __forceinline__ void mma16816(float* c, const uint32_t* a, const uint32_t* b) {
    asm volatile("mma.sync.aligned.m16n8k16.row.col.f32.f16.f16.f32 "
                 "{%0,%1,%2,%3}, {%4,%5,%6,%7}, {%8,%9}, {%0,%1,%2,%3};"
                 : "+f"(c[0]), "+f"(c[1]), "+f"(c[2]), "+f"(c[3])
                 : "r"(a[0]), "r"(a[1]), "r"(a[2]), "r"(a[3]), "r"(b[0]), "r"(b[1]));
}
// split (v0,v1) into fp16 hi + lo packed as half2 words; optional exact pow2 scale
__device__ __forceinline__ void split_pair(float v0, float v1, uint32_t& hi2, uint32_t& lo2,
                                           float scale) {
    __half h0 = __float2half_rn(v0), h1 = __float2half_rn(v1);
    __half l0 = __float2half_rn(v0 - __half2float(h0));
    __half l1 = __float2half_rn(v1 - __half2float(h1));
    if (scale != 1.f) {
        h0 = __float2half_rn(__half2float(h0) * scale);
        h1 = __float2half_rn(__half2float(h1) * scale);
        l0 = __float2half_rn(__half2float(l0) * scale);
        l1 = __float2half_rn(__half2float(l1) * scale);
    }
    __half2 hp{h0, h1}, lp{l0, l1};
    hi2 = *(uint32_t*)&hp; lo2 = *(uint32_t*)&lp;
}

// ---------------------------------------------------------------------------
// split2: fp32 x [rows,1024] -> fp16 [rows,2048]  [hi | lo]
// ---------------------------------------------------------------------------
__global__ __launch_bounds__(256) void split2(const float* __restrict__ in,
                                              __half* __restrict__ out) {
    int idx = (blockIdx.x * 256 + threadIdx.x) * 4;
    int r = idx >> 10, c = idx & 1023;
    float4 v = *(const float4*)(in + idx);
    uint32_t h01, l01, h23, l23;
    split_pair(v.x, v.y, h01, l01, 1.f);
    split_pair(v.z, v.w, h23, l23, 1.f);
    size_t base = (size_t)r * K2 + c;
    *(uint32_t*)(out + base)            = h01;
    *(uint32_t*)(out + base + 2)        = h23;
    *(uint32_t*)(out + base + 1024)     = l01;
    *(uint32_t*)(out + base + 1024 + 2) = l23;
}

// wconv4: Wq/Wk/Wv -> merged fp16 buffer; Wo -> own plane. One launch.
__global__ __launch_bounds__(256) void wconv4(const float* __restrict__ w0,
                                              const float* __restrict__ w1,
                                              const float* __restrict__ w2,
                                              const float* __restrict__ w3,
                                              __half* __restrict__ wqkv,
                                              __half* __restrict__ wo) {
    const float* in; __half* out;
    switch (blockIdx.y) {
        case 0: in = w0; out = wqkv; break;
        case 1: in = w1; out = wqkv + DDIM*DDIM; break;
        case 2: in = w2; out = wqkv + 2*DDIM*DDIM; break;
        default: in = w3; out = wo; break;
    }
    int idx = (blockIdx.x * 256 + threadIdx.x) * 4;
    float4 v = *(const float4*)(in + idx);
    __half2 a{__float2half_rn(v.x), __float2half_rn(v.y)};
    __half2 b{__float2half_rn(v.z), __float2half_rn(v.w)};
    *(uint32_t*)(out + idx)     = *(uint32_t*)&a;
    *(uint32_t*)(out + idx + 2) = *(uint32_t*)&b;
}

// ---------------------------------------------------------------------------
// fp16 HMMA NT GEMM, 2-term split-K (A=[hi|lo], B plane reused c%16).
// CTA 128x128, 4 warps (2x2), warp tile 64x64, BK=64, 3-stage, 2 CTA/SM.
// mode 0: fp32 C out (width DDIM).
// mode 3: merged QKV — section n0>>10: 0 -> Q (x1/8), 1 -> K, 2 -> V; all single-plane.
// ---------------------------------------------------------------------------
#define BK      64
#define STAGES  3
#define NCHUNK  (K2 / BK)                 // 32
#define STG_A   (128 * 128)               // 16 KB
#define STG_B   (128 * 128)               // 16 KB
#define STG_SZ  (STG_A + STG_B)           // 32 KB
#define GEMM_DYN (STAGES * STG_SZ + 1024) // ~97 KB

__global__ __launch_bounds__(128, 2) void gemm_hmma(const __half* __restrict__ A,
                                                    const __half* __restrict__ B,
                                                    void* __restrict__ Cout, int mode) {
    extern __shared__ char dyn[];
    const int tid  = threadIdx.x;
    const int wid  = tid >> 5, lane = tid & 31;
    const int wm   = wid >> 1;
    const int wn   = wid & 1;
    const int m0   = blockIdx.y << 7;
    const int n0   = blockIdx.x << 7;

    const uint32_t sbase = (s2u(dyn) + 1023) & ~1023u;
    const int lrow = tid >> 3;
    const int ls16 = tid & 7;

    float acc[4][8][4];
#pragma unroll
    for (int mi = 0; mi < 4; mi++)
#pragma unroll
        for (int ni = 0; ni < 8; ni++)
#pragma unroll
            for (int j = 0; j < 4; j++) acc[mi][ni][j] = 0.f;

    const int sub  = lane >> 3;
    const int lr8  = lane & 7;
    const int aRowOff = ((sub & 1) << 3) + lr8;
    const int aKHalf  = (sub >> 1) << 4;
    const int bRowOff = ((sub >> 1) << 3) + lr8;
    const int bKHalf  = (sub & 1) << 4;

    auto load_chunk = [&](int c) {
        const int s_ = c % STAGES;
        const uint32_t sA_ = sbase + s_ * STG_SZ;
        const uint32_t sB_ = sA_ + STG_A;
        const int bc = (c & 15) * BK;     // W plane reuse: hi chunks 0-15, lo 16-31
#pragma unroll
        for (int it = 0; it < 8; it++) {
            int row = lrow + (it << 4);
            cp16(sA_ + swz(row * 128 + ls16 * 16),
                 A + (size_t)(m0 + row) * K2 + c * BK + ls16 * 8);
        }
#pragma unroll
        for (int it = 0; it < 8; it++) {
            int row = lrow + (it << 4);
            cp16(sB_ + swz(row * 128 + ls16 * 16),
                 B + (size_t)(n0 + row) * DDIM + bc + ls16 * 8);
        }
        asm volatile("cp.async.commit_group;" ::: "memory");
    };

    load_chunk(0);
    load_chunk(1);

    for (int i = 0; i < NCHUNK; i++) {
        if (i < NCHUNK - 1) asm volatile("cp.async.wait_group 1;" ::: "memory");
        else                asm volatile("cp.async.wait_group 0;" ::: "memory");
        __syncthreads();

        if (i + 2 < NCHUNK) load_chunk(i + 2);

        const int s = i % STAGES;
        const uint32_t sA = sbase + s * STG_SZ;
        const uint32_t sB = sA + STG_A;

#pragma unroll
        for (int kk = 0; kk < 4; kk++) {
            uint32_t af[4][4], bf[4][4];
#pragma unroll
            for (int mi = 0; mi < 4; mi++) {
                int row = wm * 64 + mi * 16 + aRowOff;
                ldsm4(af[mi], sA + swz(row * 128 + kk * 32 + aKHalf));
            }
#pragma unroll
            for (int p = 0; p < 4; p++) {
                int row = wn * 64 + p * 16 + bRowOff;
                ldsm4(bf[p], sB + swz(row * 128 + kk * 32 + bKHalf));
            }
#pragma unroll
            for (int mi = 0; mi < 4; mi++)
#pragma unroll
                for (int nj = 0; nj < 8; nj++)
                    mma16816(acc[mi][nj], af[mi], &bf[nj >> 1][(nj & 1) * 2]);
        }
    }

    const int lr = lane >> 2, lc = (lane & 3) << 1;
    if (mode == 0) {
        float* C = (float*)Cout;
#pragma unroll
        for (int mi = 0; mi < 4; mi++)
#pragma unroll
            for (int nj = 0; nj < 8; nj++) {
                int grow = m0 + wm * 64 + mi * 16 + lr;
                int gcol = n0 + wn * 64 + nj * 8 + lc;
                *(float2*)&C[(size_t)grow * DDIM + gcol] =
                    make_float2(acc[mi][nj][0], acc[mi][nj][1]);
                *(float2*)&C[(size_t)(grow + 8) * DDIM + gcol] =
                    make_float2(acc[mi][nj][2], acc[mi][nj][3]);
            }
    } else {
        const int sect = n0 >> 10;                // 0=Q, 1=K, 2=V
        const float sc = (sect == 0) ? 0.125f : 1.f;
        const int hh = ((n0 & 1023) >> 6) + wn;   // warp's 64-col slab == one head
        __half* P = (sect == 0) ? g_qp : (sect == 1) ? g_kp : g_vp;
#pragma unroll
        for (int mi = 0; mi < 4; mi++)
#pragma unroll
            for (int nj = 0; nj < 8; nj++) {
                int grow = m0 + wm * 64 + mi * 16 + lr;
                int d    = nj * 8 + lc;
#pragma unroll
                for (int half_ = 0; half_ < 2; half_++) {
                    int row = grow + half_ * 8;
                    int b = row >> 11, t = row & 2047;
                    uint32_t hi2, lo2;
                    split_pair(acc[mi][nj][half_ * 2], acc[mi][nj][half_ * 2 + 1], hi2, lo2, sc);
                    size_t base = ((size_t)(b * HH + hh) * TT + t) * DKK + d;
                    *(uint32_t*)(P + base) = hi2;
                }
            }
    }
}

// ---------------------------------------------------------------------------
// fp16 flash attention, software-pipelined:
//   QK(jt+1) issued BEFORE softmax(jt) (scores double-buffered in regs),
//   3-stage KV smem ring, Q/K/V single fp16 plane, V via trans-ldmatrix.
// 128 threads (4 warps x 16 q-rows = 64 q-rows/CTA), KV tile 64, 2 CTAs/SM.
// Heavy-first: qb = gridDim.x-1-blockIdx.x. Writes [hi|lo] K2 activation.
// ---------------------------------------------------------------------------
#define ATT_QSZ   8192                     // 64 x 128B (Q single plane)
#define ATT_STG   16384                    // K 8KB + V 8KB
#define ATT_DYN   (ATT_QSZ + 3*ATT_STG + 1024)   // ~58 KB

__global__ __launch_bounds__(128, 2) void attn_mma(const __half* __restrict__ Qp,
                                                   const __half* __restrict__ Kp,
                                                   const __half* __restrict__ Vp,
                                                   __half* __restrict__ Osplit) {
    extern __shared__ char dyn[];
    const int tid = threadIdx.x, wid = tid >> 5, lane = tid & 31;
    const int qb = (int)(gridDim.x - 1 - blockIdx.x);   // heavy-first
    const int h = blockIdx.y, b = blockIdx.z;
    const int q0 = qb << 6;
    const int ntiles = qb + 1;

    const uint32_t sb = (s2u(dyn) + 1023) & ~1023u;
    const uint32_t QS = sb;
    const uint32_t STG0 = sb + ATT_QSZ;

    const int sub = lane >> 3, lr8 = lane & 7;
    const int aRowOff = ((sub & 1) << 3) + lr8;   // also trans-ldsm row offset
    const int aKHalf  = (sub >> 1) << 4;          // also trans-ldsm col offset
    const int bRowOff = ((sub >> 1) << 3) + lr8;
    const int bKHalf  = (sub & 1) << 4;

    const size_t bh = (size_t)(b * HH + h);
    const __half* Qg = Qp + (bh * TT + q0) * DKK;
    const __half* Kg = Kp + bh * TT * DKK;
    const __half* Vg = Vp + bh * TT * DKK;

    auto stg = [&](int jt) { return STG0 + (uint32_t)(jt % 3) * ATT_STG; };

    // Q tile: 64 rows x 64 halfs = 512 cp16 / 128 threads = 4 iters
#pragma unroll
    for (int it = 0; it < 4; it++) {
        int idx = tid + it * 128;
        int row = idx >> 3, seg = idx & 7;
        cp16(QS + swz(row * 128 + seg * 16), Qg + (size_t)row * DKK + seg * 8);
    }
    asm volatile("cp.async.commit_group;" ::: "memory");

    auto load_kv = [&](int jt) {
        const uint32_t S = stg(jt);
        const int kv0 = jt << 6;
#pragma unroll
        for (int it = 0; it < 4; it++) {       // K [s][d] 64x128B
            int idx = tid + it * 128;
            int row = idx >> 3, seg = idx & 7;
            cp16(S + swz(row * 128 + seg * 16),
                 Kg + (size_t)(kv0 + row) * DKK + seg * 8);
        }
#pragma unroll
        for (int it = 0; it < 4; it++) {       // V [s][d] 64x128B
            int idx = tid + it * 128;
            int row = idx >> 3, seg = idx & 7;
            cp16(S + 8192 + swz(row * 128 + seg * 16),
                 Vg + (size_t)(kv0 + row) * DKK + seg * 8);
        }
        asm volatile("cp.async.commit_group;" ::: "memory");
    };
    load_kv(0);
    if (ntiles > 1) load_kv(1);
    if (ntiles > 2) load_kv(2);

    // Wait for Q + kv0 (leave later kv groups pending; conditional on commits)
    if (ntiles > 2)      asm volatile("cp.async.wait_group 2;" ::: "memory");
    else if (ntiles > 1) asm volatile("cp.async.wait_group 1;" ::: "memory");
    else                 asm volatile("cp.async.wait_group 0;" ::: "memory");
    __syncthreads();

    uint32_t qa[4][4];
#pragma unroll
    for (int kk = 0; kk < 4; kk++) {
        int row = wid * 16 + aRowOff;
        ldsm4(qa[kk], QS + swz(row * 128 + kk * 32 + aKHalf));
    }

    float oc[8][4];
#pragma unroll
    for (int j = 0; j < 8; j++)
#pragma unroll
        for (int e = 0; e < 4; e++) oc[j][e] = 0.f;
    float m0 = -1e30f, m1 = -1e30f, l0 = 0.f, l1 = 0.f;

    const int trow0 = q0 + wid * 16 + (lane >> 2);

    auto compute_qk = [&](float (&sc)[8][4], int jt) {
        const uint32_t S = stg(jt);
#pragma unroll
        for (int j = 0; j < 8; j++)
#pragma unroll
            for (int e = 0; e < 4; e++) sc[j][e] = 0.f;
#pragma unroll
        for (int kk = 0; kk < 4; kk++) {
            uint32_t kf[4][4];
#pragma unroll
            for (int p = 0; p < 4; p++)
                ldsm4(kf[p], S + swz((p * 16 + bRowOff) * 128 + kk * 32 + bKHalf));
#pragma unroll
            for (int j = 0; j < 8; j++)
                mma16816(sc[j], qa[kk], &kf[j >> 1][(j & 1) * 2]);
        }
    };

    auto process = [&](float (&scCur)[8][4], float (&scNext)[8][4], int jt) {
        // Pipeline: issue next tile's QK before this tile's softmax.
        if (jt + 1 < ntiles) {
            if (jt + 2 < ntiles) asm volatile("cp.async.wait_group 1;" ::: "memory");
            else                 asm volatile("cp.async.wait_group 0;" ::: "memory");
            __syncthreads();               // kv(jt+1) visibility across warps
            compute_qk(scNext, jt + 1);
        }

        if (jt == ntiles - 1) {            // diagonal tile: causal mask
            int s0c = jt << 6;
#pragma unroll
            for (int j = 0; j < 8; j++) {
                int scol = s0c + 8 * j + ((lane & 3) << 1);
                if (scol     > trow0)     scCur[j][0] = -1e30f;
                if (scol + 1 > trow0)     scCur[j][1] = -1e30f;
                if (scol     > trow0 + 8) scCur[j][2] = -1e30f;
                if (scol + 1 > trow0 + 8) scCur[j][3] = -1e30f;
            }
        }

        // online softmax (overlaps with scNext HMMAs in flight)
        float r0 = -1e30f, r1 = -1e30f;
#pragma unroll
        for (int j = 0; j < 8; j++) {
            r0 = fmaxf(r0, fmaxf(scCur[j][0], scCur[j][1]));
            r1 = fmaxf(r1, fmaxf(scCur[j][2], scCur[j][3]));
        }
        r0 = fmaxf(r0, __shfl_xor_sync(0xffffffffu, r0, 1));
        r0 = fmaxf(r0, __shfl_xor_sync(0xffffffffu, r0, 2));
        r1 = fmaxf(r1, __shfl_xor_sync(0xffffffffu, r1, 1));
        r1 = fmaxf(r1, __shfl_xor_sync(0xffffffffu, r1, 2));
        float mn0 = fmaxf(m0, r0), mn1 = fmaxf(m1, r1);
        float a0 = __expf(m0 - mn0), a1 = __expf(m1 - mn1);
        float s0 = 0.f, s1 = 0.f;
#pragma unroll
        for (int j = 0; j < 8; j++) {
            scCur[j][0] = __expf(scCur[j][0] - mn0); scCur[j][1] = __expf(scCur[j][1] - mn0);
            scCur[j][2] = __expf(scCur[j][2] - mn1); scCur[j][3] = __expf(scCur[j][3] - mn1);
            s0 += scCur[j][0] + scCur[j][1];         s1 += scCur[j][2] + scCur[j][3];
        }
        s0 += __shfl_xor_sync(0xffffffffu, s0, 1);
        s0 += __shfl_xor_sync(0xffffffffu, s0, 2);
        s1 += __shfl_xor_sync(0xffffffffu, s1, 1);
        s1 += __shfl_xor_sync(0xffffffffu, s1, 2);
        l0 = l0 * a0 + s0; l1 = l1 * a1 + s1; m0 = mn0; m1 = mn1;
#pragma unroll
        for (int j = 0; j < 8; j++) {
            oc[j][0] *= a0; oc[j][1] *= a0; oc[j][2] *= a1; oc[j][3] *= a1;
        }

        // single fp16 P (C-frag -> A-frag packing, register-only)
        uint32_t ph[8][2];
#pragma unroll
        for (int j = 0; j < 8; j++) {
            __half2 t01{__float2half_rn(scCur[j][0]), __float2half_rn(scCur[j][1])};
            __half2 t23{__float2half_rn(scCur[j][2]), __float2half_rn(scCur[j][3])};
            ph[j][0] = *(uint32_t*)&t01; ph[j][1] = *(uint32_t*)&t23;
        }

        // PV from stage jt (V via trans-ldmatrix)
        const uint32_t S = stg(jt);
#pragma unroll
        for (int kc = 0; kc < 4; kc++) {
            uint32_t pah[4] = {ph[2*kc][0], ph[2*kc][1], ph[2*kc+1][0], ph[2*kc+1][1]};
            uint32_t vf[4][4];
#pragma unroll
            for (int p = 0; p < 4; p++)
                ldsm4t(vf[p], S + 8192 +
                       swz((kc * 16 + aRowOff) * 128 + p * 32 + aKHalf));
#pragma unroll
            for (int j = 0; j < 8; j++)
                mma16816(oc[j], pah, &vf[j >> 1][(j & 1) * 2]);
        }
        __syncthreads();                   // all warps done with stage jt%3
        if (jt + 3 < ntiles) load_kv(jt + 3);
    };

    float scA[8][4], scB[8][4];
    compute_qk(scA, 0);
    for (int jt = 0; jt < ntiles; jt += 2) {
        process(scA, scB, jt);
        if (jt + 1 < ntiles) process(scB, scA, jt + 1);
    }

    // Epilogue: normalize + split to [hi | lo] K2 fp16 layout
    float i0 = 1.f / l0, i1 = 1.f / l1;
    size_t rA = (size_t)(b * TT + trow0) * K2 + h * HDD;
    size_t rB = rA + (size_t)8 * K2;
#pragma unroll
    for (int j = 0; j < 8; j++) {
        int col = 8 * j + ((lane & 3) << 1);
        uint32_t hi2, lo2;
        split_pair(oc[j][0] * i0, oc[j][1] * i0, hi2, lo2, 1.f);
        *(uint32_t*)(Osplit + rA + col)        = hi2;
        *(uint32_t*)(Osplit + rA + col + 1024) = lo2;
        split_pair(oc[j][2] * i1, oc[j][3] * i1, hi2, lo2, 1.f);
        *(uint32_t*)(Osplit + rB + col)        = hi2;
        *(uint32_t*)(Osplit + rB + col + 1024) = lo2;
    }
}

// ---------------------------------------------------------------------------
extern "C" void kernel_launch(void* const* d_in, const int* in_sizes, int n_in,
                              void* d_out, int out_size) {
    const float* x  = (const float*)d_in[0];
    const float* Wq = (const float*)d_in[1];
    const float* Wk = (const float*)d_in[2];
    const float* Wv = (const float*)d_in[3];
    const float* Wo = (const float*)d_in[4];
    float* out = (float*)d_out;

    __half *xs, *ats, *w16, *wo16, *qp, *kp, *vp;
    cudaGetSymbolAddress((void**)&xs, g_xs);
    cudaGetSymbolAddress((void**)&ats, g_atts);
    cudaGetSymbolAddress((void**)&w16, g_w16);
    cudaGetSymbolAddress((void**)&wo16, g_wo16);
    cudaGetSymbolAddress((void**)&qp, g_qp);
    cudaGetSymbolAddress((void**)&kp, g_kp);
    cudaGetSymbolAddress((void**)&vp, g_vp);

    cudaFuncSetAttribute(gemm_hmma, cudaFuncAttributeMaxDynamicSharedMemorySize, GEMM_DYN);
    cudaFuncSetAttribute(attn_mma, cudaFuncAttributeMaxDynamicSharedMemorySize, ATT_DYN);

    // operand prep
    split2<<<MM, 256>>>(x, xs);
    dim3 wgrid(DDIM, 4);
    wconv4<<<wgrid, 256>>>(Wq, Wk, Wv, Wo, w16, wo16);

    // merged Q/K/V projection: one launch, N=3072, packed epilogues
    dim3 qkvgrid(3 * DDIM / 128, MM / 128);   // (24, 32) = 768 CTAs
    gemm_hmma<<<qkvgrid, 128, GEMM_DYN>>>(xs, w16, nullptr, 3);

    dim3 agrid(TT / 64, HH, BB);              // (32, 16, 2) = 1024 CTAs
    attn_mma<<<agrid, 128, ATT_DYN>>>(qp, kp, vp, ats);

    // Wo: 2-term fp16
    dim3 ogrid(DDIM / 128, MM / 128);         // (8, 32)
    gemm_hmma<<<ogrid, 128, GEMM_DYN>>>(ats, wo16, out, 0);
}

// round 14
// speedup vs baseline: 15.7905x; 1.1691x over previous
#include <cuda_runtime.h>
#include <cuda_fp16.h>
#include <cstdint>

// Problem constants
#define BB   2
#define TT   2048
#define DDIM 1024
#define HH   16
#define HDD  64
#define MM   (BB*TT)   // 4096 rows
#define K2   2048      // split-K: [hi | lo] activations, W plane reused
#define DKK  64        // attention Q/K/V dim (hi only)

// Scratch (__device__ globals; no allocations allowed)
__device__ __half g_xs[MM*K2];
__device__ __half g_atts[MM*K2];
__device__ __half g_w16[3*DDIM*DDIM];    // [Wq | Wk | Wv] fp16 planes
__device__ __half g_wo16[DDIM*DDIM];
__device__ __half g_qp[BB*HH*TT*DKK];
__device__ __half g_kp[BB*HH*TT*DKK];
__device__ __half g_vp[BB*HH*TT*DKK];

// ---------------------------------------------------------------------------
__device__ __forceinline__ uint32_t s2u(const void* p) {
    uint32_t a;
    asm("{ .reg .u64 t; cvta.to.shared.u64 t, %1; cvt.u32.u64 %0, t; }" : "=r"(a) : "l"(p));
    return a;
}
__device__ __forceinline__ uint32_t swz(uint32_t o) { return o ^ ((o >> 3) & 0x70); }
__device__ __forceinline__ void cp16(uint32_t dst, const void* src) {
    asm volatile("cp.async.cg.shared.global [%0], [%1], 16;" :: "r"(dst), "l"(src));
}
__device__ __forceinline__ void ldsm4(uint32_t* r, uint32_t addr) {
    asm volatile("ldmatrix.sync.aligned.m8n8.x4.shared.b16 {%0,%1,%2,%3}, [%4];"
                 : "=r"(r[0]), "=r"(r[1]), "=r"(r[2]), "=r"(r[3]) : "r"(addr));
}
__device__ __forceinline__ void ldsm4t(uint32_t* r, uint32_t addr) {
    asm volatile("ldmatrix.sync.aligned.m8n8.x4.trans.shared.b16 {%0,%1,%2,%3}, [%4];"
                 : "=r"(r[0]), "=r"(r[1]), "=r"(r[2]), "=r"(r[3]) : "r"(addr));
}
__device__ __forceinline__ void mma16816(float* c, const uint32_t* a, const uint32_t* b) {
    asm volatile("mma.sync.aligned.m16n8k16.row.col.f32.f16.f16.f32 "
                 "{%0,%1,%2,%3}, {%4,%5,%6,%7}, {%8,%9}, {%0,%1,%2,%3};"
                 : "+f"(c[0]), "+f"(c[1]), "+f"(c[2]), "+f"(c[3])
                 : "r"(a[0]), "r"(a[1]), "r"(a[2]), "r"(a[3]), "r"(b[0]), "r"(b[1]));
}
__device__ __forceinline__ float ex2(float x) {
    float y; asm("ex2.approx.f32 %0, %1;" : "=f"(y) : "f"(x)); return y;
}
// split (v0,v1) into fp16 hi + lo packed as half2 words; optional scale
__device__ __forceinline__ void split_pair(float v0, float v1, uint32_t& hi2, uint32_t& lo2,
                                           float scale) {
    __half h0 = __float2half_rn(v0), h1 = __float2half_rn(v1);
    __half l0 = __float2half_rn(v0 - __half2float(h0));
    __half l1 = __float2half_rn(v1 - __half2float(h1));
    if (scale != 1.f) {
        h0 = __float2half_rn(__half2float(h0) * scale);
        h1 = __float2half_rn(__half2float(h1) * scale);
        l0 = __float2half_rn(__half2float(l0) * scale);
        l1 = __float2half_rn(__half2float(l1) * scale);
    }
    __half2 hp{h0, h1}, lp{l0, l1};
    hi2 = *(uint32_t*)&hp; lo2 = *(uint32_t*)&lp;
}

// ---------------------------------------------------------------------------
// split2: fp32 x [rows,1024] -> fp16 [rows,2048]  [hi | lo]
// ---------------------------------------------------------------------------
__global__ __launch_bounds__(256) void split2(const float* __restrict__ in,
                                              __half* __restrict__ out) {
    int idx = (blockIdx.x * 256 + threadIdx.x) * 4;
    int r = idx >> 10, c = idx & 1023;
    float4 v = *(const float4*)(in + idx);
    uint32_t h01, l01, h23, l23;
    split_pair(v.x, v.y, h01, l01, 1.f);
    split_pair(v.z, v.w, h23, l23, 1.f);
    size_t base = (size_t)r * K2 + c;
    *(uint32_t*)(out + base)            = h01;
    *(uint32_t*)(out + base + 2)        = h23;
    *(uint32_t*)(out + base + 1024)     = l01;
    *(uint32_t*)(out + base + 1024 + 2) = l23;
}

// wconv4: Wq/Wk/Wv -> merged fp16 buffer; Wo -> own plane. One launch.
__global__ __launch_bounds__(256) void wconv4(const float* __restrict__ w0,
                                              const float* __restrict__ w1,
                                              const float* __restrict__ w2,
                                              const float* __restrict__ w3,
                                              __half* __restrict__ wqkv,
                                              __half* __restrict__ wo) {
    const float* in; __half* out;
    switch (blockIdx.y) {
        case 0: in = w0; out = wqkv; break;
        case 1: in = w1; out = wqkv + DDIM*DDIM; break;
        case 2: in = w2; out = wqkv + 2*DDIM*DDIM; break;
        default: in = w3; out = wo; break;
    }
    int idx = (blockIdx.x * 256 + threadIdx.x) * 4;
    float4 v = *(const float4*)(in + idx);
    __half2 a{__float2half_rn(v.x), __float2half_rn(v.y)};
    __half2 b{__float2half_rn(v.z), __float2half_rn(v.w)};
    *(uint32_t*)(out + idx)     = *(uint32_t*)&a;
    *(uint32_t*)(out + idx + 2) = *(uint32_t*)&b;
}

// ---------------------------------------------------------------------------
// fp16 HMMA NT GEMM, split-K (A=[hi|lo], B plane reused c%16).
// CTA 128x128, 4 warps (2x2), warp tile 64x64, BK=64, 3-stage, 2 CTA/SM.
// mode 0: fp32 C out (2-term, 32 chunks).
// mode 3: merged QKV — sect 0 (Q): 2-term + x(0.125*log2e) pack;
//                      sect 1/2 (K/V): hi-only (16 chunks), unit pack.
// ---------------------------------------------------------------------------
#define BK      64
#define STAGES  3
#define STG_A   (128 * 128)               // 16 KB
#define STG_B   (128 * 128)               // 16 KB
#define STG_SZ  (STG_A + STG_B)           // 32 KB
#define GEMM_DYN (STAGES * STG_SZ + 1024) // ~97 KB
#define QSCALE  0.180336880111f           // 0.125 * log2(e)

__global__ __launch_bounds__(128, 2) void gemm_hmma(const __half* __restrict__ A,
                                                    const __half* __restrict__ B,
                                                    void* __restrict__ Cout, int mode) {
    extern __shared__ char dyn[];
    const int tid  = threadIdx.x;
    const int wid  = tid >> 5, lane = tid & 31;
    const int wm   = wid >> 1;
    const int wn   = wid & 1;
    const int m0   = blockIdx.y << 7;
    const int n0   = blockIdx.x << 7;

    const int sect = (mode == 3) ? (n0 >> 10) : -1;   // 0=Q,1=K,2=V
    const int nchunk = (mode == 3 && sect != 0) ? 16 : 32;

    const uint32_t sbase = (s2u(dyn) + 1023) & ~1023u;
    const int lrow = tid >> 3;
    const int ls16 = tid & 7;

    float acc[4][8][4];
#pragma unroll
    for (int mi = 0; mi < 4; mi++)
#pragma unroll
        for (int ni = 0; ni < 8; ni++)
#pragma unroll
            for (int j = 0; j < 4; j++) acc[mi][ni][j] = 0.f;

    const int sub  = lane >> 3;
    const int lr8  = lane & 7;
    const int aRowOff = ((sub & 1) << 3) + lr8;
    const int aKHalf  = (sub >> 1) << 4;
    const int bRowOff = ((sub >> 1) << 3) + lr8;
    const int bKHalf  = (sub & 1) << 4;

    auto load_chunk = [&](int c) {
        const int s_ = c % STAGES;
        const uint32_t sA_ = sbase + s_ * STG_SZ;
        const uint32_t sB_ = sA_ + STG_A;
        const int bc = (c & 15) * BK;     // W plane reuse: hi chunks 0-15, lo 16-31
#pragma unroll
        for (int it = 0; it < 8; it++) {
            int row = lrow + (it << 4);
            cp16(sA_ + swz(row * 128 + ls16 * 16),
                 A + (size_t)(m0 + row) * K2 + c * BK + ls16 * 8);
        }
#pragma unroll
        for (int it = 0; it < 8; it++) {
            int row = lrow + (it << 4);
            cp16(sB_ + swz(row * 128 + ls16 * 16),
                 B + (size_t)(n0 + row) * DDIM + bc + ls16 * 8);
        }
        asm volatile("cp.async.commit_group;" ::: "memory");
    };

    load_chunk(0);
    load_chunk(1);

    for (int i = 0; i < nchunk; i++) {
        if (i < nchunk - 1) asm volatile("cp.async.wait_group 1;" ::: "memory");
        else                asm volatile("cp.async.wait_group 0;" ::: "memory");
        __syncthreads();

        if (i + 2 < nchunk) load_chunk(i + 2);

        const int s = i % STAGES;
        const uint32_t sA = sbase + s * STG_SZ;
        const uint32_t sB = sA + STG_A;

#pragma unroll
        for (int kk = 0; kk < 4; kk++) {
            uint32_t af[4][4], bf[4][4];
#pragma unroll
            for (int mi = 0; mi < 4; mi++) {
                int row = wm * 64 + mi * 16 + aRowOff;
                ldsm4(af[mi], sA + swz(row * 128 + kk * 32 + aKHalf));
            }
#pragma unroll
            for (int p = 0; p < 4; p++) {
                int row = wn * 64 + p * 16 + bRowOff;
                ldsm4(bf[p], sB + swz(row * 128 + kk * 32 + bKHalf));
            }
#pragma unroll
            for (int mi = 0; mi < 4; mi++)
#pragma unroll
                for (int nj = 0; nj < 8; nj++)
                    mma16816(acc[mi][nj], af[mi], &bf[nj >> 1][(nj & 1) * 2]);
        }
    }

    const int lr = lane >> 2, lc = (lane & 3) << 1;
    if (mode == 0) {
        float* C = (float*)Cout;
#pragma unroll
        for (int mi = 0; mi < 4; mi++)
#pragma unroll
            for (int nj = 0; nj < 8; nj++) {
                int grow = m0 + wm * 64 + mi * 16 + lr;
                int gcol = n0 + wn * 64 + nj * 8 + lc;
                *(float2*)&C[(size_t)grow * DDIM + gcol] =
                    make_float2(acc[mi][nj][0], acc[mi][nj][1]);
                *(float2*)&C[(size_t)(grow + 8) * DDIM + gcol] =
                    make_float2(acc[mi][nj][2], acc[mi][nj][3]);
            }
    } else {
        const float sc = (sect == 0) ? QSCALE : 1.f;
        const int hh = ((n0 & 1023) >> 6) + wn;   // warp's 64-col slab == one head
        __half* P = (sect == 0) ? g_qp : (sect == 1) ? g_kp : g_vp;
#pragma unroll
        for (int mi = 0; mi < 4; mi++)
#pragma unroll
            for (int nj = 0; nj < 8; nj++) {
                int grow = m0 + wm * 64 + mi * 16 + lr;
                int d    = nj * 8 + lc;
#pragma unroll
                for (int half_ = 0; half_ < 2; half_++) {
                    int row = grow + half_ * 8;
                    int b = row >> 11, t = row & 2047;
                    float v0 = acc[mi][nj][half_ * 2] * sc;
                    float v1 = acc[mi][nj][half_ * 2 + 1] * sc;
                    __half2 hp{__float2half_rn(v0), __float2half_rn(v1)};
                    size_t base = ((size_t)(b * HH + hh) * TT + t) * DKK + d;
                    *(uint32_t*)(P + base) = *(uint32_t*)&hp;
                }
            }
    }
}

// ---------------------------------------------------------------------------
// fp16 flash attention, KV tile 128 (amortized softmax fixed costs).
// Q/K/V single fp16 plane; scores in log2 domain (Q pre-scaled by
// 0.125*log2e) -> ex2.approx softmax. V via trans-ldmatrix.
// 128 threads (4 warps x 16 q-rows = 64 q-rows/CTA), 2-stage KV, 2 CTAs/SM.
// Heavy-first: qb = gridDim.x-1-blockIdx.x. Writes [hi|lo] K2 activation.
// ---------------------------------------------------------------------------
#define ATT_QSZ   8192                     // 64 x 128B (Q single plane)
#define ATT_STG   32768                    // K 16KB + V 16KB (128 kv rows)
#define ATT_DYN   (ATT_QSZ + 2*ATT_STG + 1024)   // ~74 KB

__global__ __launch_bounds__(128, 2) void attn_mma(const __half* __restrict__ Qp,
                                                   const __half* __restrict__ Kp,
                                                   const __half* __restrict__ Vp,
                                                   __half* __restrict__ Osplit) {
    extern __shared__ char dyn[];
    const int tid = threadIdx.x, wid = tid >> 5, lane = tid & 31;
    const int qb = (int)(gridDim.x - 1 - blockIdx.x);   // heavy-first
    const int h = blockIdx.y, b = blockIdx.z;
    const int q0 = qb << 6;
    const int JT = (qb >> 1) + 1;          // 128-wide kv tiles

    const uint32_t sb = (s2u(dyn) + 1023) & ~1023u;
    const uint32_t QS = sb;
    const uint32_t ST0 = sb + ATT_QSZ;
    const uint32_t ST1 = ST0 + ATT_STG;

    const int sub = lane >> 3, lr8 = lane & 7;
    const int aRowOff = ((sub & 1) << 3) + lr8;   // also trans-ldsm row offset
    const int aKHalf  = (sub >> 1) << 4;          // also trans-ldsm col offset
    const int bRowOff = ((sub >> 1) << 3) + lr8;
    const int bKHalf  = (sub & 1) << 4;

    const size_t bh = (size_t)(b * HH + h);
    const __half* Qg = Qp + (bh * TT + q0) * DKK;
    const __half* Kg = Kp + bh * TT * DKK;
    const __half* Vg = Vp + bh * TT * DKK;

    // Q tile: 64 rows x 64 halfs = 512 cp16 / 128 threads = 4 iters
#pragma unroll
    for (int it = 0; it < 4; it++) {
        int idx = tid + it * 128;
        int row = idx >> 3, seg = idx & 7;
        cp16(QS + swz(row * 128 + seg * 16), Qg + (size_t)row * DKK + seg * 8);
    }
    asm volatile("cp.async.commit_group;" ::: "memory");

    auto load_kv = [&](int jt) {
        const uint32_t S = (jt & 1) ? ST1 : ST0;
        const int kv0 = jt << 7;
#pragma unroll
        for (int it = 0; it < 8; it++) {       // K [s][d] 128x128B
            int idx = tid + it * 128;
            int row = idx >> 3, seg = idx & 7;
            cp16(S + swz(row * 128 + seg * 16),
                 Kg + (size_t)(kv0 + row) * DKK + seg * 8);
        }
#pragma unroll
        for (int it = 0; it < 8; it++) {       // V [s][d] 128x128B
            int idx = tid + it * 128;
            int row = idx >> 3, seg = idx & 7;
            cp16(S + 16384 + swz(row * 128 + seg * 16),
                 Vg + (size_t)(kv0 + row) * DKK + seg * 8);
        }
        asm volatile("cp.async.commit_group;" ::: "memory");
    };
    load_kv(0);
    if (JT > 1) load_kv(1);

    // Q (+kv0) complete before ldsm; conditional on committed group count
    if (JT > 1) asm volatile("cp.async.wait_group 1;" ::: "memory");
    else        asm volatile("cp.async.wait_group 0;" ::: "memory");
    __syncthreads();

    uint32_t qa[4][4];
#pragma unroll
    for (int kk = 0; kk < 4; kk++) {
        int row = wid * 16 + aRowOff;
        ldsm4(qa[kk], QS + swz(row * 128 + kk * 32 + aKHalf));
    }

    float oc[8][4];
#pragma unroll
    for (int j = 0; j < 8; j++)
#pragma unroll
        for (int e = 0; e < 4; e++) oc[j][e] = 0.f;
    float m0 = -1e30f, m1 = -1e30f, l0 = 0.f, l1 = 0.f;

    const int trow0 = q0 + wid * 16 + (lane >> 2);

    for (int jt = 0; jt < JT; jt++) {
        if (jt + 1 < JT) asm volatile("cp.async.wait_group 1;" ::: "memory");
        else             asm volatile("cp.async.wait_group 0;" ::: "memory");
        __syncthreads();
        const uint32_t S = (jt & 1) ? ST1 : ST0;

        // scores: 16 j-frags x 128 kv cols, log2 domain
        float sc[16][4];
#pragma unroll
        for (int j = 0; j < 16; j++)
#pragma unroll
            for (int e = 0; e < 4; e++) sc[j][e] = 0.f;
#pragma unroll
        for (int kk = 0; kk < 4; kk++) {
            uint32_t kf[8][4];
#pragma unroll
            for (int p = 0; p < 8; p++)
                ldsm4(kf[p], S + swz((p * 16 + bRowOff) * 128 + kk * 32 + bKHalf));
#pragma unroll
            for (int j = 0; j < 16; j++)
                mma16816(sc[j], qa[kk], &kf[j >> 1][(j & 1) * 2]);
        }

        if (jt == JT - 1) {                // diagonal tile: causal mask
            int s0c = jt << 7;
#pragma unroll
            for (int j = 0; j < 16; j++) {
                int scol = s0c + 8 * j + ((lane & 3) << 1);
                if (scol     > trow0)     sc[j][0] = -1e30f;
                if (scol + 1 > trow0)     sc[j][1] = -1e30f;
                if (scol     > trow0 + 8) sc[j][2] = -1e30f;
                if (scol + 1 > trow0 + 8) sc[j][3] = -1e30f;
            }
        }

        // online softmax (base-2)
        float r0 = -1e30f, r1 = -1e30f;
#pragma unroll
        for (int j = 0; j < 16; j++) {
            r0 = fmaxf(r0, fmaxf(sc[j][0], sc[j][1]));
            r1 = fmaxf(r1, fmaxf(sc[j][2], sc[j][3]));
        }
        r0 = fmaxf(r0, __shfl_xor_sync(0xffffffffu, r0, 1));
        r0 = fmaxf(r0, __shfl_xor_sync(0xffffffffu, r0, 2));
        r1 = fmaxf(r1, __shfl_xor_sync(0xffffffffu, r1, 1));
        r1 = fmaxf(r1, __shfl_xor_sync(0xffffffffu, r1, 2));
        float mn0 = fmaxf(m0, r0), mn1 = fmaxf(m1, r1);
        float a0 = ex2(m0 - mn0), a1 = ex2(m1 - mn1);
        float s0 = 0.f, s1 = 0.f;
#pragma unroll
        for (int j = 0; j < 16; j++) {
            sc[j][0] = ex2(sc[j][0] - mn0); sc[j][1] = ex2(sc[j][1] - mn0);
            sc[j][2] = ex2(sc[j][2] - mn1); sc[j][3] = ex2(sc[j][3] - mn1);
            s0 += sc[j][0] + sc[j][1];      s1 += sc[j][2] + sc[j][3];
        }
        s0 += __shfl_xor_sync(0xffffffffu, s0, 1);
        s0 += __shfl_xor_sync(0xffffffffu, s0, 2);
        s1 += __shfl_xor_sync(0xffffffffu, s1, 1);
        s1 += __shfl_xor_sync(0xffffffffu, s1, 2);
        l0 = l0 * a0 + s0; l1 = l1 * a1 + s1; m0 = mn0; m1 = mn1;
#pragma unroll
        for (int j = 0; j < 8; j++) {
            oc[j][0] *= a0; oc[j][1] *= a0; oc[j][2] *= a1; oc[j][3] *= a1;
        }

        // PV: K-dim 128 = 8 k16 steps; P converted per-step (short live range)
#pragma unroll
        for (int kc = 0; kc < 8; kc++) {
            __half2 p01{__float2half_rn(sc[2*kc][0]),   __float2half_rn(sc[2*kc][1])};
            __half2 p23{__float2half_rn(sc[2*kc][2]),   __float2half_rn(sc[2*kc][3])};
            __half2 q01{__float2half_rn(sc[2*kc+1][0]), __float2half_rn(sc[2*kc+1][1])};
            __half2 q23{__float2half_rn(sc[2*kc+1][2]), __float2half_rn(sc[2*kc+1][3])};
            uint32_t pah[4] = {*(uint32_t*)&p01, *(uint32_t*)&p23,
                               *(uint32_t*)&q01, *(uint32_t*)&q23};
            uint32_t vf[4][4];
#pragma unroll
            for (int p = 0; p < 4; p++)
                ldsm4t(vf[p], S + 16384 +
                       swz((kc * 16 + aRowOff) * 128 + p * 32 + aKHalf));
#pragma unroll
            for (int j = 0; j < 8; j++)
                mma16816(oc[j], pah, &vf[j >> 1][(j & 1) * 2]);
        }
        __syncthreads();                   // all warps done with stage jt&1
        if (jt + 2 < JT) load_kv(jt + 2);
    }

    // Epilogue: normalize + split to [hi | lo] K2 fp16 layout
    float i0 = 1.f / l0, i1 = 1.f / l1;
    size_t rA = (size_t)(b * TT + trow0) * K2 + h * HDD;
    size_t rB = rA + (size_t)8 * K2;
#pragma unroll
    for (int j = 0; j < 8; j++) {
        int col = 8 * j + ((lane & 3) << 1);
        uint32_t hi2, lo2;
        split_pair(oc[j][0] * i0, oc[j][1] * i0, hi2, lo2, 1.f);
        *(uint32_t*)(Osplit + rA + col)        = hi2;
        *(uint32_t*)(Osplit + rA + col + 1024) = lo2;
        split_pair(oc[j][2] * i1, oc[j][3] * i1, hi2, lo2, 1.f);
        *(uint32_t*)(Osplit + rB + col)        = hi2;
        *(uint32_t*)(Osplit + rB + col + 1024) = lo2;
    }
}

// ---------------------------------------------------------------------------
extern "C" void kernel_launch(void* const* d_in, const int* in_sizes, int n_in,
                              void* d_out, int out_size) {
    const float* x  = (const float*)d_in[0];
    const float* Wq = (const float*)d_in[1];
    const float* Wk = (const float*)d_in[2];
    const float* Wv = (const float*)d_in[3];
    const float* Wo = (const float*)d_in[4];
    float* out = (float*)d_out;

    __half *xs, *ats, *w16, *wo16, *qp, *kp, *vp;
    cudaGetSymbolAddress((void**)&xs, g_xs);
    cudaGetSymbolAddress((void**)&ats, g_atts);
    cudaGetSymbolAddress((void**)&w16, g_w16);
    cudaGetSymbolAddress((void**)&wo16, g_wo16);
    cudaGetSymbolAddress((void**)&qp, g_qp);
    cudaGetSymbolAddress((void**)&kp, g_kp);
    cudaGetSymbolAddress((void**)&vp, g_vp);

    cudaFuncSetAttribute(gemm_hmma, cudaFuncAttributeMaxDynamicSharedMemorySize, GEMM_DYN);
    cudaFuncSetAttribute(attn_mma, cudaFuncAttributeMaxDynamicSharedMemorySize, ATT_DYN);

    // operand prep
    split2<<<MM, 256>>>(x, xs);
    dim3 wgrid(DDIM, 4);
    wconv4<<<wgrid, 256>>>(Wq, Wk, Wv, Wo, w16, wo16);

    // merged Q/K/V projection: one launch, N=3072; K/V sections hi-only
    dim3 qkvgrid(3 * DDIM / 128, MM / 128);   // (24, 32) = 768 CTAs
    gemm_hmma<<<qkvgrid, 128, GEMM_DYN>>>(xs, w16, nullptr, 3);

    dim3 agrid(TT / 64, HH, BB);              // (32, 16, 2) = 1024 CTAs
    attn_mma<<<agrid, 128, ATT_DYN>>>(qp, kp, vp, ats);

    // Wo: 2-term fp16
    dim3 ogrid(DDIM / 128, MM / 128);         // (8, 32)
    gemm_hmma<<<ogrid, 128, GEMM_DYN>>>(ats, wo16, out, 0);
}

// round 15
// speedup vs baseline: 20.5505x; 1.3014x over previous
#include <cuda_runtime.h>
#include <cuda_fp16.h>
#include <cstdint>

// Problem constants
#define BB   2
#define TT   2048
#define DDIM 1024
#define HH   16
#define HDD  64
#define MM   (BB*TT)   // 4096 rows
#define DKK  64        // attention Q/K/V dim

// Scratch (__device__ globals; no allocations allowed)
__device__ __half g_xh[MM*DDIM];
__device__ __half g_atts[MM*DDIM];
__device__ __half g_w16[3*DDIM*DDIM];    // [Wq | Wk | Wv] fp16 planes
__device__ __half g_wo16[DDIM*DDIM];
__device__ __half g_qp[BB*HH*TT*DKK];
__device__ __half g_kp[BB*HH*TT*DKK];
__device__ __half g_vp[BB*HH*TT*DKK];

// ---------------------------------------------------------------------------
__device__ __forceinline__ uint32_t s2u(const void* p) {
    uint32_t a;
    asm("{ .reg .u64 t; cvta.to.shared.u64 t, %1; cvt.u32.u64 %0, t; }" : "=r"(a) : "l"(p));
    return a;
}
__device__ __forceinline__ uint32_t swz(uint32_t o) { return o ^ ((o >> 3) & 0x70); }
__device__ __forceinline__ void cp16(uint32_t dst, const void* src) {
    asm volatile("cp.async.cg.shared.global [%0], [%1], 16;" :: "r"(dst), "l"(src));
}
__device__ __forceinline__ void ldsm4(uint32_t* r, uint32_t addr) {
    asm volatile("ldmatrix.sync.aligned.m8n8.x4.shared.b16 {%0,%1,%2,%3}, [%4];"
                 : "=r"(r[0]), "=r"(r[1]), "=r"(r[2]), "=r"(r[3]) : "r"(addr));
}
__device__ __forceinline__ void ldsm4t(uint32_t* r, uint32_t addr) {
    asm volatile("ldmatrix.sync.aligned.m8n8.x4.trans.shared.b16 {%0,%1,%2,%3}, [%4];"
                 : "=r"(r[0]), "=r"(r[1]), "=r"(r[2]), "=r"(r[3]) : "r"(addr));
}
__device__ __forceinline__ void mma16816(float* c, const uint32_t* a, const uint32_t* b) {
    asm volatile("mma.sync.aligned.m16n8k16.row.col.f32.f16.f16.f32 "
                 "{%0,%1,%2,%3}, {%4,%5,%6,%7}, {%8,%9}, {%0,%1,%2,%3};"
                 : "+f"(c[0]), "+f"(c[1]), "+f"(c[2]), "+f"(c[3])
                 : "r"(a[0]), "r"(a[1]), "r"(a[2]), "r"(a[3]), "r"(b[0]), "r"(b[1]));
}
__device__ __forceinline__ float ex2(float x) {
    float y; asm("ex2.approx.f32 %0, %1;" : "=f"(y) : "f"(x)); return y;
}

// ---------------------------------------------------------------------------
// xconv: fp32 x [4096,1024] -> fp16 single plane
// ---------------------------------------------------------------------------
__global__ __launch_bounds__(256) void xconv(const float* __restrict__ in,
                                             __half* __restrict__ out) {
    int idx = (blockIdx.x * 256 + threadIdx.x) * 4;
    float4 v = *(const float4*)(in + idx);
    __half2 a{__float2half_rn(v.x), __float2half_rn(v.y)};
    __half2 b{__float2half_rn(v.z), __float2half_rn(v.w)};
    *(uint32_t*)(out + idx)     = *(uint32_t*)&a;
    *(uint32_t*)(out + idx + 2) = *(uint32_t*)&b;
}

// wconv4: Wq/Wk/Wv -> merged fp16 buffer; Wo -> own plane. One launch.
__global__ __launch_bounds__(256) void wconv4(const float* __restrict__ w0,
                                              const float* __restrict__ w1,
                                              const float* __restrict__ w2,
                                              const float* __restrict__ w3,
                                              __half* __restrict__ wqkv,
                                              __half* __restrict__ wo) {
    const float* in; __half* out;
    switch (blockIdx.y) {
        case 0: in = w0; out = wqkv; break;
        case 1: in = w1; out = wqkv + DDIM*DDIM; break;
        case 2: in = w2; out = wqkv + 2*DDIM*DDIM; break;
        default: in = w3; out = wo; break;
    }
    int idx = (blockIdx.x * 256 + threadIdx.x) * 4;
    float4 v = *(const float4*)(in + idx);
    __half2 a{__float2half_rn(v.x), __float2half_rn(v.y)};
    __half2 b{__float2half_rn(v.z), __float2half_rn(v.w)};
    *(uint32_t*)(out + idx)     = *(uint32_t*)&a;
    *(uint32_t*)(out + idx + 2) = *(uint32_t*)&b;
}

// ---------------------------------------------------------------------------
// fp16 HMMA NT GEMM, K=1024 single plane (16 chunks).
// CTA 128x128, 4 warps (2x2), warp tile 64x64, BK=64, 3-stage, 2 CTA/SM.
// mode 0: fp32 C out.  mode 3: merged QKV — sect 0 Q (x 0.125*log2e), 1 K, 2 V.
// ---------------------------------------------------------------------------
#define BK      64
#define STAGES  3
#define NCHUNK  (DDIM / BK)               // 16
#define STG_A   (128 * 128)               // 16 KB
#define STG_B   (128 * 128)               // 16 KB
#define STG_SZ  (STG_A + STG_B)           // 32 KB
#define GEMM_DYN (STAGES * STG_SZ + 1024) // ~97 KB
#define QSCALE  0.180336880111f           // 0.125 * log2(e)

__global__ __launch_bounds__(128, 2) void gemm_hmma(const __half* __restrict__ A,
                                                    const __half* __restrict__ B,
                                                    void* __restrict__ Cout, int mode) {
    extern __shared__ char dyn[];
    const int tid  = threadIdx.x;
    const int wid  = tid >> 5, lane = tid & 31;
    const int wm   = wid >> 1;
    const int wn   = wid & 1;
    const int m0   = blockIdx.y << 7;
    const int n0   = blockIdx.x << 7;

    const uint32_t sbase = (s2u(dyn) + 1023) & ~1023u;
    const int lrow = tid >> 3;
    const int ls16 = tid & 7;

    float acc[4][8][4];
#pragma unroll
    for (int mi = 0; mi < 4; mi++)
#pragma unroll
        for (int ni = 0; ni < 8; ni++)
#pragma unroll
            for (int j = 0; j < 4; j++) acc[mi][ni][j] = 0.f;

    const int sub  = lane >> 3;
    const int lr8  = lane & 7;
    const int aRowOff = ((sub & 1) << 3) + lr8;
    const int aKHalf  = (sub >> 1) << 4;
    const int bRowOff = ((sub >> 1) << 3) + lr8;
    const int bKHalf  = (sub & 1) << 4;

    auto load_chunk = [&](int c) {
        const int s_ = c % STAGES;
        const uint32_t sA_ = sbase + s_ * STG_SZ;
        const uint32_t sB_ = sA_ + STG_A;
#pragma unroll
        for (int it = 0; it < 8; it++) {
            int row = lrow + (it << 4);
            cp16(sA_ + swz(row * 128 + ls16 * 16),
                 A + (size_t)(m0 + row) * DDIM + c * BK + ls16 * 8);
        }
#pragma unroll
        for (int it = 0; it < 8; it++) {
            int row = lrow + (it << 4);
            cp16(sB_ + swz(row * 128 + ls16 * 16),
                 B + (size_t)(n0 + row) * DDIM + c * BK + ls16 * 8);
        }
        asm volatile("cp.async.commit_group;" ::: "memory");
    };

    load_chunk(0);
    load_chunk(1);

    for (int i = 0; i < NCHUNK; i++) {
        if (i < NCHUNK - 1) asm volatile("cp.async.wait_group 1;" ::: "memory");
        else                asm volatile("cp.async.wait_group 0;" ::: "memory");
        __syncthreads();

        if (i + 2 < NCHUNK) load_chunk(i + 2);

        const int s = i % STAGES;
        const uint32_t sA = sbase + s * STG_SZ;
        const uint32_t sB = sA + STG_A;

#pragma unroll
        for (int kk = 0; kk < 4; kk++) {
            uint32_t af[4][4], bf[4][4];
#pragma unroll
            for (int mi = 0; mi < 4; mi++) {
                int row = wm * 64 + mi * 16 + aRowOff;
                ldsm4(af[mi], sA + swz(row * 128 + kk * 32 + aKHalf));
            }
#pragma unroll
            for (int p = 0; p < 4; p++) {
                int row = wn * 64 + p * 16 + bRowOff;
                ldsm4(bf[p], sB + swz(row * 128 + kk * 32 + bKHalf));
            }
#pragma unroll
            for (int mi = 0; mi < 4; mi++)
#pragma unroll
                for (int nj = 0; nj < 8; nj++)
                    mma16816(acc[mi][nj], af[mi], &bf[nj >> 1][(nj & 1) * 2]);
        }
    }

    const int lr = lane >> 2, lc = (lane & 3) << 1;
    if (mode == 0) {
        float* C = (float*)Cout;
#pragma unroll
        for (int mi = 0; mi < 4; mi++)
#pragma unroll
            for (int nj = 0; nj < 8; nj++) {
                int grow = m0 + wm * 64 + mi * 16 + lr;
                int gcol = n0 + wn * 64 + nj * 8 + lc;
                *(float2*)&C[(size_t)grow * DDIM + gcol] =
                    make_float2(acc[mi][nj][0], acc[mi][nj][1]);
                *(float2*)&C[(size_t)(grow + 8) * DDIM + gcol] =
                    make_float2(acc[mi][nj][2], acc[mi][nj][3]);
            }
    } else {
        const int sect = n0 >> 10;                // 0=Q, 1=K, 2=V
        const float sc = (sect == 0) ? QSCALE : 1.f;
        const int hh = ((n0 & 1023) >> 6) + wn;   // warp's 64-col slab == one head
        __half* P = (sect == 0) ? g_qp : (sect == 1) ? g_kp : g_vp;
#pragma unroll
        for (int mi = 0; mi < 4; mi++)
#pragma unroll
            for (int nj = 0; nj < 8; nj++) {
                int grow = m0 + wm * 64 + mi * 16 + lr;
                int d    = nj * 8 + lc;
#pragma unroll
                for (int half_ = 0; half_ < 2; half_++) {
                    int row = grow + half_ * 8;
                    int b = row >> 11, t = row & 2047;
                    float v0 = acc[mi][nj][half_ * 2] * sc;
                    float v1 = acc[mi][nj][half_ * 2 + 1] * sc;
                    __half2 hp{__float2half_rn(v0), __float2half_rn(v1)};
                    size_t base = ((size_t)(b * HH + hh) * TT + t) * DKK + d;
                    *(uint32_t*)(P + base) = *(uint32_t*)&hp;
                }
            }
    }
}

// ---------------------------------------------------------------------------
// fp16 flash attention, KV tile 128. Q/K/V single fp16 plane; log2-domain
// softmax (ex2.approx); V via trans-ldmatrix. Writes single-plane fp16 atts.
// 128 threads (4 warps x 16 q-rows = 64 q-rows/CTA), 2-stage KV, 2 CTAs/SM.
// Heavy-first: qb = gridDim.x-1-blockIdx.x.
// ---------------------------------------------------------------------------
#define ATT_QSZ   8192                     // 64 x 128B (Q single plane)
#define ATT_STG   32768                    // K 16KB + V 16KB (128 kv rows)
#define ATT_DYN   (ATT_QSZ + 2*ATT_STG + 1024)   // ~74 KB

__global__ __launch_bounds__(128, 2) void attn_mma(const __half* __restrict__ Qp,
                                                   const __half* __restrict__ Kp,
                                                   const __half* __restrict__ Vp,
                                                   __half* __restrict__ Oout) {
    extern __shared__ char dyn[];
    const int tid = threadIdx.x, wid = tid >> 5, lane = tid & 31;
    const int qb = (int)(gridDim.x - 1 - blockIdx.x);   // heavy-first
    const int h = blockIdx.y, b = blockIdx.z;
    const int q0 = qb << 6;
    const int JT = (qb >> 1) + 1;          // 128-wide kv tiles

    const uint32_t sb = (s2u(dyn) + 1023) & ~1023u;
    const uint32_t QS = sb;
    const uint32_t ST0 = sb + ATT_QSZ;
    const uint32_t ST1 = ST0 + ATT_STG;

    const int sub = lane >> 3, lr8 = lane & 7;
    const int aRowOff = ((sub & 1) << 3) + lr8;   // also trans-ldsm row offset
    const int aKHalf  = (sub >> 1) << 4;          // also trans-ldsm col offset
    const int bRowOff = ((sub >> 1) << 3) + lr8;
    const int bKHalf  = (sub & 1) << 4;

    const size_t bh = (size_t)(b * HH + h);
    const __half* Qg = Qp + (bh * TT + q0) * DKK;
    const __half* Kg = Kp + bh * TT * DKK;
    const __half* Vg = Vp + bh * TT * DKK;

    // Q tile: 64 rows x 64 halfs = 512 cp16 / 128 threads = 4 iters
#pragma unroll
    for (int it = 0; it < 4; it++) {
        int idx = tid + it * 128;
        int row = idx >> 3, seg = idx & 7;
        cp16(QS + swz(row * 128 + seg * 16), Qg + (size_t)row * DKK + seg * 8);
    }
    asm volatile("cp.async.commit_group;" ::: "memory");

    auto load_kv = [&](int jt) {
        const uint32_t S = (jt & 1) ? ST1 : ST0;
        const int kv0 = jt << 7;
#pragma unroll
        for (int it = 0; it < 8; it++) {       // K [s][d] 128x128B
            int idx = tid + it * 128;
            int row = idx >> 3, seg = idx & 7;
            cp16(S + swz(row * 128 + seg * 16),
                 Kg + (size_t)(kv0 + row) * DKK + seg * 8);
        }
#pragma unroll
        for (int it = 0; it < 8; it++) {       // V [s][d] 128x128B
            int idx = tid + it * 128;
            int row = idx >> 3, seg = idx & 7;
            cp16(S + 16384 + swz(row * 128 + seg * 16),
                 Vg + (size_t)(kv0 + row) * DKK + seg * 8);
        }
        asm volatile("cp.async.commit_group;" ::: "memory");
    };
    load_kv(0);
    if (JT > 1) load_kv(1);

    // Q (+kv0) complete before ldsm; conditional on committed group count
    if (JT > 1) asm volatile("cp.async.wait_group 1;" ::: "memory");
    else        asm volatile("cp.async.wait_group 0;" ::: "memory");
    __syncthreads();

    uint32_t qa[4][4];
#pragma unroll
    for (int kk = 0; kk < 4; kk++) {
        int row = wid * 16 + aRowOff;
        ldsm4(qa[kk], QS + swz(row * 128 + kk * 32 + aKHalf));
    }

    float oc[8][4];
#pragma unroll
    for (int j = 0; j < 8; j++)
#pragma unroll
        for (int e = 0; e < 4; e++) oc[j][e] = 0.f;
    float m0 = -1e30f, m1 = -1e30f, l0 = 0.f, l1 = 0.f;

    const int trow0 = q0 + wid * 16 + (lane >> 2);

    for (int jt = 0; jt < JT; jt++) {
        if (jt + 1 < JT) asm volatile("cp.async.wait_group 1;" ::: "memory");
        else             asm volatile("cp.async.wait_group 0;" ::: "memory");
        __syncthreads();
        const uint32_t S = (jt & 1) ? ST1 : ST0;

        // scores: 16 j-frags x 128 kv cols, log2 domain
        float sc[16][4];
#pragma unroll
        for (int j = 0; j < 16; j++)
#pragma unroll
            for (int e = 0; e < 4; e++) sc[j][e] = 0.f;
#pragma unroll
        for (int kk = 0; kk < 4; kk++) {
            uint32_t kf[8][4];
#pragma unroll
            for (int p = 0; p < 8; p++)
                ldsm4(kf[p], S + swz((p * 16 + bRowOff) * 128 + kk * 32 + bKHalf));
#pragma unroll
            for (int j = 0; j < 16; j++)
                mma16816(sc[j], qa[kk], &kf[j >> 1][(j & 1) * 2]);
        }

        if (jt == JT - 1) {                // diagonal tile: causal mask
            int s0c = jt << 7;
#pragma unroll
            for (int j = 0; j < 16; j++) {
                int scol = s0c + 8 * j + ((lane & 3) << 1);
                if (scol     > trow0)     sc[j][0] = -1e30f;
                if (scol + 1 > trow0)     sc[j][1] = -1e30f;
                if (scol     > trow0 + 8) sc[j][2] = -1e30f;
                if (scol + 1 > trow0 + 8) sc[j][3] = -1e30f;
            }
        }

        // online softmax (base-2)
        float r0 = -1e30f, r1 = -1e30f;
#pragma unroll
        for (int j = 0; j < 16; j++) {
            r0 = fmaxf(r0, fmaxf(sc[j][0], sc[j][1]));
            r1 = fmaxf(r1, fmaxf(sc[j][2], sc[j][3]));
        }
        r0 = fmaxf(r0, __shfl_xor_sync(0xffffffffu, r0, 1));
        r0 = fmaxf(r0, __shfl_xor_sync(0xffffffffu, r0, 2));
        r1 = fmaxf(r1, __shfl_xor_sync(0xffffffffu, r1, 1));
        r1 = fmaxf(r1, __shfl_xor_sync(0xffffffffu, r1, 2));
        float mn0 = fmaxf(m0, r0), mn1 = fmaxf(m1, r1);
        float a0 = ex2(m0 - mn0), a1 = ex2(m1 - mn1);
        float s0 = 0.f, s1 = 0.f;
#pragma unroll
        for (int j = 0; j < 16; j++) {
            sc[j][0] = ex2(sc[j][0] - mn0); sc[j][1] = ex2(sc[j][1] - mn0);
            sc[j][2] = ex2(sc[j][2] - mn1); sc[j][3] = ex2(sc[j][3] - mn1);
            s0 += sc[j][0] + sc[j][1];      s1 += sc[j][2] + sc[j][3];
        }
        s0 += __shfl_xor_sync(0xffffffffu, s0, 1);
        s0 += __shfl_xor_sync(0xffffffffu, s0, 2);
        s1 += __shfl_xor_sync(0xffffffffu, s1, 1);
        s1 += __shfl_xor_sync(0xffffffffu, s1, 2);
        l0 = l0 * a0 + s0; l1 = l1 * a1 + s1; m0 = mn0; m1 = mn1;
#pragma unroll
        for (int j = 0; j < 8; j++) {
            oc[j][0] *= a0; oc[j][1] *= a0; oc[j][2] *= a1; oc[j][3] *= a1;
        }

        // PV: K-dim 128 = 8 k16 steps; P converted per-step (short live range)
#pragma unroll
        for (int kc = 0; kc < 8; kc++) {
            __half2 p01{__float2half_rn(sc[2*kc][0]),   __float2half_rn(sc[2*kc][1])};
            __half2 p23{__float2half_rn(sc[2*kc][2]),   __float2half_rn(sc[2*kc][3])};
            __half2 q01{__float2half_rn(sc[2*kc+1][0]), __float2half_rn(sc[2*kc+1][1])};
            __half2 q23{__float2half_rn(sc[2*kc+1][2]), __float2half_rn(sc[2*kc+1][3])};
            uint32_t pah[4] = {*(uint32_t*)&p01, *(uint32_t*)&p23,
                               *(uint32_t*)&q01, *(uint32_t*)&q23};
            uint32_t vf[4][4];
#pragma unroll
            for (int p = 0; p < 4; p++)
                ldsm4t(vf[p], S + 16384 +
                       swz((kc * 16 + aRowOff) * 128 + p * 32 + aKHalf));
#pragma unroll
            for (int j = 0; j < 8; j++)
                mma16816(oc[j], pah, &vf[j >> 1][(j & 1) * 2]);
        }
        __syncthreads();                   // all warps done with stage jt&1
        if (jt + 2 < JT) load_kv(jt + 2);
    }

    // Epilogue: normalize -> single-plane fp16 atts [4096,1024]
    float i0 = 1.f / l0, i1 = 1.f / l1;
    size_t rA = (size_t)(b * TT + trow0) * DDIM + h * HDD;
    size_t rB = rA + (size_t)8 * DDIM;
#pragma unroll
    for (int j = 0; j < 8; j++) {
        int col = 8 * j + ((lane & 3) << 1);
        __half2 oA{__float2half_rn(oc[j][0] * i0), __float2half_rn(oc[j][1] * i0)};
        __half2 oB{__float2half_rn(oc[j][2] * i1), __float2half_rn(oc[j][3] * i1)};
        *(uint32_t*)(Oout + rA + col) = *(uint32_t*)&oA;
        *(uint32_t*)(Oout + rB + col) = *(uint32_t*)&oB;
    }
}

// ---------------------------------------------------------------------------
extern "C" void kernel_launch(void* const* d_in, const int* in_sizes, int n_in,
                              void* d_out, int out_size) {
    const float* x  = (const float*)d_in[0];
    const float* Wq = (const float*)d_in[1];
    const float* Wk = (const float*)d_in[2];
    const float* Wv = (const float*)d_in[3];
    const float* Wo = (const float*)d_in[4];
    float* out = (float*)d_out;

    __half *xh, *ats, *w16, *wo16, *qp, *kp, *vp;
    cudaGetSymbolAddress((void**)&xh, g_xh);
    cudaGetSymbolAddress((void**)&ats, g_atts);
    cudaGetSymbolAddress((void**)&w16, g_w16);
    cudaGetSymbolAddress((void**)&wo16, g_wo16);
    cudaGetSymbolAddress((void**)&qp, g_qp);
    cudaGetSymbolAddress((void**)&kp, g_kp);
    cudaGetSymbolAddress((void**)&vp, g_vp);

    cudaFuncSetAttribute(gemm_hmma, cudaFuncAttributeMaxDynamicSharedMemorySize, GEMM_DYN);
    cudaFuncSetAttribute(attn_mma, cudaFuncAttributeMaxDynamicSharedMemorySize, ATT_DYN);

    // operand prep (all single-plane fp16)
    xconv<<<MM, 256>>>(x, xh);
    dim3 wgrid(DDIM, 4);
    wconv4<<<wgrid, 256>>>(Wq, Wk, Wv, Wo, w16, wo16);

    // merged Q/K/V projection: one launch, N=3072, K=1024
    dim3 qkvgrid(3 * DDIM / 128, MM / 128);   // (24, 32) = 768 CTAs
    gemm_hmma<<<qkvgrid, 128, GEMM_DYN>>>(xh, w16, nullptr, 3);

    dim3 agrid(TT / 64, HH, BB);              // (32, 16, 2) = 1024 CTAs
    attn_mma<<<agrid, 128, ATT_DYN>>>(qp, kp, vp, ats);

    // Wo: single-plane fp16, K=1024
    dim3 ogrid(DDIM / 128, MM / 128);         // (8, 32)
    gemm_hmma<<<ogrid, 128, GEMM_DYN>>>(ats, wo16, out, 0);
}

// round 16
// speedup vs baseline: 20.7688x; 1.0106x over previous
#include <cuda_runtime.h>
#include <cuda_fp16.h>
#include <cstdint>

// Problem constants
#define BB   2
#define TT   2048
#define DDIM 1024
#define HH   16
#define HDD  64
#define MM   (BB*TT)   // 4096 rows
#define DKK  64        // attention Q/K/V dim

// Scratch (__device__ globals; no allocations allowed)
__device__ __half g_xh[MM*DDIM];
__device__ __half g_atts[MM*DDIM];
__device__ __half g_w16[3*DDIM*DDIM];    // [Wq | Wk | Wv] fp16 planes
__device__ __half g_wo16[DDIM*DDIM];
__device__ __half g_qp[BB*HH*TT*DKK];
__device__ __half g_kp[BB*HH*TT*DKK];
__device__ __half g_vp[BB*HH*TT*DKK];

// ---------------------------------------------------------------------------
__device__ __forceinline__ uint32_t s2u(const void* p) {
    uint32_t a;
    asm("{ .reg .u64 t; cvta.to.shared.u64 t, %1; cvt.u32.u64 %0, t; }" : "=r"(a) : "l"(p));
    return a;
}
__device__ __forceinline__ uint32_t swz(uint32_t o) { return o ^ ((o >> 3) & 0x70); }
__device__ __forceinline__ void cp16(uint32_t dst, const void* src) {
    asm volatile("cp.async.cg.shared.global [%0], [%1], 16;" :: "r"(dst), "l"(src));
}
__device__ __forceinline__ void ldsm4(uint32_t* r, uint32_t addr) {
    asm volatile("ldmatrix.sync.aligned.m8n8.x4.shared.b16 {%0,%1,%2,%3}, [%4];"
                 : "=r"(r[0]), "=r"(r[1]), "=r"(r[2]), "=r"(r[3]) : "r"(addr));
}
__device__ __forceinline__ void ldsm4t(uint32_t* r, uint32_t addr) {
    asm volatile("ldmatrix.sync.aligned.m8n8.x4.trans.shared.b16 {%0,%1,%2,%3}, [%4];"
                 : "=r"(r[0]), "=r"(r[1]), "=r"(r[2]), "=r"(r[3]) : "r"(addr));
}
__device__ __forceinline__ void mma16816(float* c, const uint32_t* a, const uint32_t* b) {
    asm volatile("mma.sync.aligned.m16n8k16.row.col.f32.f16.f16.f32 "
                 "{%0,%1,%2,%3}, {%4,%5,%6,%7}, {%8,%9}, {%0,%1,%2,%3};"
                 : "+f"(c[0]), "+f"(c[1]), "+f"(c[2]), "+f"(c[3])
                 : "r"(a[0]), "r"(a[1]), "r"(a[2]), "r"(a[3]), "r"(b[0]), "r"(b[1]));
}
__device__ __forceinline__ float ex2(float x) {
    float y; asm("ex2.approx.f32 %0, %1;" : "=f"(y) : "f"(x)); return y;
}
// pack (lo,hi) fp32 -> f16x2 then exponentiate both lanes
__device__ __forceinline__ uint32_t ex2_pack(float lo, float hi) {
    uint32_t u;
    asm("cvt.rn.f16x2.f32 %0, %1, %2;" : "=r"(u) : "f"(hi), "f"(lo));
    asm("ex2.approx.f16x2 %0, %0;" : "+r"(u));
    return u;
}

// ---------------------------------------------------------------------------
// xconv: fp32 x [4096,1024] -> fp16 single plane
// ---------------------------------------------------------------------------
__global__ __launch_bounds__(256) void xconv(const float* __restrict__ in,
                                             __half* __restrict__ out) {
    int idx = (blockIdx.x * 256 + threadIdx.x) * 4;
    float4 v = *(const float4*)(in + idx);
    __half2 a{__float2half_rn(v.x), __float2half_rn(v.y)};
    __half2 b{__float2half_rn(v.z), __float2half_rn(v.w)};
    *(uint32_t*)(out + idx)     = *(uint32_t*)&a;
    *(uint32_t*)(out + idx + 2) = *(uint32_t*)&b;
}

// wconv4: Wq/Wk/Wv -> merged fp16 buffer; Wo -> own plane. One launch.
__global__ __launch_bounds__(256) void wconv4(const float* __restrict__ w0,
                                              const float* __restrict__ w1,
                                              const float* __restrict__ w2,
                                              const float* __restrict__ w3,
                                              __half* __restrict__ wqkv,
                                              __half* __restrict__ wo) {
    const float* in; __half* out;
    switch (blockIdx.y) {
        case 0: in = w0; out = wqkv; break;
        case 1: in = w1; out = wqkv + DDIM*DDIM; break;
        case 2: in = w2; out = wqkv + 2*DDIM*DDIM; break;
        default: in = w3; out = wo; break;
    }
    int idx = (blockIdx.x * 256 + threadIdx.x) * 4;
    float4 v = *(const float4*)(in + idx);
    __half2 a{__float2half_rn(v.x), __float2half_rn(v.y)};
    __half2 b{__float2half_rn(v.z), __float2half_rn(v.w)};
    *(uint32_t*)(out + idx)     = *(uint32_t*)&a;
    *(uint32_t*)(out + idx + 2) = *(uint32_t*)&b;
}

// ---------------------------------------------------------------------------
// fp16 HMMA NT GEMM, K=1024 single plane (16 chunks).
// CTA 128x128, 4 warps (2x2), warp tile 64x64, BK=64, 3-stage, 2 CTA/SM.
// mode 0: fp32 C out.  mode 3: merged QKV — sect 0 Q (x 0.125*log2e), 1 K, 2 V.
// ---------------------------------------------------------------------------
#define BK      64
#define STAGES  3
#define NCHUNK  (DDIM / BK)               // 16
#define STG_A   (128 * 128)               // 16 KB
#define STG_B   (128 * 128)               // 16 KB
#define STG_SZ  (STG_A + STG_B)           // 32 KB
#define GEMM_DYN (STAGES * STG_SZ + 1024) // ~97 KB
#define QSCALE  0.180336880111f           // 0.125 * log2(e)

__global__ __launch_bounds__(128, 2) void gemm_hmma(const __half* __restrict__ A,
                                                    const __half* __restrict__ B,
                                                    void* __restrict__ Cout, int mode) {
    extern __shared__ char dyn[];
    const int tid  = threadIdx.x;
    const int wid  = tid >> 5, lane = tid & 31;
    const int wm   = wid >> 1;
    const int wn   = wid & 1;
    const int m0   = blockIdx.y << 7;
    const int n0   = blockIdx.x << 7;

    const uint32_t sbase = (s2u(dyn) + 1023) & ~1023u;
    const int lrow = tid >> 3;
    const int ls16 = tid & 7;

    float acc[4][8][4];
#pragma unroll
    for (int mi = 0; mi < 4; mi++)
#pragma unroll
        for (int ni = 0; ni < 8; ni++)
#pragma unroll
            for (int j = 0; j < 4; j++) acc[mi][ni][j] = 0.f;

    const int sub  = lane >> 3;
    const int lr8  = lane & 7;
    const int aRowOff = ((sub & 1) << 3) + lr8;
    const int aKHalf  = (sub >> 1) << 4;
    const int bRowOff = ((sub >> 1) << 3) + lr8;
    const int bKHalf  = (sub & 1) << 4;

    auto load_chunk = [&](int c) {
        const int s_ = c % STAGES;
        const uint32_t sA_ = sbase + s_ * STG_SZ;
        const uint32_t sB_ = sA_ + STG_A;
#pragma unroll
        for (int it = 0; it < 8; it++) {
            int row = lrow + (it << 4);
            cp16(sA_ + swz(row * 128 + ls16 * 16),
                 A + (size_t)(m0 + row) * DDIM + c * BK + ls16 * 8);
        }
#pragma unroll
        for (int it = 0; it < 8; it++) {
            int row = lrow + (it << 4);
            cp16(sB_ + swz(row * 128 + ls16 * 16),
                 B + (size_t)(n0 + row) * DDIM + c * BK + ls16 * 8);
        }
        asm volatile("cp.async.commit_group;" ::: "memory");
    };

    load_chunk(0);
    load_chunk(1);

    for (int i = 0; i < NCHUNK; i++) {
        if (i < NCHUNK - 1) asm volatile("cp.async.wait_group 1;" ::: "memory");
        else                asm volatile("cp.async.wait_group 0;" ::: "memory");
        __syncthreads();

        if (i + 2 < NCHUNK) load_chunk(i + 2);

        const int s = i % STAGES;
        const uint32_t sA = sbase + s * STG_SZ;
        const uint32_t sB = sA + STG_A;

#pragma unroll
        for (int kk = 0; kk < 4; kk++) {
            uint32_t af[4][4], bf[4][4];
#pragma unroll
            for (int mi = 0; mi < 4; mi++) {
                int row = wm * 64 + mi * 16 + aRowOff;
                ldsm4(af[mi], sA + swz(row * 128 + kk * 32 + aKHalf));
            }
#pragma unroll
            for (int p = 0; p < 4; p++) {
                int row = wn * 64 + p * 16 + bRowOff;
                ldsm4(bf[p], sB + swz(row * 128 + kk * 32 + bKHalf));
            }
#pragma unroll
            for (int mi = 0; mi < 4; mi++)
#pragma unroll
                for (int nj = 0; nj < 8; nj++)
                    mma16816(acc[mi][nj], af[mi], &bf[nj >> 1][(nj & 1) * 2]);
        }
    }

    const int lr = lane >> 2, lc = (lane & 3) << 1;
    if (mode == 0) {
        float* C = (float*)Cout;
#pragma unroll
        for (int mi = 0; mi < 4; mi++)
#pragma unroll
            for (int nj = 0; nj < 8; nj++) {
                int grow = m0 + wm * 64 + mi * 16 + lr;
                int gcol = n0 + wn * 64 + nj * 8 + lc;
                *(float2*)&C[(size_t)grow * DDIM + gcol] =
                    make_float2(acc[mi][nj][0], acc[mi][nj][1]);
                *(float2*)&C[(size_t)(grow + 8) * DDIM + gcol] =
                    make_float2(acc[mi][nj][2], acc[mi][nj][3]);
            }
    } else {
        const int sect = n0 >> 10;                // 0=Q, 1=K, 2=V
        const float sc = (sect == 0) ? QSCALE : 1.f;
        const int hh = ((n0 & 1023) >> 6) + wn;   // warp's 64-col slab == one head
        __half* P = (sect == 0) ? g_qp : (sect == 1) ? g_kp : g_vp;
#pragma unroll
        for (int mi = 0; mi < 4; mi++)
#pragma unroll
            for (int nj = 0; nj < 8; nj++) {
                int grow = m0 + wm * 64 + mi * 16 + lr;
                int d    = nj * 8 + lc;
#pragma unroll
                for (int half_ = 0; half_ < 2; half_++) {
                    int row = grow + half_ * 8;
                    int b = row >> 11, t = row & 2047;
                    float v0 = acc[mi][nj][half_ * 2] * sc;
                    float v1 = acc[mi][nj][half_ * 2 + 1] * sc;
                    __half2 hp{__float2half_rn(v0), __float2half_rn(v1)};
                    size_t base = ((size_t)(b * HH + hh) * TT + t) * DKK + d;
                    *(uint32_t*)(P + base) = *(uint32_t*)&hp;
                }
            }
    }
}

// ---------------------------------------------------------------------------
// fp16 flash attention, KV tile 128. log2-domain softmax with f16x2 ex2
// (P produced directly in A-frag layout); row-sum via ones-column MMA
// (no sum shuffles); V via trans-ldmatrix. Writes single-plane fp16 atts.
// 128 threads (4 warps x 16 q-rows = 64 q-rows/CTA), 2-stage KV, 2 CTAs/SM.
// Heavy-first: qb = gridDim.x-1-blockIdx.x.
// ---------------------------------------------------------------------------
#define ATT_QSZ   8192                     // 64 x 128B (Q single plane)
#define ATT_STG   32768                    // K 16KB + V 16KB (128 kv rows)
#define ATT_DYN   (ATT_QSZ + 2*ATT_STG + 1024)   // ~74 KB

__global__ __launch_bounds__(128, 2) void attn_mma(const __half* __restrict__ Qp,
                                                   const __half* __restrict__ Kp,
                                                   const __half* __restrict__ Vp,
                                                   __half* __restrict__ Oout) {
    extern __shared__ char dyn[];
    const int tid = threadIdx.x, wid = tid >> 5, lane = tid & 31;
    const int qb = (int)(gridDim.x - 1 - blockIdx.x);   // heavy-first
    const int h = blockIdx.y, b = blockIdx.z;
    const int q0 = qb << 6;
    const int JT = (qb >> 1) + 1;          // 128-wide kv tiles

    const uint32_t sb = (s2u(dyn) + 1023) & ~1023u;
    const uint32_t QS = sb;
    const uint32_t ST0 = sb + ATT_QSZ;
    const uint32_t ST1 = ST0 + ATT_STG;

    const int sub = lane >> 3, lr8 = lane & 7;
    const int aRowOff = ((sub & 1) << 3) + lr8;   // also trans-ldsm row offset
    const int aKHalf  = (sub >> 1) << 4;          // also trans-ldsm col offset
    const int bRowOff = ((sub >> 1) << 3) + lr8;
    const int bKHalf  = (sub & 1) << 4;

    const size_t bh = (size_t)(b * HH + h);
    const __half* Qg = Qp + (bh * TT + q0) * DKK;
    const __half* Kg = Kp + bh * TT * DKK;
    const __half* Vg = Vp + bh * TT * DKK;

    // Q tile: 64 rows x 64 halfs = 512 cp16 / 128 threads = 4 iters
#pragma unroll
    for (int it = 0; it < 4; it++) {
        int idx = tid + it * 128;
        int row = idx >> 3, seg = idx & 7;
        cp16(QS + swz(row * 128 + seg * 16), Qg + (size_t)row * DKK + seg * 8);
    }
    asm volatile("cp.async.commit_group;" ::: "memory");

    auto load_kv = [&](int jt) {
        const uint32_t S = (jt & 1) ? ST1 : ST0;
        const int kv0 = jt << 7;
#pragma unroll
        for (int it = 0; it < 8; it++) {       // K [s][d] 128x128B
            int idx = tid + it * 128;
            int row = idx >> 3, seg = idx & 7;
            cp16(S + swz(row * 128 + seg * 16),
                 Kg + (size_t)(kv0 + row) * DKK + seg * 8);
        }
#pragma unroll
        for (int it = 0; it < 8; it++) {       // V [s][d] 128x128B
            int idx = tid + it * 128;
            int row = idx >> 3, seg = idx & 7;
            cp16(S + 16384 + swz(row * 128 + seg * 16),
                 Vg + (size_t)(kv0 + row) * DKK + seg * 8);
        }
        asm volatile("cp.async.commit_group;" ::: "memory");
    };
    load_kv(0);
    if (JT > 1) load_kv(1);

    // Q (+kv0) complete before ldsm; conditional on committed group count
    if (JT > 1) asm volatile("cp.async.wait_group 1;" ::: "memory");
    else        asm volatile("cp.async.wait_group 0;" ::: "memory");
    __syncthreads();

    uint32_t qa[4][4];
#pragma unroll
    for (int kk = 0; kk < 4; kk++) {
        int row = wid * 16 + aRowOff;
        ldsm4(qa[kk], QS + swz(row * 128 + kk * 32 + aKHalf));
    }

    float oc[8][4], ls[4];
#pragma unroll
    for (int j = 0; j < 8; j++)
#pragma unroll
        for (int e = 0; e < 4; e++) oc[j][e] = 0.f;
#pragma unroll
    for (int e = 0; e < 4; e++) ls[e] = 0.f;
    float m0 = -1e30f, m1 = -1e30f;

    const int trow0 = q0 + wid * 16 + (lane >> 2);
    const uint32_t ONE2 = 0x3C003C00u;        // (1.0h, 1.0h)
    const uint32_t ones_b[2] = {ONE2, ONE2};

    for (int jt = 0; jt < JT; jt++) {
        if (jt + 1 < JT) asm volatile("cp.async.wait_group 1;" ::: "memory");
        else             asm volatile("cp.async.wait_group 0;" ::: "memory");
        __syncthreads();
        const uint32_t S = (jt & 1) ? ST1 : ST0;

        // scores: 16 j-frags x 128 kv cols, log2 domain
        float sc[16][4];
#pragma unroll
        for (int j = 0; j < 16; j++)
#pragma unroll
            for (int e = 0; e < 4; e++) sc[j][e] = 0.f;
#pragma unroll
        for (int kk = 0; kk < 4; kk++) {
            uint32_t kf[8][4];
#pragma unroll
            for (int p = 0; p < 8; p++)
                ldsm4(kf[p], S + swz((p * 16 + bRowOff) * 128 + kk * 32 + bKHalf));
#pragma unroll
            for (int j = 0; j < 16; j++)
                mma16816(sc[j], qa[kk], &kf[j >> 1][(j & 1) * 2]);
        }

        if (jt == JT - 1) {                // diagonal tile: causal mask
            int s0c = jt << 7;
#pragma unroll
            for (int j = 0; j < 16; j++) {
                int scol = s0c + 8 * j + ((lane & 3) << 1);
                if (scol     > trow0)     sc[j][0] = -1e30f;
                if (scol + 1 > trow0)     sc[j][1] = -1e30f;
                if (scol     > trow0 + 8) sc[j][2] = -1e30f;
                if (scol + 1 > trow0 + 8) sc[j][3] = -1e30f;
            }
        }

        // row max (base-2 domain)
        float r0 = -1e30f, r1 = -1e30f;
#pragma unroll
        for (int j = 0; j < 16; j++) {
            r0 = fmaxf(r0, fmaxf(sc[j][0], sc[j][1]));
            r1 = fmaxf(r1, fmaxf(sc[j][2], sc[j][3]));
        }
        r0 = fmaxf(r0, __shfl_xor_sync(0xffffffffu, r0, 1));
        r0 = fmaxf(r0, __shfl_xor_sync(0xffffffffu, r0, 2));
        r1 = fmaxf(r1, __shfl_xor_sync(0xffffffffu, r1, 1));
        r1 = fmaxf(r1, __shfl_xor_sync(0xffffffffu, r1, 2));
        float mn0 = fmaxf(m0, r0), mn1 = fmaxf(m1, r1);
        float a0 = ex2(m0 - mn0), a1 = ex2(m1 - mn1);
        m0 = mn0; m1 = mn1;

        // P = ex2(sc - mn) directly in f16x2 A-frag layout
        uint32_t ph[16][2];
#pragma unroll
        for (int j = 0; j < 16; j++) {
            ph[j][0] = ex2_pack(sc[j][0] - mn0, sc[j][1] - mn0);
            ph[j][1] = ex2_pack(sc[j][2] - mn1, sc[j][3] - mn1);
        }

        // rescale accumulators (ls[1], ls[3] are duplicate columns, unread)
        ls[0] *= a0; ls[2] *= a1;
#pragma unroll
        for (int j = 0; j < 8; j++) {
            oc[j][0] *= a0; oc[j][1] *= a0; oc[j][2] *= a1; oc[j][3] *= a1;
        }

        // PV + ones-column row-sum: 8 k16 steps
#pragma unroll
        for (int kc = 0; kc < 8; kc++) {
            uint32_t pah[4] = {ph[2*kc][0], ph[2*kc][1], ph[2*kc+1][0], ph[2*kc+1][1]};
            uint32_t vf[4][4];
#pragma unroll
            for (int p = 0; p < 4; p++)
                ldsm4t(vf[p], S + 16384 +
                       swz((kc * 16 + aRowOff) * 128 + p * 32 + aKHalf));
#pragma unroll
            for (int j = 0; j < 8; j++)
                mma16816(oc[j], pah, &vf[j >> 1][(j & 1) * 2]);
            mma16816(ls, pah, ones_b);     // row sum of P (full k-reduction)
        }
        __syncthreads();                   // all warps done with stage jt&1
        if (jt + 2 < JT) load_kv(jt + 2);
    }

    // Epilogue: normalize -> single-plane fp16 atts [4096,1024]
    float i0 = 1.f / ls[0], i1 = 1.f / ls[2];
    size_t rA = (size_t)(b * TT + trow0) * DDIM + h * HDD;
    size_t rB = rA + (size_t)8 * DDIM;
#pragma unroll
    for (int j = 0; j < 8; j++) {
        int col = 8 * j + ((lane & 3) << 1);
        __half2 oA{__float2half_rn(oc[j][0] * i0), __float2half_rn(oc[j][1] * i0)};
        __half2 oB{__float2half_rn(oc[j][2] * i1), __float2half_rn(oc[j][3] * i1)};
        *(uint32_t*)(Oout + rA + col) = *(uint32_t*)&oA;
        *(uint32_t*)(Oout + rB + col) = *(uint32_t*)&oB;
    }
}

// ---------------------------------------------------------------------------
extern "C" void kernel_launch(void* const* d_in, const int* in_sizes, int n_in,
                              void* d_out, int out_size) {
    const float* x  = (const float*)d_in[0];
    const float* Wq = (const float*)d_in[1];
    const float* Wk = (const float*)d_in[2];
    const float* Wv = (const float*)d_in[3];
    const float* Wo = (const float*)d_in[4];
    float* out = (float*)d_out;

    __half *xh, *ats, *w16, *wo16, *qp, *kp, *vp;
    cudaGetSymbolAddress((void**)&xh, g_xh);
    cudaGetSymbolAddress((void**)&ats, g_atts);
    cudaGetSymbolAddress((void**)&w16, g_w16);
    cudaGetSymbolAddress((void**)&wo16, g_wo16);
    cudaGetSymbolAddress((void**)&qp, g_qp);
    cudaGetSymbolAddress((void**)&kp, g_kp);
    cudaGetSymbolAddress((void**)&vp, g_vp);

    cudaFuncSetAttribute(gemm_hmma, cudaFuncAttributeMaxDynamicSharedMemorySize, GEMM_DYN);
    cudaFuncSetAttribute(attn_mma, cudaFuncAttributeMaxDynamicSharedMemorySize, ATT_DYN);

    // operand prep (all single-plane fp16)
    xconv<<<MM, 256>>>(x, xh);
    dim3 wgrid(DDIM, 4);
    wconv4<<<wgrid, 256>>>(Wq, Wk, Wv, Wo, w16, wo16);

    // merged Q/K/V projection: one launch, N=3072, K=1024
    dim3 qkvgrid(3 * DDIM / 128, MM / 128);   // (24, 32) = 768 CTAs
    gemm_hmma<<<qkvgrid, 128, GEMM_DYN>>>(xh, w16, nullptr, 3);

    dim3 agrid(TT / 64, HH, BB);              // (32, 16, 2) = 1024 CTAs
    attn_mma<<<agrid, 128, ATT_DYN>>>(qp, kp, vp, ats);

    // Wo: single-plane fp16, K=1024
    dim3 ogrid(DDIM / 128, MM / 128);         // (8, 32)
    gemm_hmma<<<ogrid, 128, GEMM_DYN>>>(ats, wo16, out, 0);
}